// round 3
// baseline (speedup 1.0000x reference)
#include <cuda_runtime.h>
#include <math.h>

#define NN 4096
#define DD 1024
#define WW 10
#define BAND 21
#define NSPK 8

// ---------------- device scratch (static, no allocation) ----------------
__device__ float g_band[NN * BAND];
__device__ float g_c[NN];
__device__ float g_diag[NN];
__device__ float g_Mp[NN * DD];
__device__ float g_Ms[NN * DD];
__device__ float g_Msm[NN * DD];
__device__ float g_Mdf[NN * DD];
__device__ float g_Ma[NN * DD];
__device__ float g_PreP[NN * DD];
__device__ float g_PreS[NN * DD];
__device__ float g_chunk[32 * DD];
__device__ float g_Ssm[NSPK * DD];
__device__ float g_Sdf[NSPK * DD];
__device__ float g_h1[NN * DD];
__device__ float g_h2[NN * DD];
__device__ float g_T[NN * DD];

// ---------------- banded attention logits: dot(x_i, x_j), |i-j|<=W ------
__global__ __launch_bounds__(256) void att_logits(const float* __restrict__ x,
                                                  float* __restrict__ band) {
    __shared__ float xi[DD];
    __shared__ float red[8];
    int i = blockIdx.x;
    int tid = threadIdx.x;
    for (int d = tid; d < DD; d += 256) xi[d] = x[i * DD + d];
    __syncthreads();

    float acc[BAND];
#pragma unroll
    for (int jo = 0; jo < BAND; jo++) acc[jo] = 0.f;

    for (int d = tid; d < DD; d += 256) {
        float xv = xi[d];
#pragma unroll
        for (int jo = 0; jo < BAND; jo++) {
            int j = i - WW + jo;
            if (j >= 0 && j < NN) acc[jo] += xv * x[j * DD + d];
        }
    }
    int lane = tid & 31, w = tid >> 5;
    for (int jo = 0; jo < BAND; jo++) {
        float v = acc[jo];
#pragma unroll
        for (int o = 16; o > 0; o >>= 1) v += __shfl_down_sync(0xffffffffu, v, o);
        if (lane == 0) red[w] = v;
        __syncthreads();
        if (tid == 0) {
            float s = 0.f;
#pragma unroll
            for (int k = 0; k < 8; k++) s += red[k];
            band[i * BAND + jo] = s;
        }
        __syncthreads();
    }
}

// softmax over full row: band logits + (N - band_count) exact zeros
__global__ void att_softmax(float* __restrict__ band, float* __restrict__ cvec,
                            float* __restrict__ diag) {
    int i = blockIdx.x * 128 + threadIdx.x;
    if (i >= NN) return;
    int lo = max(i - WW, 0), hi = min(i + WW, NN - 1);
    int cnt = hi - lo + 1;
    float m = 0.0f;  // zeros always present (N >> band), so max includes 0
#pragma unroll
    for (int jo = 0; jo < BAND; jo++) {
        int j = i - WW + jo;
        if (j >= 0 && j < NN) m = fmaxf(m, band[i * BAND + jo]);
    }
    float em = expf(-m);
    float Z = (float)(NN - cnt) * em;
    float vals[BAND];
#pragma unroll
    for (int jo = 0; jo < BAND; jo++) {
        int j = i - WW + jo;
        float v = 0.f;
        if (j >= 0 && j < NN) {
            v = expf(band[i * BAND + jo] - m);
            Z += v;
        }
        vals[jo] = v;
    }
    float inv = 1.0f / Z;
#pragma unroll
    for (int jo = 0; jo < BAND; jo++) band[i * BAND + jo] = vals[jo] * inv;
    cvec[i] = em * inv;
    diag[i] = vals[WW] * inv;
}

// ---------------- tiled SGEMM: C[M,N] = A[M,K] @ B[K,N] (+C if acc) -----
__global__ __launch_bounds__(256) void sgemm_nn(const float* __restrict__ A,
                                                const float* __restrict__ B,
                                                float* __restrict__ C,
                                                int M, int N, int K, int acc) {
    const int BM = 128, BN = 128, BK = 16;
    __shared__ float As[BK][BM];
    __shared__ float Bs[BK][BN];
    int tid = threadIdx.x;
    int bx = blockIdx.x, by = blockIdx.y;
    int tx = tid % 16, ty = tid / 16;
    int rowL = ty * 8;           // local row of 8x8 micro tile
    int colL = tx * 8;
    float accv[8][8];
#pragma unroll
    for (int m = 0; m < 8; m++)
#pragma unroll
        for (int n = 0; n < 8; n++) accv[m][n] = 0.f;

    for (int k0 = 0; k0 < K; k0 += BK) {
#pragma unroll
        for (int l = 0; l < 2; l++) {
            int q = tid + l * 256;
            int ar = q >> 2;           // 0..127
            int ac = (q & 3) * 4;      // 0,4,8,12
            float4 va = *(const float4*)&A[(size_t)(by * BM + ar) * K + k0 + ac];
            As[ac + 0][ar] = va.x;
            As[ac + 1][ar] = va.y;
            As[ac + 2][ar] = va.z;
            As[ac + 3][ar] = va.w;
            int br = q >> 5;           // 0..15
            int bc = (q & 31) * 4;     // 0..124
            *(float4*)&Bs[br][bc] = *(const float4*)&B[(size_t)(k0 + br) * N + bx * BN + bc];
        }
        __syncthreads();
#pragma unroll
        for (int kk = 0; kk < BK; kk++) {
            float ra[8], rb[8];
#pragma unroll
            for (int m = 0; m < 8; m++) ra[m] = As[kk][rowL + m];
#pragma unroll
            for (int n = 0; n < 8; n++) rb[n] = Bs[kk][colL + n];
#pragma unroll
            for (int m = 0; m < 8; m++)
#pragma unroll
                for (int n = 0; n < 8; n++) accv[m][n] += ra[m] * rb[n];
        }
        __syncthreads();
    }
    int row0 = by * BM + rowL;
    int col0 = bx * BN + colL;
#pragma unroll
    for (int m = 0; m < 8; m++) {
        float* crow = &C[(size_t)(row0 + m) * N + col0];
#pragma unroll
        for (int n = 0; n < 8; n += 4) {
            float4 o;
            o.x = accv[m][n]; o.y = accv[m][n + 1]; o.z = accv[m][n + 2]; o.w = accv[m][n + 3];
            if (acc) {
                float4 old = *(float4*)&crow[n];
                o.x += old.x; o.y += old.y; o.z += old.z; o.w += old.w;
            }
            *(float4*)&crow[n] = o;
        }
    }
}

// ---------------- chunked prefix scan along rows (per column) -----------
__global__ void scan_chunk(const float* __restrict__ M, float* __restrict__ chunk) {
    int d = blockIdx.y * 256 + threadIdx.x;
    int c = blockIdx.x;
    int base = c * 128;
    float s = 0.f;
#pragma unroll 4
    for (int r = 0; r < 128; r++) s += M[(size_t)(base + r) * DD + d];
    chunk[c * DD + d] = s;
}

__global__ void scan_offsets(float* __restrict__ chunk) {
    int d = blockIdx.x * 256 + threadIdx.x;
    float off = 0.f;
#pragma unroll
    for (int c = 0; c < 32; c++) {
        float t = chunk[c * DD + d];
        chunk[c * DD + d] = off;  // exclusive
        off += t;
    }
}

__global__ void scan_write(const float* __restrict__ M, const float* __restrict__ chunk,
                           float* __restrict__ P) {
    int d = blockIdx.y * 256 + threadIdx.x;
    int c = blockIdx.x;
    int base = c * 128;
    float acc = chunk[c * DD + d];
#pragma unroll 4
    for (int r = 0; r < 128; r++) {
        acc += M[(size_t)(base + r) * DD + d];
        P[(size_t)(base + r) * DD + d] = acc;  // inclusive prefix
    }
}

__global__ void zero2(float* __restrict__ a, float* __restrict__ b, int n) {
    int i = blockIdx.x * 256 + threadIdx.x;
    if (i < n) { a[i] = 0.f; b[i] = 0.f; }
}

// per-speaker column sums for Msm and Mdf
__global__ __launch_bounds__(256) void spk_sums(const float* __restrict__ Msm,
                                                const float* __restrict__ Mdf,
                                                const int* __restrict__ spk,
                                                float* __restrict__ Ssm,
                                                float* __restrict__ Sdf) {
    __shared__ float s1[NSPK * 256];
    __shared__ float s2[NSPK * 256];
    int tid = threadIdx.x;
    int d = blockIdx.y * 256 + tid;
#pragma unroll
    for (int k = 0; k < NSPK; k++) { s1[k * 256 + tid] = 0.f; s2[k * 256 + tid] = 0.f; }
    int base = blockIdx.x * 256;
    for (int r = 0; r < 256; r++) {
        int j = base + r;
        int sp = spk[j];
        s1[sp * 256 + tid] += Msm[(size_t)j * DD + d];
        s2[sp * 256 + tid] += Mdf[(size_t)j * DD + d];
    }
#pragma unroll
    for (int k = 0; k < NSPK; k++) {
        atomicAdd(&Ssm[k * DD + d], s1[k * 256 + tid]);
        atomicAdd(&Sdf[k * DD + d], s2[k * 256 + tid]);
    }
}

// ---------------- band combine + diag self-term + relu ------------------
__global__ __launch_bounds__(256) void combine(
    const float* __restrict__ Mp, const float* __restrict__ Ms,
    const float* __restrict__ Msm, const float* __restrict__ Mdf,
    const float* __restrict__ Ma,
    const float* __restrict__ PreP, const float* __restrict__ PreS,
    const float* __restrict__ Ssm, const float* __restrict__ Sdf,
    const float* __restrict__ band, const float* __restrict__ cvec,
    const float* __restrict__ diag, const int* __restrict__ spk,
    float* __restrict__ out) {
    int i = blockIdx.x;
    int d = blockIdx.y * 256 + threadIdx.x;
    __shared__ float a_sh[BAND];
    __shared__ int sp_sh[BAND];
    __shared__ float cs, dg;
    __shared__ int spi;
    if (threadIdx.x < BAND) {
        int j = i - WW + (int)threadIdx.x;
        bool valid = (j >= 0 && j < NN);
        a_sh[threadIdx.x] = valid ? band[i * BAND + threadIdx.x] : 0.f;
        sp_sh[threadIdx.x] = valid ? spk[j] : -1;
    }
    if (threadIdx.x == 0) { cs = cvec[i]; dg = diag[i]; spi = spk[i]; }
    __syncthreads();

    float c = cs;
    float acc = 0.f;
#pragma unroll
    for (int jo = 0; jo < BAND; jo++) {
        int spj = sp_sh[jo];
        if (spj < 0) continue;  // block-uniform branch
        int j = i - WW + jo;
        float a = a_sh[jo];
        // pred (j>=i) uses Mp; suc (j<i) uses Ms
        float v1 = (jo >= WW) ? Mp[(size_t)j * DD + d] : Ms[(size_t)j * DD + d];
        acc += a * v1;
        // same/diff: coefficient (a - c) on band; c * speaker-sum added below
        float v2 = (spj == spi) ? Msm[(size_t)j * DD + d] : Mdf[(size_t)j * DD + d];
        acc += (a - c) * v2;
    }
    int hi = min(i + WW, NN - 1);
    float suf = PreP[(size_t)(NN - 1) * DD + d] - PreP[(size_t)hi * DD + d];
    float pre = (i - WW - 1 >= 0) ? PreS[(size_t)(i - WW - 1) * DD + d] : 0.f;
    float stot = 0.f;
#pragma unroll
    for (int k = 0; k < NSPK; k++) stot += Sdf[k * DD + d];
    float sameS = Ssm[spi * DD + d];
    float diffS = stot - Sdf[spi * DD + d];
    acc += c * (suf + pre + sameS + diffS);
    acc += dg * Ma[(size_t)i * DD + d];
    out[(size_t)i * DD + d] = fmaxf(acc, 0.f);
}

// ---------------- heads --------------------------------------------------
__global__ void bias_relu(float* __restrict__ T, const float* __restrict__ b) {
    int idx = blockIdx.x * 256 + threadIdx.x;
    int d = idx & (DD - 1);
    T[idx] = fmaxf(T[idx] + b[d], 0.f);
}

__global__ void emotion_head(const float* __restrict__ T, const float* __restrict__ We2,
                             const float* __restrict__ be2, float* __restrict__ out) {
    int i = blockIdx.x;
    int w = threadIdx.x >> 5, lane = threadIdx.x & 31;
    float acc = 0.f;
    for (int k = lane; k < DD; k += 32) acc += T[(size_t)i * DD + k] * We2[k * 7 + w];
#pragma unroll
    for (int o = 16; o > 0; o >>= 1) acc += __shfl_down_sync(0xffffffffu, acc, o);
    if (lane == 0) out[i * 7 + w] = acc + be2[w];
}

__global__ void sentiment_head(const float* __restrict__ h2, const float* __restrict__ x,
                               const float* __restrict__ Wst, const float* __restrict__ bst,
                               float* __restrict__ out) {
    int i = blockIdx.x;
    int w = threadIdx.x >> 5, lane = threadIdx.x & 31;
    float acc = 0.f;
    for (int k = lane; k < DD; k += 32) acc += h2[(size_t)i * DD + k] * Wst[k * 3 + w];
    for (int k = lane; k < DD; k += 32) acc += x[(size_t)i * DD + k] * Wst[(DD + k) * 3 + w];
#pragma unroll
    for (int o = 16; o > 0; o >>= 1) acc += __shfl_down_sync(0xffffffffu, acc, o);
    if (lane == 0) out[i * 3 + w] = acc + bst[w];
}

// ---------------- launch --------------------------------------------------
extern "C" void kernel_launch(void* const* d_in, const int* in_sizes, int n_in,
                              void* d_out, int out_size) {
    const float* x = (const float*)d_in[0];
    const int* spk = (const int*)d_in[1];
    const float* Wl[2][5] = {
        {(const float*)d_in[2], (const float*)d_in[3], (const float*)d_in[4],
         (const float*)d_in[5], (const float*)d_in[10]},
        {(const float*)d_in[6], (const float*)d_in[7], (const float*)d_in[8],
         (const float*)d_in[9], (const float*)d_in[11]}};
    const float* We1 = (const float*)d_in[12];
    const float* be1 = (const float*)d_in[13];
    const float* We2 = (const float*)d_in[14];
    const float* be2 = (const float*)d_in[15];
    const float* Wst = (const float*)d_in[16];
    const float* bst = (const float*)d_in[17];
    float* out = (float*)d_out;

    float *band, *cvec, *diag, *Mp, *Ms, *Msm, *Mdf, *Ma, *PreP, *PreS, *chunk,
        *Ssm, *Sdf, *h1, *h2, *T;
    cudaGetSymbolAddress((void**)&band, g_band);
    cudaGetSymbolAddress((void**)&cvec, g_c);
    cudaGetSymbolAddress((void**)&diag, g_diag);
    cudaGetSymbolAddress((void**)&Mp, g_Mp);
    cudaGetSymbolAddress((void**)&Ms, g_Ms);
    cudaGetSymbolAddress((void**)&Msm, g_Msm);
    cudaGetSymbolAddress((void**)&Mdf, g_Mdf);
    cudaGetSymbolAddress((void**)&Ma, g_Ma);
    cudaGetSymbolAddress((void**)&PreP, g_PreP);
    cudaGetSymbolAddress((void**)&PreS, g_PreS);
    cudaGetSymbolAddress((void**)&chunk, g_chunk);
    cudaGetSymbolAddress((void**)&Ssm, g_Ssm);
    cudaGetSymbolAddress((void**)&Sdf, g_Sdf);
    cudaGetSymbolAddress((void**)&h1, g_h1);
    cudaGetSymbolAddress((void**)&h2, g_h2);
    cudaGetSymbolAddress((void**)&T, g_T);

    att_logits<<<NN, 256>>>(x, band);
    att_softmax<<<NN / 128, 128>>>(band, cvec, diag);

    dim3 ggemm(DD / 128, NN / 128);
    const float* hin = x;
    float* houts[2] = {h1, h2};
    for (int L = 0; L < 2; L++) {
        sgemm_nn<<<ggemm, 256>>>(hin, Wl[L][0], Mp, NN, DD, DD, 0);
        sgemm_nn<<<ggemm, 256>>>(hin, Wl[L][1], Ms, NN, DD, DD, 0);
        sgemm_nn<<<ggemm, 256>>>(hin, Wl[L][2], Msm, NN, DD, DD, 0);
        sgemm_nn<<<ggemm, 256>>>(hin, Wl[L][3], Mdf, NN, DD, DD, 0);
        sgemm_nn<<<ggemm, 256>>>(hin, Wl[L][4], Ma, NN, DD, DD, 0);

        scan_chunk<<<dim3(32, 4), 256>>>(Mp, chunk);
        scan_offsets<<<4, 256>>>(chunk);
        scan_write<<<dim3(32, 4), 256>>>(Mp, chunk, PreP);
        scan_chunk<<<dim3(32, 4), 256>>>(Ms, chunk);
        scan_offsets<<<4, 256>>>(chunk);
        scan_write<<<dim3(32, 4), 256>>>(Ms, chunk, PreS);

        zero2<<<(NSPK * DD + 255) / 256, 256>>>(Ssm, Sdf, NSPK * DD);
        spk_sums<<<dim3(16, 4), 256>>>(Msm, Mdf, spk, Ssm, Sdf);

        combine<<<dim3(NN, 4), 256>>>(Mp, Ms, Msm, Mdf, Ma, PreP, PreS, Ssm, Sdf,
                                      band, cvec, diag, spk, houts[L]);
        hin = houts[L];
    }

    // heads: h = [h2 | x];  T = relu(h @ We1 + be1)
    sgemm_nn<<<ggemm, 256>>>(h2, We1, T, NN, DD, DD, 0);
    sgemm_nn<<<ggemm, 256>>>(x, We1 + (size_t)DD * DD, T, NN, DD, DD, 1);
    bias_relu<<<NN * DD / 256, 256>>>(T, be1);
    emotion_head<<<NN, 224>>>(T, We2, be2, out);
    sentiment_head<<<NN, 96>>>(h2, x, Wst, bst, out + NN * 7);
}

// round 4
// speedup vs baseline: 2.2967x; 2.2967x over previous
#include <cuda_runtime.h>
#include <math.h>
#include <stdint.h>

#define NN 4096
#define DD 1024
#define WW 10
#define BAND 21
#define NSPK 8

// ---------------- device scratch (static, no allocation) ----------------
__device__ float g_band[NN * BAND];
__device__ float g_c[NN];
__device__ float g_diag[NN];
__device__ float g_Mp[NN * DD];
__device__ float g_Ms[NN * DD];
__device__ float g_Msm[NN * DD];
__device__ float g_Mdf[NN * DD];
__device__ float g_Ma[NN * DD];
__device__ float g_PreP[NN * DD];
__device__ float g_PreS[NN * DD];
__device__ float g_chunk[32 * DD];
__device__ float g_Ssm[NSPK * DD];
__device__ float g_Sdf[NSPK * DD];
__device__ float g_h1[NN * DD];
__device__ float g_h2[NN * DD];
__device__ float g_T[NN * DD];

// ---------------- banded attention logits: dot(x_i, x_j), |i-j|<=W ------
__global__ __launch_bounds__(256) void att_logits(const float* __restrict__ x,
                                                  float* __restrict__ band) {
    __shared__ float xi[DD];
    __shared__ float red[8];
    int i = blockIdx.x;
    int tid = threadIdx.x;
    for (int d = tid; d < DD; d += 256) xi[d] = x[i * DD + d];
    __syncthreads();

    float acc[BAND];
#pragma unroll
    for (int jo = 0; jo < BAND; jo++) acc[jo] = 0.f;

    for (int d = tid; d < DD; d += 256) {
        float xv = xi[d];
#pragma unroll
        for (int jo = 0; jo < BAND; jo++) {
            int j = i - WW + jo;
            if (j >= 0 && j < NN) acc[jo] += xv * x[j * DD + d];
        }
    }
    int lane = tid & 31, w = tid >> 5;
    for (int jo = 0; jo < BAND; jo++) {
        float v = acc[jo];
#pragma unroll
        for (int o = 16; o > 0; o >>= 1) v += __shfl_down_sync(0xffffffffu, v, o);
        if (lane == 0) red[w] = v;
        __syncthreads();
        if (tid == 0) {
            float s = 0.f;
#pragma unroll
            for (int k = 0; k < 8; k++) s += red[k];
            band[i * BAND + jo] = s;
        }
        __syncthreads();
    }
}

// softmax over full row: band logits + (N - band_count) exact zeros
__global__ void att_softmax(float* __restrict__ band, float* __restrict__ cvec,
                            float* __restrict__ diag) {
    int i = blockIdx.x * 128 + threadIdx.x;
    if (i >= NN) return;
    int lo = max(i - WW, 0), hi = min(i + WW, NN - 1);
    int cnt = hi - lo + 1;
    float m = 0.0f;  // zeros always present (N >> band), so max includes 0
#pragma unroll
    for (int jo = 0; jo < BAND; jo++) {
        int j = i - WW + jo;
        if (j >= 0 && j < NN) m = fmaxf(m, band[i * BAND + jo]);
    }
    float em = expf(-m);
    float Z = (float)(NN - cnt) * em;
    float vals[BAND];
#pragma unroll
    for (int jo = 0; jo < BAND; jo++) {
        int j = i - WW + jo;
        float v = 0.f;
        if (j >= 0 && j < NN) {
            v = expf(band[i * BAND + jo] - m);
            Z += v;
        }
        vals[jo] = v;
    }
    float inv = 1.0f / Z;
#pragma unroll
    for (int jo = 0; jo < BAND; jo++) band[i * BAND + jo] = vals[jo] * inv;
    cvec[i] = em * inv;
    diag[i] = vals[WW] * inv;
}

// ---------------- tf32 tensor-core GEMM ---------------------------------
// C[NN,DD] = A0[NN,DD] @ B0[DD,DD] (+ A1 @ B1 if A1 != nullptr)
// Block tile 128x128, 8 warps of 64x32, BK=16, double-buffered smem,
// mma.sync m16n8k8 tf32 with fp32 accumulate.

struct MMJob {
    const float* A0;
    const float* B0;
    const float* A1;
    const float* B1;
    float* C;
};
struct MMBatch {
    MMJob j[5];
};

__device__ __forceinline__ float f2tf32(float x) {
    uint32_t u;
    asm("cvt.rna.tf32.f32 %0, %1;" : "=r"(u) : "f"(x));
    return __uint_as_float(u);
}

__device__ __forceinline__ float4 f2tf32x4(float4 v) {
    float4 w;
    w.x = f2tf32(v.x); w.y = f2tf32(v.y); w.z = f2tf32(v.z); w.w = f2tf32(v.w);
    return w;
}

__device__ __forceinline__ void mma8(float c[4], const uint32_t a[4],
                                     const uint32_t b[2]) {
    asm volatile(
        "mma.sync.aligned.m16n8k8.row.col.f32.tf32.tf32.f32 "
        "{%0,%1,%2,%3}, {%4,%5,%6,%7}, {%8,%9}, {%0,%1,%2,%3};"
        : "+f"(c[0]), "+f"(c[1]), "+f"(c[2]), "+f"(c[3])
        : "r"(a[0]), "r"(a[1]), "r"(a[2]), "r"(a[3]), "r"(b[0]), "r"(b[1]));
}

__global__ __launch_bounds__(256) void gemm_tf32(MMBatch batch) {
    __shared__ float As[2][128][20];   // row-major, pad 16->20 (conflict-free frags)
    __shared__ float Bs[2][16][136];   // row-major, pad 128->136

    MMJob job = batch.j[blockIdx.z];
    const int tid = threadIdx.x;
    const int row0 = blockIdx.y * 128;
    const int col0 = blockIdx.x * 128;
    const int KT = job.A1 ? 128 : 64;  // 64 tiles of BK=16 per K-segment

    const int wid = tid >> 5, lane = tid & 31;
    const int g = lane >> 2, t = lane & 3;
    const int wr = (wid & 1) * 64;   // warp row offset within block tile
    const int wc = (wid >> 1) * 32;  // warp col offset

    float acc[4][4][4];
#pragma unroll
    for (int m = 0; m < 4; m++)
#pragma unroll
        for (int n = 0; n < 4; n++)
#pragma unroll
            for (int q = 0; q < 4; q++) acc[m][n][q] = 0.f;

    // prologue: load tile kt=0 into buffer 0
    {
#pragma unroll
        for (int l = 0; l < 2; l++) {
            int idx = tid + l * 256;
            int ar = idx >> 2, ac = (idx & 3) * 4;
            float4 va = *(const float4*)&job.A0[(size_t)(row0 + ar) * DD + ac];
            *(float4*)&As[0][ar][ac] = f2tf32x4(va);
            int br = idx >> 5, bc = (idx & 31) * 4;
            float4 vb = *(const float4*)&job.B0[(size_t)br * DD + col0 + bc];
            *(float4*)&Bs[0][br][bc] = f2tf32x4(vb);
        }
    }
    __syncthreads();

    for (int kt = 0; kt < KT; kt++) {
        const int buf = kt & 1;
        float4 rA[2], rB[2];
        const bool pf = (kt + 1 < KT);
        if (pf) {
            int kn = kt + 1;
            const float* A = (kn < 64) ? job.A0 : job.A1;
            const float* B = (kn < 64) ? job.B0 : job.B1;
            int kb = (kn & 63) * 16;
#pragma unroll
            for (int l = 0; l < 2; l++) {
                int idx = tid + l * 256;
                int ar = idx >> 2, ac = (idx & 3) * 4;
                rA[l] = *(const float4*)&A[(size_t)(row0 + ar) * DD + kb + ac];
                int br = idx >> 5, bc = (idx & 31) * 4;
                rB[l] = *(const float4*)&B[(size_t)(kb + br) * DD + col0 + bc];
            }
        }
        // two k8 sub-steps
#pragma unroll
        for (int ks = 0; ks < 2; ks++) {
            const int k0 = ks * 8;
            uint32_t aF[4][4], bF[4][2];
#pragma unroll
            for (int m = 0; m < 4; m++) {
                int r = wr + m * 16 + g;
                aF[m][0] = __float_as_uint(As[buf][r][k0 + t]);
                aF[m][1] = __float_as_uint(As[buf][r + 8][k0 + t]);
                aF[m][2] = __float_as_uint(As[buf][r][k0 + t + 4]);
                aF[m][3] = __float_as_uint(As[buf][r + 8][k0 + t + 4]);
            }
#pragma unroll
            for (int n = 0; n < 4; n++) {
                int c = wc + n * 8 + g;
                bF[n][0] = __float_as_uint(Bs[buf][k0 + t][c]);
                bF[n][1] = __float_as_uint(Bs[buf][k0 + t + 4][c]);
            }
#pragma unroll
            for (int m = 0; m < 4; m++)
#pragma unroll
                for (int n = 0; n < 4; n++) mma8(acc[m][n], aF[m], bF[n]);
        }
        if (pf) {
#pragma unroll
            for (int l = 0; l < 2; l++) {
                int idx = tid + l * 256;
                int ar = idx >> 2, ac = (idx & 3) * 4;
                *(float4*)&As[buf ^ 1][ar][ac] = f2tf32x4(rA[l]);
                int br = idx >> 5, bc = (idx & 31) * 4;
                *(float4*)&Bs[buf ^ 1][br][bc] = f2tf32x4(rB[l]);
            }
        }
        __syncthreads();
    }

    // epilogue
#pragma unroll
    for (int m = 0; m < 4; m++) {
        int r = row0 + wr + m * 16 + g;
#pragma unroll
        for (int n = 0; n < 4; n++) {
            int c = col0 + wc + n * 8 + t * 2;
            *(float2*)&job.C[(size_t)r * DD + c] =
                make_float2(acc[m][n][0], acc[m][n][1]);
            *(float2*)&job.C[(size_t)(r + 8) * DD + c] =
                make_float2(acc[m][n][2], acc[m][n][3]);
        }
    }
}

// ---------------- chunked prefix scan along rows (per column) -----------
__global__ void scan_chunk(const float* __restrict__ M, float* __restrict__ chunk) {
    int d = blockIdx.y * 256 + threadIdx.x;
    int c = blockIdx.x;
    int base = c * 128;
    float s = 0.f;
#pragma unroll 4
    for (int r = 0; r < 128; r++) s += M[(size_t)(base + r) * DD + d];
    chunk[c * DD + d] = s;
}

__global__ void scan_offsets(float* __restrict__ chunk) {
    int d = blockIdx.x * 256 + threadIdx.x;
    float off = 0.f;
#pragma unroll
    for (int c = 0; c < 32; c++) {
        float t = chunk[c * DD + d];
        chunk[c * DD + d] = off;  // exclusive
        off += t;
    }
}

__global__ void scan_write(const float* __restrict__ M, const float* __restrict__ chunk,
                           float* __restrict__ P) {
    int d = blockIdx.y * 256 + threadIdx.x;
    int c = blockIdx.x;
    int base = c * 128;
    float acc = chunk[c * DD + d];
#pragma unroll 4
    for (int r = 0; r < 128; r++) {
        acc += M[(size_t)(base + r) * DD + d];
        P[(size_t)(base + r) * DD + d] = acc;  // inclusive prefix
    }
}

__global__ void zero2(float* __restrict__ a, float* __restrict__ b, int n) {
    int i = blockIdx.x * 256 + threadIdx.x;
    if (i < n) { a[i] = 0.f; b[i] = 0.f; }
}

// per-speaker column sums for Msm and Mdf
__global__ __launch_bounds__(256) void spk_sums(const float* __restrict__ Msm,
                                                const float* __restrict__ Mdf,
                                                const int* __restrict__ spk,
                                                float* __restrict__ Ssm,
                                                float* __restrict__ Sdf) {
    __shared__ float s1[NSPK * 256];
    __shared__ float s2[NSPK * 256];
    int tid = threadIdx.x;
    int d = blockIdx.y * 256 + tid;
#pragma unroll
    for (int k = 0; k < NSPK; k++) { s1[k * 256 + tid] = 0.f; s2[k * 256 + tid] = 0.f; }
    int base = blockIdx.x * 256;
    for (int r = 0; r < 256; r++) {
        int j = base + r;
        int sp = spk[j];
        s1[sp * 256 + tid] += Msm[(size_t)j * DD + d];
        s2[sp * 256 + tid] += Mdf[(size_t)j * DD + d];
    }
#pragma unroll
    for (int k = 0; k < NSPK; k++) {
        atomicAdd(&Ssm[k * DD + d], s1[k * 256 + tid]);
        atomicAdd(&Sdf[k * DD + d], s2[k * 256 + tid]);
    }
}

// ---------------- band combine + diag self-term + relu ------------------
__global__ __launch_bounds__(256) void combine(
    const float* __restrict__ Mp, const float* __restrict__ Ms,
    const float* __restrict__ Msm, const float* __restrict__ Mdf,
    const float* __restrict__ Ma,
    const float* __restrict__ PreP, const float* __restrict__ PreS,
    const float* __restrict__ Ssm, const float* __restrict__ Sdf,
    const float* __restrict__ band, const float* __restrict__ cvec,
    const float* __restrict__ diag, const int* __restrict__ spk,
    float* __restrict__ out) {
    int i = blockIdx.x;
    int d = blockIdx.y * 256 + threadIdx.x;
    __shared__ float a_sh[BAND];
    __shared__ int sp_sh[BAND];
    __shared__ float cs, dg;
    __shared__ int spi;
    if (threadIdx.x < BAND) {
        int j = i - WW + (int)threadIdx.x;
        bool valid = (j >= 0 && j < NN);
        a_sh[threadIdx.x] = valid ? band[i * BAND + threadIdx.x] : 0.f;
        sp_sh[threadIdx.x] = valid ? spk[j] : -1;
    }
    if (threadIdx.x == 0) { cs = cvec[i]; dg = diag[i]; spi = spk[i]; }
    __syncthreads();

    float c = cs;
    float acc = 0.f;
#pragma unroll
    for (int jo = 0; jo < BAND; jo++) {
        int spj = sp_sh[jo];
        if (spj < 0) continue;  // block-uniform branch
        int j = i - WW + jo;
        float a = a_sh[jo];
        // pred (j>=i) uses Mp; suc (j<i) uses Ms
        float v1 = (jo >= WW) ? Mp[(size_t)j * DD + d] : Ms[(size_t)j * DD + d];
        acc += a * v1;
        // same/diff: coefficient (a - c) on band; c * speaker-sum added below
        float v2 = (spj == spi) ? Msm[(size_t)j * DD + d] : Mdf[(size_t)j * DD + d];
        acc += (a - c) * v2;
    }
    int hi = min(i + WW, NN - 1);
    float suf = PreP[(size_t)(NN - 1) * DD + d] - PreP[(size_t)hi * DD + d];
    float pre = (i - WW - 1 >= 0) ? PreS[(size_t)(i - WW - 1) * DD + d] : 0.f;
    float stot = 0.f;
#pragma unroll
    for (int k = 0; k < NSPK; k++) stot += Sdf[k * DD + d];
    float sameS = Ssm[spi * DD + d];
    float diffS = stot - Sdf[spi * DD + d];
    acc += c * (suf + pre + sameS + diffS);
    acc += dg * Ma[(size_t)i * DD + d];
    out[(size_t)i * DD + d] = fmaxf(acc, 0.f);
}

// ---------------- heads --------------------------------------------------
__global__ void bias_relu(float* __restrict__ T, const float* __restrict__ b) {
    int idx = blockIdx.x * 256 + threadIdx.x;
    int d = idx & (DD - 1);
    T[idx] = fmaxf(T[idx] + b[d], 0.f);
}

__global__ void emotion_head(const float* __restrict__ T, const float* __restrict__ We2,
                             const float* __restrict__ be2, float* __restrict__ out) {
    int i = blockIdx.x;
    int w = threadIdx.x >> 5, lane = threadIdx.x & 31;
    float acc = 0.f;
    for (int k = lane; k < DD; k += 32) acc += T[(size_t)i * DD + k] * We2[k * 7 + w];
#pragma unroll
    for (int o = 16; o > 0; o >>= 1) acc += __shfl_down_sync(0xffffffffu, acc, o);
    if (lane == 0) out[i * 7 + w] = acc + be2[w];
}

__global__ void sentiment_head(const float* __restrict__ h2, const float* __restrict__ x,
                               const float* __restrict__ Wst, const float* __restrict__ bst,
                               float* __restrict__ out) {
    int i = blockIdx.x;
    int w = threadIdx.x >> 5, lane = threadIdx.x & 31;
    float acc = 0.f;
    for (int k = lane; k < DD; k += 32) acc += h2[(size_t)i * DD + k] * Wst[k * 3 + w];
    for (int k = lane; k < DD; k += 32) acc += x[(size_t)i * DD + k] * Wst[(DD + k) * 3 + w];
#pragma unroll
    for (int o = 16; o > 0; o >>= 1) acc += __shfl_down_sync(0xffffffffu, acc, o);
    if (lane == 0) out[i * 3 + w] = acc + bst[w];
}

// ---------------- launch --------------------------------------------------
extern "C" void kernel_launch(void* const* d_in, const int* in_sizes, int n_in,
                              void* d_out, int out_size) {
    const float* x = (const float*)d_in[0];
    const int* spk = (const int*)d_in[1];
    const float* Wl[2][5] = {
        {(const float*)d_in[2], (const float*)d_in[3], (const float*)d_in[4],
         (const float*)d_in[5], (const float*)d_in[10]},
        {(const float*)d_in[6], (const float*)d_in[7], (const float*)d_in[8],
         (const float*)d_in[9], (const float*)d_in[11]}};
    const float* We1 = (const float*)d_in[12];
    const float* be1 = (const float*)d_in[13];
    const float* We2 = (const float*)d_in[14];
    const float* be2 = (const float*)d_in[15];
    const float* Wst = (const float*)d_in[16];
    const float* bst = (const float*)d_in[17];
    float* out = (float*)d_out;

    float *band, *cvec, *diag, *Mp, *Ms, *Msm, *Mdf, *Ma, *PreP, *PreS, *chunk,
        *Ssm, *Sdf, *h1, *h2, *T;
    cudaGetSymbolAddress((void**)&band, g_band);
    cudaGetSymbolAddress((void**)&cvec, g_c);
    cudaGetSymbolAddress((void**)&diag, g_diag);
    cudaGetSymbolAddress((void**)&Mp, g_Mp);
    cudaGetSymbolAddress((void**)&Ms, g_Ms);
    cudaGetSymbolAddress((void**)&Msm, g_Msm);
    cudaGetSymbolAddress((void**)&Mdf, g_Mdf);
    cudaGetSymbolAddress((void**)&Ma, g_Ma);
    cudaGetSymbolAddress((void**)&PreP, g_PreP);
    cudaGetSymbolAddress((void**)&PreS, g_PreS);
    cudaGetSymbolAddress((void**)&chunk, g_chunk);
    cudaGetSymbolAddress((void**)&Ssm, g_Ssm);
    cudaGetSymbolAddress((void**)&Sdf, g_Sdf);
    cudaGetSymbolAddress((void**)&h1, g_h1);
    cudaGetSymbolAddress((void**)&h2, g_h2);
    cudaGetSymbolAddress((void**)&T, g_T);

    att_logits<<<NN, 256>>>(x, band);
    att_softmax<<<NN / 128, 128>>>(band, cvec, diag);

    const float* hin = x;
    float* houts[2] = {h1, h2};
    float* Mdst[5];
    Mdst[0] = Mp; Mdst[1] = Ms; Mdst[2] = Msm; Mdst[3] = Mdf; Mdst[4] = Ma;

    for (int L = 0; L < 2; L++) {
        MMBatch b;
        for (int q = 0; q < 5; q++) {
            b.j[q].A0 = hin;
            b.j[q].B0 = Wl[L][q];
            b.j[q].A1 = nullptr;
            b.j[q].B1 = nullptr;
            b.j[q].C = Mdst[q];
        }
        gemm_tf32<<<dim3(DD / 128, NN / 128, 5), 256>>>(b);

        scan_chunk<<<dim3(32, 4), 256>>>(Mp, chunk);
        scan_offsets<<<4, 256>>>(chunk);
        scan_write<<<dim3(32, 4), 256>>>(Mp, chunk, PreP);
        scan_chunk<<<dim3(32, 4), 256>>>(Ms, chunk);
        scan_offsets<<<4, 256>>>(chunk);
        scan_write<<<dim3(32, 4), 256>>>(Ms, chunk, PreS);

        zero2<<<(NSPK * DD + 255) / 256, 256>>>(Ssm, Sdf, NSPK * DD);
        spk_sums<<<dim3(16, 4), 256>>>(Msm, Mdf, spk, Ssm, Sdf);

        combine<<<dim3(NN, 4), 256>>>(Mp, Ms, Msm, Mdf, Ma, PreP, PreS, Ssm, Sdf,
                                      band, cvec, diag, spk, houts[L]);
        hin = houts[L];
    }

    // heads: h = [h2 | x];  T = relu(h @ We1 + be1) in ONE dual-K GEMM launch
    {
        MMBatch hb;
        for (int q = 0; q < 5; q++) {
            hb.j[q].A0 = h2;
            hb.j[q].B0 = We1;
            hb.j[q].A1 = x;
            hb.j[q].B1 = We1 + (size_t)DD * DD;
            hb.j[q].C = T;
        }
        gemm_tf32<<<dim3(DD / 128, NN / 128, 1), 256>>>(hb);
    }
    bias_relu<<<NN * DD / 256, 256>>>(T, be1);
    emotion_head<<<NN, 224>>>(T, We2, be2, out);
    sentiment_head<<<NN, 96>>>(h2, x, Wst, bst, out + NN * 7);
}

// round 5
// speedup vs baseline: 2.8250x; 1.2300x over previous
#include <cuda_runtime.h>
#include <math.h>
#include <stdint.h>

#define NN 4096
#define DD 1024
#define WW 10
#define BAND 21
#define NSPK 8

// ---------------- device scratch (static, no allocation) ----------------
__device__ float g_band[NN * BAND];
__device__ float g_c[NN];
__device__ float g_diag[NN];
__device__ float g_Pre[NN * DD];
__device__ float g_chunk[32 * DD];
__device__ float g_S[NSPK * DD];
__device__ float g_Y[NN * 5 * DD];
__device__ float g_h1[NN * DD];
__device__ float g_h2[NN * DD];
__device__ float g_T[NN * DD];

// ---------------- banded attention logits: dot(x_i, x_j), |i-j|<=W ------
__global__ __launch_bounds__(256) void att_logits(const float* __restrict__ x,
                                                  float* __restrict__ band) {
    __shared__ float xi[DD];
    __shared__ float red[8];
    int i = blockIdx.x;
    int tid = threadIdx.x;
    for (int d = tid; d < DD; d += 256) xi[d] = x[i * DD + d];
    __syncthreads();

    float acc[BAND];
#pragma unroll
    for (int jo = 0; jo < BAND; jo++) acc[jo] = 0.f;

    for (int d = tid; d < DD; d += 256) {
        float xv = xi[d];
#pragma unroll
        for (int jo = 0; jo < BAND; jo++) {
            int j = i - WW + jo;
            if (j >= 0 && j < NN) acc[jo] += xv * x[j * DD + d];
        }
    }
    int lane = tid & 31, w = tid >> 5;
    for (int jo = 0; jo < BAND; jo++) {
        float v = acc[jo];
#pragma unroll
        for (int o = 16; o > 0; o >>= 1) v += __shfl_down_sync(0xffffffffu, v, o);
        if (lane == 0) red[w] = v;
        __syncthreads();
        if (tid == 0) {
            float s = 0.f;
#pragma unroll
            for (int k = 0; k < 8; k++) s += red[k];
            band[i * BAND + jo] = s;
        }
        __syncthreads();
    }
}

// softmax over full row: band logits + (N - band_count) exact zeros
__global__ void att_softmax(float* __restrict__ band, float* __restrict__ cvec,
                            float* __restrict__ diag) {
    int i = blockIdx.x * 128 + threadIdx.x;
    if (i >= NN) return;
    int lo = max(i - WW, 0), hi = min(i + WW, NN - 1);
    int cnt = hi - lo + 1;
    float m = 0.0f;  // zeros always present (N >> band), so max includes 0
#pragma unroll
    for (int jo = 0; jo < BAND; jo++) {
        int j = i - WW + jo;
        if (j >= 0 && j < NN) m = fmaxf(m, band[i * BAND + jo]);
    }
    float em = expf(-m);
    float Z = (float)(NN - cnt) * em;
    float vals[BAND];
#pragma unroll
    for (int jo = 0; jo < BAND; jo++) {
        int j = i - WW + jo;
        float v = 0.f;
        if (j >= 0 && j < NN) {
            v = expf(band[i * BAND + jo] - m);
            Z += v;
        }
        vals[jo] = v;
    }
    float inv = 1.0f / Z;
#pragma unroll
    for (int jo = 0; jo < BAND; jo++) band[i * BAND + jo] = vals[jo] * inv;
    cvec[i] = em * inv;
    diag[i] = vals[WW] * inv;
}

// ---------------- chunked prefix scan along rows (per column) -----------
__global__ void scan_chunk(const float* __restrict__ M, float* __restrict__ chunk) {
    int d = blockIdx.y * 256 + threadIdx.x;
    int c = blockIdx.x;
    int base = c * 128;
    float s = 0.f;
#pragma unroll 4
    for (int r = 0; r < 128; r++) s += M[(size_t)(base + r) * DD + d];
    chunk[c * DD + d] = s;
}

__global__ void scan_offsets(float* __restrict__ chunk) {
    int d = blockIdx.x * 256 + threadIdx.x;
    float off = 0.f;
#pragma unroll
    for (int c = 0; c < 32; c++) {
        float t = chunk[c * DD + d];
        chunk[c * DD + d] = off;  // exclusive
        off += t;
    }
}

__global__ void scan_write(const float* __restrict__ M, const float* __restrict__ chunk,
                           float* __restrict__ P) {
    int d = blockIdx.y * 256 + threadIdx.x;
    int c = blockIdx.x;
    int base = c * 128;
    float acc = chunk[c * DD + d];
#pragma unroll 4
    for (int r = 0; r < 128; r++) {
        acc += M[(size_t)(base + r) * DD + d];
        P[(size_t)(base + r) * DD + d] = acc;  // inclusive prefix
    }
}

__global__ void zero1(float* __restrict__ a, int n) {
    int i = blockIdx.x * 256 + threadIdx.x;
    if (i < n) a[i] = 0.f;
}

// per-speaker column sums of h
__global__ __launch_bounds__(256) void spk_sums1(const float* __restrict__ h,
                                                 const int* __restrict__ spk,
                                                 float* __restrict__ S) {
    __shared__ float s1[NSPK * 256];
    int tid = threadIdx.x;
    int d = blockIdx.y * 256 + tid;
#pragma unroll
    for (int k = 0; k < NSPK; k++) s1[k * 256 + tid] = 0.f;
    int base = blockIdx.x * 256;
    for (int r = 0; r < 256; r++) {
        int j = base + r;
        s1[spk[j] * 256 + tid] += h[(size_t)j * DD + d];
    }
#pragma unroll
    for (int k = 0; k < NSPK; k++) atomicAdd(&S[k * DD + d], s1[k * 256 + tid]);
}

// ---------------- build Y = [ypred | ysuc | ysame | ydiff | diag*h] -----
// ypred_i = sum_{j>=i,band} a*h_j + c_i*(tot - Pre[i+W])
// ysuc_i  = sum_{j<i,band}  a*h_j + c_i*Pre[i-W-1]
// ysame_i = sum_band (a-c)*[spk==]*h_j + c_i*S[spk_i]
// ydiff_i = sum_band (a-c)*[spk!=]*h_j + c_i*(tot - S[spk_i])
__global__ __launch_bounds__(256) void build_y(
    const float* __restrict__ h, const float* __restrict__ Pre,
    const float* __restrict__ S, const float* __restrict__ band,
    const float* __restrict__ cvec, const float* __restrict__ diag,
    const int* __restrict__ spk, float* __restrict__ Y) {
    __shared__ float hs[36][256];
    __shared__ float a_sh[16][21];
    __shared__ int sp_sh[36];
    __shared__ float c_sh[16], dg_sh[16];
    __shared__ int spi_sh[16];
    int tid = threadIdx.x;
    int i0 = blockIdx.x * 16;
    int d = blockIdx.y * 256 + tid;

#pragma unroll
    for (int r = 0; r < 36; r++) {
        int j = i0 - WW + r;
        hs[r][tid] = (j >= 0 && j < NN) ? h[(size_t)j * DD + d] : 0.f;
    }
    for (int idx = tid; idx < 16 * 21; idx += 256) {
        int il = idx / 21, jo = idx - il * 21;
        int i = i0 + il, j = i - WW + jo;
        a_sh[il][jo] = (j >= 0 && j < NN) ? band[i * BAND + jo] : 0.f;
    }
    if (tid < 36) {
        int j = i0 - WW + tid;
        sp_sh[tid] = (j >= 0 && j < NN) ? spk[j] : -1;
    }
    if (tid < 16) {
        c_sh[tid] = cvec[i0 + tid];
        dg_sh[tid] = diag[i0 + tid];
        spi_sh[tid] = spk[i0 + tid];
    }
    __syncthreads();

    float tot = Pre[(size_t)(NN - 1) * DD + d];
#pragma unroll 2
    for (int ti = 0; ti < 16; ti++) {
        int i = i0 + ti;
        float c = c_sh[ti];
        int spi = spi_sh[ti];
        float yp = 0.f, ys = 0.f, ysm = 0.f, ydf = 0.f;
#pragma unroll
        for (int jo = 0; jo < BAND; jo++) {
            float a = a_sh[ti][jo];
            float hv = hs[ti + jo][tid];
            if (jo >= WW) yp += a * hv; else ys += a * hv;
            float t = (a - c) * hv;
            if (sp_sh[ti + jo] == spi) ysm += t; else ydf += t;
        }
        int hi = min(i + WW, NN - 1);
        yp += c * (tot - Pre[(size_t)hi * DD + d]);
        if (i - WW - 1 >= 0) ys += c * Pre[(size_t)(i - WW - 1) * DD + d];
        float Ssp = S[spi * DD + d];
        ysm += c * Ssp;
        ydf += c * (tot - Ssp);
        size_t base = (size_t)i * (5 * DD) + d;
        Y[base] = yp;
        Y[base + DD] = ys;
        Y[base + 2 * DD] = ysm;
        Y[base + 3 * DD] = ydf;
        Y[base + 4 * DD] = dg_sh[ti] * hs[ti + WW][tid];
    }
}

// ---------------- tf32 tensor-core GEMM (segmented K, fused epilogue) ---
// C[NN,DD] = sum_s Aseg[s][:,0:1024] @ Bseg[s]   (+bias, relu optional)
struct GJob {
    const float* Aseg[5];
    const float* Bseg[5];
    const float* bias;  // nullptr = none
    float* C;
    int nseg;
    int lda;
    int relu;
};

__device__ __forceinline__ float f2tf32(float x) {
    uint32_t u;
    asm("cvt.rna.tf32.f32 %0, %1;" : "=r"(u) : "f"(x));
    return __uint_as_float(u);
}

__device__ __forceinline__ float4 f2tf32x4(float4 v) {
    float4 w;
    w.x = f2tf32(v.x); w.y = f2tf32(v.y); w.z = f2tf32(v.z); w.w = f2tf32(v.w);
    return w;
}

__device__ __forceinline__ void mma8(float c[4], const uint32_t a[4],
                                     const uint32_t b[2]) {
    asm volatile(
        "mma.sync.aligned.m16n8k8.row.col.f32.tf32.tf32.f32 "
        "{%0,%1,%2,%3}, {%4,%5,%6,%7}, {%8,%9}, {%0,%1,%2,%3};"
        : "+f"(c[0]), "+f"(c[1]), "+f"(c[2]), "+f"(c[3])
        : "r"(a[0]), "r"(a[1]), "r"(a[2]), "r"(a[3]), "r"(b[0]), "r"(b[1]));
}

__global__ __launch_bounds__(256) void gemm_tf32(GJob job) {
    __shared__ float As[2][128][20];   // pad 16->20
    __shared__ float Bs[2][16][136];   // pad 128->136

    const int tid = threadIdx.x;
    const int row0 = blockIdx.y * 128;
    const int col0 = blockIdx.x * 128;
    const int KT = job.nseg * 64;
    const int lda = job.lda;

    const int wid = tid >> 5, lane = tid & 31;
    const int g = lane >> 2, t = lane & 3;
    const int wr = (wid & 1) * 64;
    const int wc = (wid >> 1) * 32;

    float acc[4][4][4];
#pragma unroll
    for (int m = 0; m < 4; m++)
#pragma unroll
        for (int n = 0; n < 4; n++)
#pragma unroll
            for (int q = 0; q < 4; q++) acc[m][n][q] = 0.f;

    // prologue: tile kt=0
    {
        const float* A = job.Aseg[0];
        const float* B = job.Bseg[0];
#pragma unroll
        for (int l = 0; l < 2; l++) {
            int idx = tid + l * 256;
            int ar = idx >> 2, ac = (idx & 3) * 4;
            float4 va = *(const float4*)&A[(size_t)(row0 + ar) * lda + ac];
            *(float4*)&As[0][ar][ac] = f2tf32x4(va);
            int br = idx >> 5, bc = (idx & 31) * 4;
            float4 vb = *(const float4*)&B[(size_t)br * DD + col0 + bc];
            *(float4*)&Bs[0][br][bc] = f2tf32x4(vb);
        }
    }
    __syncthreads();

    for (int kt = 0; kt < KT; kt++) {
        const int buf = kt & 1;
        float4 rA[2], rB[2];
        const bool pf = (kt + 1 < KT);
        if (pf) {
            int kn = kt + 1;
            int seg = kn >> 6;
            int kb = (kn & 63) * 16;
            const float* A = job.Aseg[seg];
            const float* B = job.Bseg[seg];
#pragma unroll
            for (int l = 0; l < 2; l++) {
                int idx = tid + l * 256;
                int ar = idx >> 2, ac = (idx & 3) * 4;
                rA[l] = *(const float4*)&A[(size_t)(row0 + ar) * lda + kb + ac];
                int br = idx >> 5, bc = (idx & 31) * 4;
                rB[l] = *(const float4*)&B[(size_t)(kb + br) * DD + col0 + bc];
            }
        }
#pragma unroll
        for (int ks = 0; ks < 2; ks++) {
            const int k0 = ks * 8;
            uint32_t aF[4][4], bF[4][2];
#pragma unroll
            for (int m = 0; m < 4; m++) {
                int r = wr + m * 16 + g;
                aF[m][0] = __float_as_uint(As[buf][r][k0 + t]);
                aF[m][1] = __float_as_uint(As[buf][r + 8][k0 + t]);
                aF[m][2] = __float_as_uint(As[buf][r][k0 + t + 4]);
                aF[m][3] = __float_as_uint(As[buf][r + 8][k0 + t + 4]);
            }
#pragma unroll
            for (int n = 0; n < 4; n++) {
                int c = wc + n * 8 + g;
                bF[n][0] = __float_as_uint(Bs[buf][k0 + t][c]);
                bF[n][1] = __float_as_uint(Bs[buf][k0 + t + 4][c]);
            }
#pragma unroll
            for (int m = 0; m < 4; m++)
#pragma unroll
                for (int n = 0; n < 4; n++) mma8(acc[m][n], aF[m], bF[n]);
        }
        if (pf) {
#pragma unroll
            for (int l = 0; l < 2; l++) {
                int idx = tid + l * 256;
                int ar = idx >> 2, ac = (idx & 3) * 4;
                *(float4*)&As[buf ^ 1][ar][ac] = f2tf32x4(rA[l]);
                int br = idx >> 5, bc = (idx & 31) * 4;
                *(float4*)&Bs[buf ^ 1][br][bc] = f2tf32x4(rB[l]);
            }
        }
        __syncthreads();
    }

    // epilogue: optional bias + relu
#pragma unroll
    for (int m = 0; m < 4; m++) {
        int r = row0 + wr + m * 16 + g;
#pragma unroll
        for (int n = 0; n < 4; n++) {
            int c = col0 + wc + n * 8 + t * 2;
            float2 v0 = make_float2(acc[m][n][0], acc[m][n][1]);
            float2 v1 = make_float2(acc[m][n][2], acc[m][n][3]);
            if (job.bias) {
                float2 b2 = *(const float2*)&job.bias[c];
                v0.x += b2.x; v0.y += b2.y; v1.x += b2.x; v1.y += b2.y;
            }
            if (job.relu) {
                v0.x = fmaxf(v0.x, 0.f); v0.y = fmaxf(v0.y, 0.f);
                v1.x = fmaxf(v1.x, 0.f); v1.y = fmaxf(v1.y, 0.f);
            }
            *(float2*)&job.C[(size_t)r * DD + c] = v0;
            *(float2*)&job.C[(size_t)(r + 8) * DD + c] = v1;
        }
    }
}

// ---------------- heads --------------------------------------------------
__global__ void emotion_head(const float* __restrict__ T, const float* __restrict__ We2,
                             const float* __restrict__ be2, float* __restrict__ out) {
    int i = blockIdx.x;
    int w = threadIdx.x >> 5, lane = threadIdx.x & 31;
    float acc = 0.f;
    for (int k = lane; k < DD; k += 32) acc += T[(size_t)i * DD + k] * We2[k * 7 + w];
#pragma unroll
    for (int o = 16; o > 0; o >>= 1) acc += __shfl_down_sync(0xffffffffu, acc, o);
    if (lane == 0) out[i * 7 + w] = acc + be2[w];
}

__global__ void sentiment_head(const float* __restrict__ h2, const float* __restrict__ x,
                               const float* __restrict__ Wst, const float* __restrict__ bst,
                               float* __restrict__ out) {
    int i = blockIdx.x;
    int w = threadIdx.x >> 5, lane = threadIdx.x & 31;
    float acc = 0.f;
    for (int k = lane; k < DD; k += 32) acc += h2[(size_t)i * DD + k] * Wst[k * 3 + w];
    for (int k = lane; k < DD; k += 32) acc += x[(size_t)i * DD + k] * Wst[(DD + k) * 3 + w];
#pragma unroll
    for (int o = 16; o > 0; o >>= 1) acc += __shfl_down_sync(0xffffffffu, acc, o);
    if (lane == 0) out[i * 3 + w] = acc + bst[w];
}

// ---------------- launch --------------------------------------------------
extern "C" void kernel_launch(void* const* d_in, const int* in_sizes, int n_in,
                              void* d_out, int out_size) {
    const float* x = (const float*)d_in[0];
    const int* spk = (const int*)d_in[1];
    const float* Wl[2][5] = {
        {(const float*)d_in[2], (const float*)d_in[3], (const float*)d_in[4],
         (const float*)d_in[5], (const float*)d_in[10]},
        {(const float*)d_in[6], (const float*)d_in[7], (const float*)d_in[8],
         (const float*)d_in[9], (const float*)d_in[11]}};
    const float* We1 = (const float*)d_in[12];
    const float* be1 = (const float*)d_in[13];
    const float* We2 = (const float*)d_in[14];
    const float* be2 = (const float*)d_in[15];
    const float* Wst = (const float*)d_in[16];
    const float* bst = (const float*)d_in[17];
    float* out = (float*)d_out;

    float *band, *cvec, *diag, *Pre, *chunk, *S, *Y, *h1, *h2, *T;
    cudaGetSymbolAddress((void**)&band, g_band);
    cudaGetSymbolAddress((void**)&cvec, g_c);
    cudaGetSymbolAddress((void**)&diag, g_diag);
    cudaGetSymbolAddress((void**)&Pre, g_Pre);
    cudaGetSymbolAddress((void**)&chunk, g_chunk);
    cudaGetSymbolAddress((void**)&S, g_S);
    cudaGetSymbolAddress((void**)&Y, g_Y);
    cudaGetSymbolAddress((void**)&h1, g_h1);
    cudaGetSymbolAddress((void**)&h2, g_h2);
    cudaGetSymbolAddress((void**)&T, g_T);

    att_logits<<<NN, 256>>>(x, band);
    att_softmax<<<NN / 128, 128>>>(band, cvec, diag);

    const float* hin = x;
    float* houts[2] = {h1, h2};
    dim3 ggemm(DD / 128, NN / 128);

    for (int L = 0; L < 2; L++) {
        scan_chunk<<<dim3(32, 4), 256>>>(hin, chunk);
        scan_offsets<<<4, 256>>>(chunk);
        scan_write<<<dim3(32, 4), 256>>>(hin, chunk, Pre);
        zero1<<<(NSPK * DD + 255) / 256, 256>>>(S, NSPK * DD);
        spk_sums1<<<dim3(16, 4), 256>>>(hin, spk, S);
        build_y<<<dim3(NN / 16, 4), 256>>>(hin, Pre, S, band, cvec, diag, spk, Y);

        GJob jb;
        for (int s = 0; s < 5; s++) {
            jb.Aseg[s] = Y + (size_t)s * DD;
            jb.Bseg[s] = Wl[L][s];
        }
        jb.bias = nullptr;
        jb.C = houts[L];
        jb.nseg = 5;
        jb.lda = 5 * DD;
        jb.relu = 1;
        gemm_tf32<<<ggemm, 256>>>(jb);
        hin = houts[L];
    }

    // heads: h = [h2 | x];  T = relu(h @ We1 + be1) in one GEMM (bias+relu fused)
    {
        GJob jb;
        jb.Aseg[0] = h2; jb.Aseg[1] = x;
        jb.Bseg[0] = We1; jb.Bseg[1] = We1 + (size_t)DD * DD;
        for (int s = 2; s < 5; s++) { jb.Aseg[s] = nullptr; jb.Bseg[s] = nullptr; }
        jb.bias = be1;
        jb.C = T;
        jb.nseg = 2;
        jb.lda = DD;
        jb.relu = 1;
        gemm_tf32<<<ggemm, 256>>>(jb);
    }
    emotion_head<<<NN, 224>>>(T, We2, be2, out);
    sentiment_head<<<NN, 96>>>(h2, x, Wst, bst, out + NN * 7);
}

// round 7
// speedup vs baseline: 2.9003x; 1.0266x over previous
#include <cuda_runtime.h>
#include <math.h>
#include <stdint.h>

#define NN 4096
#define DD 1024
#define WW 10
#define BAND 21
#define NSPK 8

// ---------------- device scratch (static, no allocation) ----------------
__device__ float g_band[NN * BAND];
__device__ float g_c[NN];
__device__ float g_diag[NN];
__device__ float g_Pre[NN * DD];
__device__ float g_chunk[32 * DD];
__device__ float g_S[NSPK * DD];
__device__ float g_Y[NN * 5 * DD];
__device__ float g_h1[NN * DD];
__device__ float g_h2[NN * DD];
__device__ float g_T[NN * DD];
__device__ float g_Wr[12 * DD * DD];   // tf32-rounded weights
__device__ float g_Xr[NN * DD];        // tf32-rounded x

// ---------------- helpers -------------------------------------------------
__device__ __forceinline__ uint32_t smem_u32(const void* p) {
    uint32_t a;
    asm("{ .reg .u64 t; cvta.to.shared.u64 t, %1; cvt.u32.u64 %0, t; }"
        : "=r"(a) : "l"(p));
    return a;
}

__device__ __forceinline__ float f2tf32(float x) {
    uint32_t u;
    asm("cvt.rna.tf32.f32 %0, %1;" : "=r"(u) : "f"(x));
    return __uint_as_float(u);
}
__device__ __forceinline__ float4 f2tf32x4(float4 v) {
    float4 w;
    w.x = f2tf32(v.x); w.y = f2tf32(v.y); w.z = f2tf32(v.z); w.w = f2tf32(v.w);
    return w;
}

__device__ __forceinline__ void cp16(uint32_t dst, const void* src) {
    asm volatile("cp.async.cg.shared.global [%0], [%1], 16;"
                 :: "r"(dst), "l"(src) : "memory");
}
#define CP_COMMIT() asm volatile("cp.async.commit_group;" ::: "memory")
#define CP_WAIT2()  asm volatile("cp.async.wait_group 2;" ::: "memory")

__device__ __forceinline__ void mma8(float c[4], const uint32_t a[4],
                                     const uint32_t b[2]) {
    asm volatile(
        "mma.sync.aligned.m16n8k8.row.col.f32.tf32.tf32.f32 "
        "{%0,%1,%2,%3}, {%4,%5,%6,%7}, {%8,%9}, {%0,%1,%2,%3};"
        : "+f"(c[0]), "+f"(c[1]), "+f"(c[2]), "+f"(c[3])
        : "r"(a[0]), "r"(a[1]), "r"(a[2]), "r"(a[3]), "r"(b[0]), "r"(b[1]));
}

// ---------------- one-time rounding passes --------------------------------
struct WPack { const float* p[12]; };

__global__ __launch_bounds__(256) void round_w(WPack w, float* __restrict__ dst) {
    int z = blockIdx.y;
    size_t i = ((size_t)blockIdx.x * 256 + threadIdx.x) * 4;
    float4 v = *(const float4*)&w.p[z][i];
    *(float4*)&dst[(size_t)z * DD * DD + i] = f2tf32x4(v);
}

__global__ __launch_bounds__(256) void round_x(const float* __restrict__ x,
                                               float* __restrict__ xr) {
    size_t i = ((size_t)blockIdx.x * 256 + threadIdx.x) * 4;
    *(float4*)&xr[i] = f2tf32x4(*(const float4*)&x[i]);
}

// ---------------- banded attention logits: dot(x_i, x_j), |i-j|<=W ------
__global__ __launch_bounds__(256) void att_logits(const float* __restrict__ x,
                                                  float* __restrict__ band) {
    __shared__ float xi[DD];
    __shared__ float red[8];
    int i = blockIdx.x;
    int tid = threadIdx.x;
    for (int d = tid; d < DD; d += 256) xi[d] = x[i * DD + d];
    __syncthreads();

    float acc[BAND];
#pragma unroll
    for (int jo = 0; jo < BAND; jo++) acc[jo] = 0.f;

    for (int d = tid; d < DD; d += 256) {
        float xv = xi[d];
#pragma unroll
        for (int jo = 0; jo < BAND; jo++) {
            int j = i - WW + jo;
            if (j >= 0 && j < NN) acc[jo] += xv * x[j * DD + d];
        }
    }
    int lane = tid & 31, w = tid >> 5;
    for (int jo = 0; jo < BAND; jo++) {
        float v = acc[jo];
#pragma unroll
        for (int o = 16; o > 0; o >>= 1) v += __shfl_down_sync(0xffffffffu, v, o);
        if (lane == 0) red[w] = v;
        __syncthreads();
        if (tid == 0) {
            float s = 0.f;
#pragma unroll
            for (int k = 0; k < 8; k++) s += red[k];
            band[i * BAND + jo] = s;
        }
        __syncthreads();
    }
}

// softmax over full row: band logits + (N - band_count) exact zeros
__global__ void att_softmax(float* __restrict__ band, float* __restrict__ cvec,
                            float* __restrict__ diag) {
    int i = blockIdx.x * 128 + threadIdx.x;
    if (i >= NN) return;
    int lo = max(i - WW, 0), hi = min(i + WW, NN - 1);
    int cnt = hi - lo + 1;
    float m = 0.0f;
#pragma unroll
    for (int jo = 0; jo < BAND; jo++) {
        int j = i - WW + jo;
        if (j >= 0 && j < NN) m = fmaxf(m, band[i * BAND + jo]);
    }
    float em = expf(-m);
    float Z = (float)(NN - cnt) * em;
    float vals[BAND];
#pragma unroll
    for (int jo = 0; jo < BAND; jo++) {
        int j = i - WW + jo;
        float v = 0.f;
        if (j >= 0 && j < NN) {
            v = expf(band[i * BAND + jo] - m);
            Z += v;
        }
        vals[jo] = v;
    }
    float inv = 1.0f / Z;
#pragma unroll
    for (int jo = 0; jo < BAND; jo++) band[i * BAND + jo] = vals[jo] * inv;
    cvec[i] = em * inv;
    diag[i] = vals[WW] * inv;
}

// ---------------- chunked prefix scan along rows (per column) -----------
__global__ void scan_chunk(const float* __restrict__ M, float* __restrict__ chunk) {
    int d = blockIdx.y * 256 + threadIdx.x;
    int c = blockIdx.x;
    int base = c * 128;
    float s = 0.f;
#pragma unroll 4
    for (int r = 0; r < 128; r++) s += M[(size_t)(base + r) * DD + d];
    chunk[c * DD + d] = s;
}

__global__ void scan_offsets(float* __restrict__ chunk) {
    int d = blockIdx.x * 256 + threadIdx.x;
    float off = 0.f;
#pragma unroll
    for (int c = 0; c < 32; c++) {
        float t = chunk[c * DD + d];
        chunk[c * DD + d] = off;
        off += t;
    }
}

__global__ void scan_write(const float* __restrict__ M, const float* __restrict__ chunk,
                           float* __restrict__ P) {
    int d = blockIdx.y * 256 + threadIdx.x;
    int c = blockIdx.x;
    int base = c * 128;
    float acc = chunk[c * DD + d];
#pragma unroll 4
    for (int r = 0; r < 128; r++) {
        acc += M[(size_t)(base + r) * DD + d];
        P[(size_t)(base + r) * DD + d] = acc;
    }
}

__global__ void zero1(float* __restrict__ a, int n) {
    int i = blockIdx.x * 256 + threadIdx.x;
    if (i < n) a[i] = 0.f;
}

// per-speaker column sums of h
__global__ __launch_bounds__(256) void spk_sums1(const float* __restrict__ h,
                                                 const int* __restrict__ spk,
                                                 float* __restrict__ S) {
    __shared__ float s1[NSPK * 256];
    int tid = threadIdx.x;
    int d = blockIdx.y * 256 + tid;
#pragma unroll
    for (int k = 0; k < NSPK; k++) s1[k * 256 + tid] = 0.f;
    int base = blockIdx.x * 256;
    for (int r = 0; r < 256; r++) {
        int j = base + r;
        s1[spk[j] * 256 + tid] += h[(size_t)j * DD + d];
    }
#pragma unroll
    for (int k = 0; k < NSPK; k++) atomicAdd(&S[k * DD + d], s1[k * 256 + tid]);
}

// ---------------- build Y = [ypred | ysuc | ysame | ydiff | diag*h] -----
// writes tf32-rounded values so the GEMM can cp.async raw bytes
__global__ __launch_bounds__(256) void build_y(
    const float* __restrict__ h, const float* __restrict__ Pre,
    const float* __restrict__ S, const float* __restrict__ band,
    const float* __restrict__ cvec, const float* __restrict__ diag,
    const int* __restrict__ spk, float* __restrict__ Y) {
    __shared__ float hs[36][256];
    __shared__ float a_sh[16][21];
    __shared__ int sp_sh[36];
    __shared__ float c_sh[16], dg_sh[16];
    __shared__ int spi_sh[16];
    int tid = threadIdx.x;
    int i0 = blockIdx.x * 16;
    int d = blockIdx.y * 256 + tid;

#pragma unroll
    for (int r = 0; r < 36; r++) {
        int j = i0 - WW + r;
        hs[r][tid] = (j >= 0 && j < NN) ? h[(size_t)j * DD + d] : 0.f;
    }
    for (int idx = tid; idx < 16 * 21; idx += 256) {
        int il = idx / 21, jo = idx - il * 21;
        int i = i0 + il, j = i - WW + jo;
        a_sh[il][jo] = (j >= 0 && j < NN) ? band[i * BAND + jo] : 0.f;
    }
    if (tid < 36) {
        int j = i0 - WW + tid;
        sp_sh[tid] = (j >= 0 && j < NN) ? spk[j] : -1;
    }
    if (tid < 16) {
        c_sh[tid] = cvec[i0 + tid];
        dg_sh[tid] = diag[i0 + tid];
        spi_sh[tid] = spk[i0 + tid];
    }
    __syncthreads();

    float tot = Pre[(size_t)(NN - 1) * DD + d];
#pragma unroll 2
    for (int ti = 0; ti < 16; ti++) {
        int i = i0 + ti;
        float c = c_sh[ti];
        int spi = spi_sh[ti];
        float yp = 0.f, ys = 0.f, ysm = 0.f, ydf = 0.f;
#pragma unroll
        for (int jo = 0; jo < BAND; jo++) {
            float a = a_sh[ti][jo];
            float hv = hs[ti + jo][tid];
            if (jo >= WW) yp += a * hv; else ys += a * hv;
            float t = (a - c) * hv;
            if (sp_sh[ti + jo] == spi) ysm += t; else ydf += t;
        }
        int hi = min(i + WW, NN - 1);
        yp += c * (tot - Pre[(size_t)hi * DD + d]);
        if (i - WW - 1 >= 0) ys += c * Pre[(size_t)(i - WW - 1) * DD + d];
        float Ssp = S[spi * DD + d];
        ysm += c * Ssp;
        ydf += c * (tot - Ssp);
        size_t base = (size_t)i * (5 * DD) + d;
        Y[base] = f2tf32(yp);
        Y[base + DD] = f2tf32(ys);
        Y[base + 2 * DD] = f2tf32(ysm);
        Y[base + 3 * DD] = f2tf32(ydf);
        Y[base + 4 * DD] = f2tf32(dg_sh[ti] * hs[ti + WW][tid]);
    }
}

// ---------------- tf32 mma.sync GEMM, cp.async 4-stage pipeline ----------
// C[NN,DD] = sum_s Aseg[s][:,0:1024] @ Bseg[s]   (inputs pre-rounded to tf32)
struct GJob {
    const float* Aseg[5];
    const float* Bseg[5];
    const float* bias;  // nullptr = none
    float* C;
    int nseg;
    int lda;
    int relu;
    int round_out;  // store tf32-rounded output
};

#define S_A_FLOATS (128 * 20)
#define S_B_FLOATS (16 * 136)
#define STG_FLOATS (S_A_FLOATS + S_B_FLOATS)
#define STAGES 4
#define GEMM_SMEM (STAGES * STG_FLOATS * 4)

__global__ __launch_bounds__(256) void gemm_cp(GJob job) {
    extern __shared__ float smem[];
    const uint32_t sbase = smem_u32(smem);

    const int tid = threadIdx.x;
    const int row0 = blockIdx.y * 128;
    const int col0 = blockIdx.x * 128;
    const int KT = job.nseg * 64;
    const int lda = job.lda;

    const int wid = tid >> 5, lane = tid & 31;
    const int g = lane >> 2, t = lane & 3;
    const int wr = (wid & 1) * 64;
    const int wc = (wid >> 1) * 32;

    // per-thread copy indices (2 A chunks + 2 B chunks per stage)
    const int a_r0 = tid >> 2, a_c0 = (tid & 3) * 4;
    const int a_r1 = (tid + 256) >> 2, a_c1 = ((tid + 256) & 3) * 4;
    const int b_r0 = tid >> 5, b_c0 = (tid & 31) * 4;
    const int b_r1 = (tid + 256) >> 5, b_c1 = ((tid + 256) & 31) * 4;

    float acc[4][4][4];
#pragma unroll
    for (int m = 0; m < 4; m++)
#pragma unroll
        for (int n = 0; n < 4; n++)
#pragma unroll
            for (int q = 0; q < 4; q++) acc[m][n][q] = 0.f;

    // issue stage kt into buffer kt % STAGES
    auto issue = [&](int kt) {
        int seg = kt >> 6;
        int kb = (kt & 63) * 16;
        const float* A = job.Aseg[seg];
        const float* B = job.Bseg[seg];
        uint32_t st = sbase + (uint32_t)((kt & (STAGES - 1)) * STG_FLOATS * 4);
        uint32_t stB = st + S_A_FLOATS * 4;
        cp16(st + (uint32_t)(a_r0 * 20 + a_c0) * 4,
             &A[(size_t)(row0 + a_r0) * lda + kb + a_c0]);
        cp16(st + (uint32_t)(a_r1 * 20 + a_c1) * 4,
             &A[(size_t)(row0 + a_r1) * lda + kb + a_c1]);
        cp16(stB + (uint32_t)(b_r0 * 136 + b_c0) * 4,
             &B[(size_t)(kb + b_r0) * DD + col0 + b_c0]);
        cp16(stB + (uint32_t)(b_r1 * 136 + b_c1) * 4,
             &B[(size_t)(kb + b_r1) * DD + col0 + b_c1]);
    };

#pragma unroll
    for (int s = 0; s < STAGES - 1; s++) {
        issue(s);
        CP_COMMIT();
    }

    for (int kt = 0; kt < KT; kt++) {
        if (kt + STAGES - 1 < KT) issue(kt + STAGES - 1);
        CP_COMMIT();
        CP_WAIT2();
        __syncthreads();

        const float* st = smem + (kt & (STAGES - 1)) * STG_FLOATS;
        const float(*As)[20] = (const float(*)[20])st;
        const float(*Bs)[136] = (const float(*)[136])(st + S_A_FLOATS);

#pragma unroll
        for (int ks = 0; ks < 2; ks++) {
            const int k0 = ks * 8;
            uint32_t aF[4][4], bF[4][2];
#pragma unroll
            for (int m = 0; m < 4; m++) {
                int r = wr + m * 16 + g;
                aF[m][0] = __float_as_uint(As[r][k0 + t]);
                aF[m][1] = __float_as_uint(As[r + 8][k0 + t]);
                aF[m][2] = __float_as_uint(As[r][k0 + t + 4]);
                aF[m][3] = __float_as_uint(As[r + 8][k0 + t + 4]);
            }
#pragma unroll
            for (int n = 0; n < 4; n++) {
                int c = wc + n * 8 + g;
                bF[n][0] = __float_as_uint(Bs[k0 + t][c]);
                bF[n][1] = __float_as_uint(Bs[k0 + t + 4][c]);
            }
#pragma unroll
            for (int m = 0; m < 4; m++)
#pragma unroll
                for (int n = 0; n < 4; n++) mma8(acc[m][n], aF[m], bF[n]);
        }
        __syncthreads();
    }

    // epilogue: optional bias + relu (+ tf32 rounding of output)
#pragma unroll
    for (int m = 0; m < 4; m++) {
        int r = row0 + wr + m * 16 + g;
#pragma unroll
        for (int n = 0; n < 4; n++) {
            int c = col0 + wc + n * 8 + t * 2;
            float2 v0 = make_float2(acc[m][n][0], acc[m][n][1]);
            float2 v1 = make_float2(acc[m][n][2], acc[m][n][3]);
            if (job.bias) {
                float2 b2 = *(const float2*)&job.bias[c];
                v0.x += b2.x; v0.y += b2.y; v1.x += b2.x; v1.y += b2.y;
            }
            if (job.relu) {
                v0.x = fmaxf(v0.x, 0.f); v0.y = fmaxf(v0.y, 0.f);
                v1.x = fmaxf(v1.x, 0.f); v1.y = fmaxf(v1.y, 0.f);
            }
            if (job.round_out) {
                v0.x = f2tf32(v0.x); v0.y = f2tf32(v0.y);
                v1.x = f2tf32(v1.x); v1.y = f2tf32(v1.y);
            }
            *(float2*)&job.C[(size_t)r * DD + c] = v0;
            *(float2*)&job.C[(size_t)(r + 8) * DD + c] = v1;
        }
    }
}

// ---------------- heads --------------------------------------------------
__global__ void emotion_head(const float* __restrict__ T, const float* __restrict__ We2,
                             const float* __restrict__ be2, float* __restrict__ out) {
    int i = blockIdx.x;
    int w = threadIdx.x >> 5, lane = threadIdx.x & 31;
    float acc = 0.f;
    for (int k = lane; k < DD; k += 32) acc += T[(size_t)i * DD + k] * We2[k * 7 + w];
#pragma unroll
    for (int o = 16; o > 0; o >>= 1) acc += __shfl_down_sync(0xffffffffu, acc, o);
    if (lane == 0) out[i * 7 + w] = acc + be2[w];
}

__global__ void sentiment_head(const float* __restrict__ h2, const float* __restrict__ x,
                               const float* __restrict__ Wst, const float* __restrict__ bst,
                               float* __restrict__ out) {
    int i = blockIdx.x;
    int w = threadIdx.x >> 5, lane = threadIdx.x & 31;
    float acc = 0.f;
    for (int k = lane; k < DD; k += 32) acc += h2[(size_t)i * DD + k] * Wst[k * 3 + w];
    for (int k = lane; k < DD; k += 32) acc += x[(size_t)i * DD + k] * Wst[(DD + k) * 3 + w];
#pragma unroll
    for (int o = 16; o > 0; o >>= 1) acc += __shfl_down_sync(0xffffffffu, acc, o);
    if (lane == 0) out[i * 3 + w] = acc + bst[w];
}

// ---------------- launch --------------------------------------------------
extern "C" void kernel_launch(void* const* d_in, const int* in_sizes, int n_in,
                              void* d_out, int out_size) {
    const float* x = (const float*)d_in[0];
    const int* spk = (const int*)d_in[1];
    const float* Wl[2][5] = {
        {(const float*)d_in[2], (const float*)d_in[3], (const float*)d_in[4],
         (const float*)d_in[5], (const float*)d_in[10]},
        {(const float*)d_in[6], (const float*)d_in[7], (const float*)d_in[8],
         (const float*)d_in[9], (const float*)d_in[11]}};
    const float* We1 = (const float*)d_in[12];
    const float* be1 = (const float*)d_in[13];
    const float* We2 = (const float*)d_in[14];
    const float* be2 = (const float*)d_in[15];
    const float* Wst = (const float*)d_in[16];
    const float* bst = (const float*)d_in[17];
    float* out = (float*)d_out;

    float *band, *cvec, *diag, *Pre, *chunk, *S, *Y, *h1, *h2, *T, *Wr, *Xr;
    cudaGetSymbolAddress((void**)&band, g_band);
    cudaGetSymbolAddress((void**)&cvec, g_c);
    cudaGetSymbolAddress((void**)&diag, g_diag);
    cudaGetSymbolAddress((void**)&Pre, g_Pre);
    cudaGetSymbolAddress((void**)&chunk, g_chunk);
    cudaGetSymbolAddress((void**)&S, g_S);
    cudaGetSymbolAddress((void**)&Y, g_Y);
    cudaGetSymbolAddress((void**)&h1, g_h1);
    cudaGetSymbolAddress((void**)&h2, g_h2);
    cudaGetSymbolAddress((void**)&T, g_T);
    cudaGetSymbolAddress((void**)&Wr, g_Wr);
    cudaGetSymbolAddress((void**)&Xr, g_Xr);

    cudaFuncSetAttribute(gemm_cp, cudaFuncAttributeMaxDynamicSharedMemorySize,
                         GEMM_SMEM);

    // one-time per replay: round weights and x to tf32 (raw-copyable by cp.async)
    WPack wp;
    for (int s = 0; s < 5; s++) { wp.p[s] = Wl[0][s]; wp.p[5 + s] = Wl[1][s]; }
    wp.p[10] = We1;
    wp.p[11] = We1 + (size_t)DD * DD;
    round_w<<<dim3(DD * DD / 1024, 12), 256>>>(wp, Wr);
    round_x<<<NN * DD / 1024, 256>>>(x, Xr);

    att_logits<<<NN, 256>>>(x, band);
    att_softmax<<<NN / 128, 128>>>(band, cvec, diag);

    const float* hin = x;
    float* houts[2] = {h1, h2};
    dim3 ggemm(DD / 128, NN / 128);

    for (int L = 0; L < 2; L++) {
        scan_chunk<<<dim3(32, 4), 256>>>(hin, chunk);
        scan_offsets<<<4, 256>>>(chunk);
        scan_write<<<dim3(32, 4), 256>>>(hin, chunk, Pre);
        zero1<<<(NSPK * DD + 255) / 256, 256>>>(S, NSPK * DD);
        spk_sums1<<<dim3(16, 4), 256>>>(hin, spk, S);
        build_y<<<dim3(NN / 16, 4), 256>>>(hin, Pre, S, band, cvec, diag, spk, Y);

        GJob jb;
        for (int s = 0; s < 5; s++) {
            jb.Aseg[s] = Y + (size_t)s * DD;
            jb.Bseg[s] = Wr + (size_t)(L * 5 + s) * DD * DD;
        }
        jb.bias = nullptr;
        jb.C = houts[L];
        jb.nseg = 5;
        jb.lda = 5 * DD;
        jb.relu = 1;
        jb.round_out = 1;  // h is consumed as tf32 GEMM input next
        gemm_cp<<<ggemm, 256, GEMM_SMEM>>>(jb);
        hin = houts[L];
    }

    // heads: T = relu([h2|x] @ We1 + be1), one GEMM with fused bias+relu
    {
        GJob jb;
        jb.Aseg[0] = h2; jb.Aseg[1] = Xr;
        jb.Bseg[0] = Wr + (size_t)10 * DD * DD;
        jb.Bseg[1] = Wr + (size_t)11 * DD * DD;
        for (int s = 2; s < 5; s++) { jb.Aseg[s] = nullptr; jb.Bseg[s] = nullptr; }
        jb.bias = be1;
        jb.C = T;
        jb.nseg = 2;
        jb.lda = DD;
        jb.relu = 1;
        jb.round_out = 0;
        gemm_cp<<<ggemm, 256, GEMM_SMEM>>>(jb);
    }
    emotion_head<<<NN, 224>>>(T, We2, be2, out);
    sentiment_head<<<NN, 96>>>(h2, x, Wst, bst, out + NN * 7);
}

// round 8
// speedup vs baseline: 4.6875x; 1.6162x over previous
#include <cuda_runtime.h>
#include <cuda_fp16.h>
#include <math.h>
#include <stdint.h>

#define NN 4096
#define DD 1024
#define WW 10
#define BAND 21
#define NSPK 8

// ---------------- device scratch (static, no allocation) ----------------
__device__ float g_band[NN * BAND];
__device__ float g_c[NN];
__device__ float g_diag[NN];
__device__ float g_Pre[NN * DD];
__device__ float g_chunk[32 * DD];
__device__ float g_S[NSPK * DD];
__device__ __half g_Yh[NN * 5 * DD];
__device__ float g_h1[NN * DD];
__device__ float g_h2[NN * DD];
__device__ __half g_h2h[NN * DD];
__device__ float g_T[NN * DD];
__device__ __half g_Wh[12 * DD * DD];   // fp16 weights, transposed to [N,K]
__device__ __half g_Xh[NN * DD];        // fp16 x

// ---------------- helpers -------------------------------------------------
__device__ __forceinline__ uint32_t smem_u32(const void* p) {
    uint32_t a;
    asm("{ .reg .u64 t; cvta.to.shared.u64 t, %1; cvt.u32.u64 %0, t; }"
        : "=r"(a) : "l"(p));
    return a;
}

__device__ __forceinline__ void cp16(uint32_t dst, const void* src) {
    asm volatile("cp.async.cg.shared.global [%0], [%1], 16;"
                 :: "r"(dst), "l"(src) : "memory");
}
#define CP_COMMIT() asm volatile("cp.async.commit_group;" ::: "memory")
#define CP_WAIT2()  asm volatile("cp.async.wait_group 2;" ::: "memory")

__device__ __forceinline__ void mma16(float c[4], const uint32_t a[4],
                                      const uint32_t b[2]) {
    asm volatile(
        "mma.sync.aligned.m16n8k16.row.col.f32.f16.f16.f32 "
        "{%0,%1,%2,%3}, {%4,%5,%6,%7}, {%8,%9}, {%0,%1,%2,%3};"
        : "+f"(c[0]), "+f"(c[1]), "+f"(c[2]), "+f"(c[3])
        : "r"(a[0]), "r"(a[1]), "r"(a[2]), "r"(a[3]), "r"(b[0]), "r"(b[1]));
}

// ---------------- one-time conversion passes ------------------------------
struct WPack { const float* p[12]; };

// dst[z][n*DD + k] = (half) src[z][k*DD + n]
__global__ __launch_bounds__(256) void conv_w(WPack w, __half* __restrict__ dst) {
    __shared__ float t[32][33];
    int z = blockIdx.z;
    const float* src = w.p[z];
    __half* d = dst + (size_t)z * DD * DD;
    int bx = blockIdx.x * 32, by = blockIdx.y * 32;
    int tx = threadIdx.x & 31, ty = threadIdx.x >> 5;  // 32 x 8
#pragma unroll
    for (int j = 0; j < 32; j += 8)
        t[ty + j][tx] = src[(size_t)(by + ty + j) * DD + bx + tx];
    __syncthreads();
#pragma unroll
    for (int j = 0; j < 32; j += 8)
        d[(size_t)(bx + ty + j) * DD + by + tx] = __float2half_rn(t[tx][ty + j]);
}

__global__ __launch_bounds__(256) void conv_x(const float* __restrict__ x,
                                              __half* __restrict__ xh) {
    size_t i = ((size_t)blockIdx.x * 256 + threadIdx.x) * 4;
    float4 v = *(const float4*)&x[i];
    __half2 h0 = __floats2half2_rn(v.x, v.y);
    __half2 h1 = __floats2half2_rn(v.z, v.w);
    *(__half2*)&xh[i] = h0;
    *(__half2*)&xh[i + 2] = h1;
}

// ---------------- banded attention logits (tiled: 8 i-rows/block) -------
__global__ __launch_bounds__(256) void att_logits(const float* __restrict__ x,
                                                  float* __restrict__ band) {
    __shared__ float hs[28][256];
    int i0 = blockIdx.x * 8;
    int tid = threadIdx.x, w = tid >> 5, l = tid & 31;

    float acc[BAND];
#pragma unroll
    for (int jo = 0; jo < BAND; jo++) acc[jo] = 0.f;

    for (int ch = 0; ch < 4; ch++) {
        int d0 = ch * 256;
        __syncthreads();
#pragma unroll
        for (int r = 0; r < 28; r++) {
            int j = i0 - WW + r;
            hs[r][tid] = (j >= 0 && j < NN) ? x[(size_t)j * DD + d0 + tid] : 0.f;
        }
        __syncthreads();
#pragma unroll
        for (int e = 0; e < 8; e++) {
            int d = l + e * 32;
            float xv = hs[WW + w][d];
#pragma unroll
            for (int jo = 0; jo < BAND; jo++) acc[jo] += xv * hs[w + jo][d];
        }
    }
#pragma unroll
    for (int jo = 0; jo < BAND; jo++) {
        float v = acc[jo];
#pragma unroll
        for (int o = 16; o > 0; o >>= 1) v += __shfl_down_sync(0xffffffffu, v, o);
        if (l == 0) band[(i0 + w) * BAND + jo] = v;
    }
}

// softmax over full row: band logits + (N - band_count) exact zeros
__global__ void att_softmax(float* __restrict__ band, float* __restrict__ cvec,
                            float* __restrict__ diag) {
    int i = blockIdx.x * 128 + threadIdx.x;
    if (i >= NN) return;
    int lo = max(i - WW, 0), hi = min(i + WW, NN - 1);
    int cnt = hi - lo + 1;
    float m = 0.0f;
#pragma unroll
    for (int jo = 0; jo < BAND; jo++) {
        int j = i - WW + jo;
        if (j >= 0 && j < NN) m = fmaxf(m, band[i * BAND + jo]);
    }
    float em = expf(-m);
    float Z = (float)(NN - cnt) * em;
    float vals[BAND];
#pragma unroll
    for (int jo = 0; jo < BAND; jo++) {
        int j = i - WW + jo;
        float v = 0.f;
        if (j >= 0 && j < NN) {
            v = expf(band[i * BAND + jo] - m);
            Z += v;
        }
        vals[jo] = v;
    }
    float inv = 1.0f / Z;
#pragma unroll
    for (int jo = 0; jo < BAND; jo++) band[i * BAND + jo] = vals[jo] * inv;
    cvec[i] = em * inv;
    diag[i] = vals[WW] * inv;
}

// ---------------- chunked prefix scan along rows (per column) -----------
__global__ void scan_chunk(const float* __restrict__ M, float* __restrict__ chunk) {
    int d = blockIdx.y * 256 + threadIdx.x;
    int c = blockIdx.x;
    int base = c * 128;
    float s = 0.f;
#pragma unroll 4
    for (int r = 0; r < 128; r++) s += M[(size_t)(base + r) * DD + d];
    chunk[c * DD + d] = s;
}

__global__ void scan_offsets(float* __restrict__ chunk) {
    int d = blockIdx.x * 256 + threadIdx.x;
    float off = 0.f;
#pragma unroll
    for (int c = 0; c < 32; c++) {
        float t = chunk[c * DD + d];
        chunk[c * DD + d] = off;
        off += t;
    }
}

__global__ void scan_write(const float* __restrict__ M, const float* __restrict__ chunk,
                           float* __restrict__ P) {
    int d = blockIdx.y * 256 + threadIdx.x;
    int c = blockIdx.x;
    int base = c * 128;
    float acc = chunk[c * DD + d];
#pragma unroll 4
    for (int r = 0; r < 128; r++) {
        acc += M[(size_t)(base + r) * DD + d];
        P[(size_t)(base + r) * DD + d] = acc;
    }
}

__global__ void zero1(float* __restrict__ a, int n) {
    int i = blockIdx.x * 256 + threadIdx.x;
    if (i < n) a[i] = 0.f;
}

// per-speaker column sums of h
__global__ __launch_bounds__(256) void spk_sums1(const float* __restrict__ h,
                                                 const int* __restrict__ spk,
                                                 float* __restrict__ S) {
    __shared__ float s1[NSPK * 256];
    int tid = threadIdx.x;
    int d = blockIdx.y * 256 + tid;
#pragma unroll
    for (int k = 0; k < NSPK; k++) s1[k * 256 + tid] = 0.f;
    int base = blockIdx.x * 256;
    for (int r = 0; r < 256; r++) {
        int j = base + r;
        s1[spk[j] * 256 + tid] += h[(size_t)j * DD + d];
    }
#pragma unroll
    for (int k = 0; k < NSPK; k++) atomicAdd(&S[k * DD + d], s1[k * 256 + tid]);
}

// ---------------- build Y = [ypred | ysuc | ysame | ydiff | diag*h] -----
// writes fp16 so the GEMM can cp.async raw bytes
__global__ __launch_bounds__(256) void build_y(
    const float* __restrict__ h, const float* __restrict__ Pre,
    const float* __restrict__ S, const float* __restrict__ band,
    const float* __restrict__ cvec, const float* __restrict__ diag,
    const int* __restrict__ spk, __half* __restrict__ Y) {
    __shared__ float hs[36][256];
    __shared__ float a_sh[16][21];
    __shared__ int sp_sh[36];
    __shared__ float c_sh[16], dg_sh[16];
    __shared__ int spi_sh[16];
    int tid = threadIdx.x;
    int i0 = blockIdx.x * 16;
    int d = blockIdx.y * 256 + tid;

#pragma unroll
    for (int r = 0; r < 36; r++) {
        int j = i0 - WW + r;
        hs[r][tid] = (j >= 0 && j < NN) ? h[(size_t)j * DD + d] : 0.f;
    }
    for (int idx = tid; idx < 16 * 21; idx += 256) {
        int il = idx / 21, jo = idx - il * 21;
        int i = i0 + il, j = i - WW + jo;
        a_sh[il][jo] = (j >= 0 && j < NN) ? band[i * BAND + jo] : 0.f;
    }
    if (tid < 36) {
        int j = i0 - WW + tid;
        sp_sh[tid] = (j >= 0 && j < NN) ? spk[j] : -1;
    }
    if (tid < 16) {
        c_sh[tid] = cvec[i0 + tid];
        dg_sh[tid] = diag[i0 + tid];
        spi_sh[tid] = spk[i0 + tid];
    }
    __syncthreads();

    float tot = Pre[(size_t)(NN - 1) * DD + d];
#pragma unroll 2
    for (int ti = 0; ti < 16; ti++) {
        int i = i0 + ti;
        float c = c_sh[ti];
        int spi = spi_sh[ti];
        float yp = 0.f, ys = 0.f, ysm = 0.f, ydf = 0.f;
#pragma unroll
        for (int jo = 0; jo < BAND; jo++) {
            float a = a_sh[ti][jo];
            float hv = hs[ti + jo][tid];
            if (jo >= WW) yp += a * hv; else ys += a * hv;
            float t = (a - c) * hv;
            if (sp_sh[ti + jo] == spi) ysm += t; else ydf += t;
        }
        int hi = min(i + WW, NN - 1);
        yp += c * (tot - Pre[(size_t)hi * DD + d]);
        if (i - WW - 1 >= 0) ys += c * Pre[(size_t)(i - WW - 1) * DD + d];
        float Ssp = S[spi * DD + d];
        ysm += c * Ssp;
        ydf += c * (tot - Ssp);
        size_t base = (size_t)i * (5 * DD) + d;
        Y[base] = __float2half_rn(yp);
        Y[base + DD] = __float2half_rn(ys);
        Y[base + 2 * DD] = __float2half_rn(ysm);
        Y[base + 3 * DD] = __float2half_rn(ydf);
        Y[base + 4 * DD] = __float2half_rn(dg_sh[ti] * hs[ti + WW][tid]);
    }
}

// ---------------- fp16 mma.sync GEMM, cp.async 3-stage, BK=32 ------------
// C[NN,DD] = sum_s Aseg[s][:,0:1024] @ Bseg[s]^T   (Bseg = fp16 [N,K])
struct GJob {
    const __half* Aseg[5];
    const __half* Bseg[5];
    const float* bias;   // nullptr = none
    float* C;
    __half* C16;         // optional fp16 mirror of C
    int nseg;
    int lda;             // in halves
    int relu;
};

#define BKH 32
#define A_STRIDE 40                     // halves per smem row (pad 32->40)
#define S_A_HALFS (128 * A_STRIDE)      // 5120
#define STG_HALFS (2 * S_A_HALFS)       // 10240 (A then B)
#define STAGES 3
#define GEMM_SMEM (STAGES * STG_HALFS * 2)  // 61440 bytes

__global__ __launch_bounds__(256) void gemm_fp16(GJob job) {
    extern __shared__ __half smh[];
    const uint32_t sbase = smem_u32(smh);

    const int tid = threadIdx.x;
    const int row0 = blockIdx.y * 128;
    const int col0 = blockIdx.x * 128;
    const int KT = job.nseg * 32;
    const int lda = job.lda;

    const int wid = tid >> 5, lane = tid & 31;
    const int g = lane >> 2, t = lane & 3;
    const int wr = (wid & 1) * 64;
    const int wc = (wid >> 1) * 32;

    float acc[4][4][4];
#pragma unroll
    for (int m = 0; m < 4; m++)
#pragma unroll
        for (int n = 0; n < 4; n++)
#pragma unroll
            for (int q = 0; q < 4; q++) acc[m][n][q] = 0.f;

    auto issue = [&](int kt) {
        int seg = kt >> 5;
        int kb = (kt & 31) * BKH;
        const __half* A = job.Aseg[seg];
        const __half* B = job.Bseg[seg];
        uint32_t st = sbase + (uint32_t)((kt % STAGES) * STG_HALFS * 2);
        uint32_t stB = st + S_A_HALFS * 2;
#pragma unroll
        for (int l = 0; l < 2; l++) {
            int q = tid + l * 256;
            int r = q >> 2, c8 = (q & 3) * 8;
            cp16(st + (uint32_t)(r * A_STRIDE + c8) * 2,
                 &A[(size_t)(row0 + r) * lda + kb + c8]);
            cp16(stB + (uint32_t)(r * A_STRIDE + c8) * 2,
                 &B[(size_t)(col0 + r) * DD + kb + c8]);
        }
    };

    issue(0);
    CP_COMMIT();
    issue(1);
    CP_COMMIT();

    for (int kt = 0; kt < KT; kt++) {
        if (kt + 2 < KT) issue(kt + 2);
        CP_COMMIT();
        CP_WAIT2();
        __syncthreads();

        const __half* st = smh + (kt % STAGES) * STG_HALFS;
        const __half* Bt = st + S_A_HALFS;

#pragma unroll
        for (int ks = 0; ks < 2; ks++) {
            const int k0 = ks * 16;
            uint32_t aF[4][4], bF[4][2];
#pragma unroll
            for (int m = 0; m < 4; m++) {
                int r = wr + m * 16 + g;
                const __half* p0 = st + r * A_STRIDE + k0 + t * 2;
                const __half* p1 = st + (r + 8) * A_STRIDE + k0 + t * 2;
                aF[m][0] = *(const uint32_t*)p0;
                aF[m][1] = *(const uint32_t*)p1;
                aF[m][2] = *(const uint32_t*)(p0 + 8);
                aF[m][3] = *(const uint32_t*)(p1 + 8);
            }
#pragma unroll
            for (int n = 0; n < 4; n++) {
                int c = wc + n * 8 + g;
                const __half* pb = Bt + c * A_STRIDE + k0 + t * 2;
                bF[n][0] = *(const uint32_t*)pb;
                bF[n][1] = *(const uint32_t*)(pb + 8);
            }
#pragma unroll
            for (int m = 0; m < 4; m++)
#pragma unroll
                for (int n = 0; n < 4; n++) mma16(acc[m][n], aF[m], bF[n]);
        }
        __syncthreads();
    }

    // epilogue: optional bias + relu (+ fp16 mirror)
#pragma unroll
    for (int m = 0; m < 4; m++) {
        int r = row0 + wr + m * 16 + g;
#pragma unroll
        for (int n = 0; n < 4; n++) {
            int c = col0 + wc + n * 8 + t * 2;
            float2 v0 = make_float2(acc[m][n][0], acc[m][n][1]);
            float2 v1 = make_float2(acc[m][n][2], acc[m][n][3]);
            if (job.bias) {
                float2 b2 = *(const float2*)&job.bias[c];
                v0.x += b2.x; v0.y += b2.y; v1.x += b2.x; v1.y += b2.y;
            }
            if (job.relu) {
                v0.x = fmaxf(v0.x, 0.f); v0.y = fmaxf(v0.y, 0.f);
                v1.x = fmaxf(v1.x, 0.f); v1.y = fmaxf(v1.y, 0.f);
            }
            *(float2*)&job.C[(size_t)r * DD + c] = v0;
            *(float2*)&job.C[(size_t)(r + 8) * DD + c] = v1;
            if (job.C16) {
                *(__half2*)&job.C16[(size_t)r * DD + c] = __floats2half2_rn(v0.x, v0.y);
                *(__half2*)&job.C16[(size_t)(r + 8) * DD + c] = __floats2half2_rn(v1.x, v1.y);
            }
        }
    }
}

// ---------------- heads --------------------------------------------------
__global__ void emotion_head(const float* __restrict__ T, const float* __restrict__ We2,
                             const float* __restrict__ be2, float* __restrict__ out) {
    int i = blockIdx.x;
    int w = threadIdx.x >> 5, lane = threadIdx.x & 31;
    float acc = 0.f;
    for (int k = lane; k < DD; k += 32) acc += T[(size_t)i * DD + k] * We2[k * 7 + w];
#pragma unroll
    for (int o = 16; o > 0; o >>= 1) acc += __shfl_down_sync(0xffffffffu, acc, o);
    if (lane == 0) out[i * 7 + w] = acc + be2[w];
}

__global__ void sentiment_head(const float* __restrict__ h2, const float* __restrict__ x,
                               const float* __restrict__ Wst, const float* __restrict__ bst,
                               float* __restrict__ out) {
    int i = blockIdx.x;
    int w = threadIdx.x >> 5, lane = threadIdx.x & 31;
    float acc = 0.f;
    for (int k = lane; k < DD; k += 32) acc += h2[(size_t)i * DD + k] * Wst[k * 3 + w];
    for (int k = lane; k < DD; k += 32) acc += x[(size_t)i * DD + k] * Wst[(DD + k) * 3 + w];
#pragma unroll
    for (int o = 16; o > 0; o >>= 1) acc += __shfl_down_sync(0xffffffffu, acc, o);
    if (lane == 0) out[i * 3 + w] = acc + bst[w];
}

// ---------------- launch --------------------------------------------------
extern "C" void kernel_launch(void* const* d_in, const int* in_sizes, int n_in,
                              void* d_out, int out_size) {
    const float* x = (const float*)d_in[0];
    const int* spk = (const int*)d_in[1];
    const float* Wl[2][5] = {
        {(const float*)d_in[2], (const float*)d_in[3], (const float*)d_in[4],
         (const float*)d_in[5], (const float*)d_in[10]},
        {(const float*)d_in[6], (const float*)d_in[7], (const float*)d_in[8],
         (const float*)d_in[9], (const float*)d_in[11]}};
    const float* We1 = (const float*)d_in[12];
    const float* be1 = (const float*)d_in[13];
    const float* We2 = (const float*)d_in[14];
    const float* be2 = (const float*)d_in[15];
    const float* Wst = (const float*)d_in[16];
    const float* bst = (const float*)d_in[17];
    float* out = (float*)d_out;

    float *band, *cvec, *diag, *Pre, *chunk, *S, *h1, *h2, *T;
    __half *Yh, *Wh, *Xh, *h2h;
    cudaGetSymbolAddress((void**)&band, g_band);
    cudaGetSymbolAddress((void**)&cvec, g_c);
    cudaGetSymbolAddress((void**)&diag, g_diag);
    cudaGetSymbolAddress((void**)&Pre, g_Pre);
    cudaGetSymbolAddress((void**)&chunk, g_chunk);
    cudaGetSymbolAddress((void**)&S, g_S);
    cudaGetSymbolAddress((void**)&h1, g_h1);
    cudaGetSymbolAddress((void**)&h2, g_h2);
    cudaGetSymbolAddress((void**)&T, g_T);
    cudaGetSymbolAddress((void**)&Yh, g_Yh);
    cudaGetSymbolAddress((void**)&Wh, g_Wh);
    cudaGetSymbolAddress((void**)&Xh, g_Xh);
    cudaGetSymbolAddress((void**)&h2h, g_h2h);

    cudaFuncSetAttribute(gemm_fp16, cudaFuncAttributeMaxDynamicSharedMemorySize,
                         GEMM_SMEM);

    // one-time per replay: weights -> fp16 [N,K]; x -> fp16
    WPack wp;
    for (int s = 0; s < 5; s++) { wp.p[s] = Wl[0][s]; wp.p[5 + s] = Wl[1][s]; }
    wp.p[10] = We1;
    wp.p[11] = We1 + (size_t)DD * DD;
    conv_w<<<dim3(32, 32, 12), 256>>>(wp, Wh);
    conv_x<<<NN * DD / 1024, 256>>>(x, Xh);

    att_logits<<<NN / 8, 256>>>(x, band);
    att_softmax<<<NN / 128, 128>>>(band, cvec, diag);

    const float* hin = x;
    float* houts[2] = {h1, h2};
    dim3 ggemm(DD / 128, NN / 128);

    for (int L = 0; L < 2; L++) {
        scan_chunk<<<dim3(32, 4), 256>>>(hin, chunk);
        scan_offsets<<<4, 256>>>(chunk);
        scan_write<<<dim3(32, 4), 256>>>(hin, chunk, Pre);
        zero1<<<(NSPK * DD + 255) / 256, 256>>>(S, NSPK * DD);
        spk_sums1<<<dim3(16, 4), 256>>>(hin, spk, S);
        build_y<<<dim3(NN / 16, 4), 256>>>(hin, Pre, S, band, cvec, diag, spk, Yh);

        GJob jb;
        for (int s = 0; s < 5; s++) {
            jb.Aseg[s] = Yh + (size_t)s * DD;
            jb.Bseg[s] = Wh + (size_t)(L * 5 + s) * DD * DD;
        }
        jb.bias = nullptr;
        jb.C = houts[L];
        jb.C16 = (L == 1) ? h2h : nullptr;  // head GEMM consumes fp16 h2
        jb.nseg = 5;
        jb.lda = 5 * DD;
        jb.relu = 1;
        gemm_fp16<<<ggemm, 256, GEMM_SMEM>>>(jb);
        hin = houts[L];
    }

    // heads: T = relu([h2|x] @ We1 + be1), one GEMM with fused bias+relu
    {
        GJob jb;
        jb.Aseg[0] = h2h; jb.Aseg[1] = Xh;
        jb.Bseg[0] = Wh + (size_t)10 * DD * DD;
        jb.Bseg[1] = Wh + (size_t)11 * DD * DD;
        for (int s = 2; s < 5; s++) { jb.Aseg[s] = nullptr; jb.Bseg[s] = nullptr; }
        jb.bias = be1;
        jb.C = T;
        jb.C16 = nullptr;
        jb.nseg = 2;
        jb.lda = DD;
        jb.relu = 1;
        gemm_fp16<<<ggemm, 256, GEMM_SMEM>>>(jb);
    }
    emotion_head<<<NN, 224>>>(T, We2, be2, out);
    sentiment_head<<<NN, 96>>>(h2, x, Wst, bst, out + NN * 7);
}

// round 9
// speedup vs baseline: 5.9365x; 1.2665x over previous
#include <cuda_runtime.h>
#include <cuda_fp16.h>
#include <math.h>
#include <stdint.h>

#define NN 4096
#define DD 1024
#define WW 10
#define BAND 21
#define NSPK 8

// ---------------- device scratch (static, no allocation) ----------------
__device__ float g_band[NN * BAND];
__device__ float g_c[NN];
__device__ float g_diag[NN];
__device__ float g_Pre[NN * DD];
__device__ float g_chunk[128 * DD];
__device__ float g_S[NSPK * DD];
__device__ __half g_Yh[NN * 4 * DD];
__device__ float g_h1[NN * DD];
__device__ float g_h2[NN * DD];
__device__ __half g_h2h[NN * DD];
__device__ __half g_Wh[10 * DD * DD];   // fp16 combined weights, [N,K]
__device__ __half g_Xh[NN * DD];        // fp16 x

// ---------------- helpers -------------------------------------------------
__device__ __forceinline__ uint32_t smem_u32(const void* p) {
    uint32_t a;
    asm("{ .reg .u64 t; cvta.to.shared.u64 t, %1; cvt.u32.u64 %0, t; }"
        : "=r"(a) : "l"(p));
    return a;
}

__device__ __forceinline__ void cp16(uint32_t dst, const void* src) {
    asm volatile("cp.async.cg.shared.global [%0], [%1], 16;"
                 :: "r"(dst), "l"(src) : "memory");
}
#define CP_COMMIT() asm volatile("cp.async.commit_group;" ::: "memory")
#define CP_WAIT2()  asm volatile("cp.async.wait_group 2;" ::: "memory")
#define CP_WAIT0()  asm volatile("cp.async.wait_group 0;" ::: "memory")

__device__ __forceinline__ void mma16(float c[4], const uint32_t a[4],
                                      const uint32_t b[2]) {
    asm volatile(
        "mma.sync.aligned.m16n8k16.row.col.f32.f16.f16.f32 "
        "{%0,%1,%2,%3}, {%4,%5,%6,%7}, {%8,%9}, {%0,%1,%2,%3};"
        : "+f"(c[0]), "+f"(c[1]), "+f"(c[2]), "+f"(c[3])
        : "r"(a[0]), "r"(a[1]), "r"(a[2]), "r"(a[3]), "r"(b[0]), "r"(b[1]));
}

// ---------------- one-time conversion: combined fp16 [N,K] weights ------
struct WCPack {
    const float* a[10];
    const float* b[10];
    float s[10];
};

// dst[z][n*DD + k] = (half)( a[z][k*DD + n] + s[z]*b[z][k*DD + n] )
__global__ __launch_bounds__(256) void conv_wc(WCPack p, __half* __restrict__ dst) {
    __shared__ float t[32][33];
    int z = blockIdx.z;
    const float* A = p.a[z];
    const float* B = p.b[z];
    float sg = p.s[z];
    __half* d = dst + (size_t)z * DD * DD;
    int bx = blockIdx.x * 32, by = blockIdx.y * 32;
    int tx = threadIdx.x & 31, ty = threadIdx.x >> 5;  // 32 x 8
#pragma unroll
    for (int j = 0; j < 32; j += 8) {
        size_t off = (size_t)(by + ty + j) * DD + bx + tx;
        t[ty + j][tx] = A[off] + sg * B[off];
    }
    __syncthreads();
#pragma unroll
    for (int j = 0; j < 32; j += 8)
        d[(size_t)(bx + ty + j) * DD + by + tx] = __float2half_rn(t[tx][ty + j]);
}

__global__ __launch_bounds__(256) void conv_x(const float* __restrict__ x,
                                              __half* __restrict__ xh) {
    size_t i = ((size_t)blockIdx.x * 256 + threadIdx.x) * 4;
    float4 v = *(const float4*)&x[i];
    *(__half2*)&xh[i] = __floats2half2_rn(v.x, v.y);
    *(__half2*)&xh[i + 2] = __floats2half2_rn(v.z, v.w);
}

// ---------------- fused banded logits + softmax (16 i-rows/block) -------
__global__ __launch_bounds__(512) void att_full(const float* __restrict__ x,
                                                float* __restrict__ band,
                                                float* __restrict__ cvec,
                                                float* __restrict__ diag) {
    __shared__ float hs[36][256];
    int i0 = blockIdx.x * 16;
    int tid = threadIdx.x, w = tid >> 5, l = tid & 31;

    float acc[BAND];
#pragma unroll
    for (int jo = 0; jo < BAND; jo++) acc[jo] = 0.f;

    for (int ch = 0; ch < 4; ch++) {
        __syncthreads();
        for (int idx = tid; idx < 36 * 256; idx += 512) {
            int r = idx >> 8, c = idx & 255;
            int j = i0 - WW + r;
            hs[r][c] = (j >= 0 && j < NN) ? x[(size_t)j * DD + ch * 256 + c] : 0.f;
        }
        __syncthreads();
#pragma unroll
        for (int e = 0; e < 8; e++) {
            int d = l + e * 32;
            float xv = hs[WW + w][d];
#pragma unroll
            for (int jo = 0; jo < BAND; jo++) acc[jo] += xv * hs[w + jo][d];
        }
    }
#pragma unroll
    for (int jo = 0; jo < BAND; jo++) {
        float v = acc[jo];
#pragma unroll
        for (int o = 16; o > 0; o >>= 1) v += __shfl_down_sync(0xffffffffu, v, o);
        acc[jo] = v;
    }
    if (l == 0) {
        int i = i0 + w;
        int lo = max(i - WW, 0), hi = min(i + WW, NN - 1);
        int cnt = hi - lo + 1;
        float m = 0.0f;  // zeros always in row
#pragma unroll
        for (int jo = 0; jo < BAND; jo++) {
            int j = i - WW + jo;
            if (j >= 0 && j < NN) m = fmaxf(m, acc[jo]);
        }
        float em = expf(-m);
        float Z = (float)(NN - cnt) * em;
        float vals[BAND];
#pragma unroll
        for (int jo = 0; jo < BAND; jo++) {
            int j = i - WW + jo;
            float v = 0.f;
            if (j >= 0 && j < NN) {
                v = expf(acc[jo] - m);
                Z += v;
            }
            vals[jo] = v;
        }
        float inv = 1.0f / Z;
#pragma unroll
        for (int jo = 0; jo < BAND; jo++) band[i * BAND + jo] = vals[jo] * inv;
        cvec[i] = em * inv;
        diag[i] = vals[WW] * inv;
    }
}

// ---------------- scan pass 1: chunk sums + per-speaker sums -------------
__global__ __launch_bounds__(256) void scan1(const float* __restrict__ h,
                                             const int* __restrict__ spk,
                                             float* __restrict__ chunk,
                                             float* __restrict__ S) {
    __shared__ int sp_sh[32];
    int tid = threadIdx.x;
    int d = blockIdx.y * 256 + tid;
    int base = blockIdx.x * 32;
    if (tid < 32) sp_sh[tid] = spk[base + tid];
    __syncthreads();
    float s = 0.f, sreg[NSPK];
#pragma unroll
    for (int k = 0; k < NSPK; k++) sreg[k] = 0.f;
#pragma unroll 8
    for (int r = 0; r < 32; r++) {
        float v = h[(size_t)(base + r) * DD + d];
        s += v;
        int sp = sp_sh[r];
#pragma unroll
        for (int k = 0; k < NSPK; k++)
            if (sp == k) sreg[k] += v;
    }
    chunk[blockIdx.x * DD + d] = s;
#pragma unroll
    for (int k = 0; k < NSPK; k++) atomicAdd(&S[k * DD + d], sreg[k]);
}

// ---------------- scan pass 2: prefix write (offset from chunk sums) ----
__global__ __launch_bounds__(256) void scan2(const float* __restrict__ h,
                                             const float* __restrict__ chunk,
                                             float* __restrict__ P) {
    int tid = threadIdx.x;
    int d = blockIdx.y * 256 + tid;
    int bx = blockIdx.x;
    int base = bx * 32;
    float off = 0.f;
#pragma unroll 4
    for (int c = 0; c < bx; c++) off += chunk[c * DD + d];
    float acc = off;
#pragma unroll 8
    for (int r = 0; r < 32; r++) {
        acc += h[(size_t)(base + r) * DD + d];
        P[(size_t)(base + r) * DD + d] = acc;
    }
}

__global__ void zero1(float* __restrict__ a, int n) {
    int i = blockIdx.x * 256 + threadIdx.x;
    if (i < n) a[i] = 0.f;
}

// ---------------- build Y = [ypred | ysuc | ysame | diag*h] (fp16) ------
// (ydiff folded into weights: ydf = yp + ys - ysm)
__global__ __launch_bounds__(256) void build_y(
    const float* __restrict__ h, const float* __restrict__ Pre,
    const float* __restrict__ S, const float* __restrict__ band,
    const float* __restrict__ cvec, const float* __restrict__ diag,
    const int* __restrict__ spk, __half* __restrict__ Y) {
    __shared__ float hs[36][256];
    __shared__ float a_sh[16][21];
    __shared__ int sp_sh[36];
    __shared__ float c_sh[16], dg_sh[16];
    __shared__ int spi_sh[16];
    int tid = threadIdx.x;
    int i0 = blockIdx.x * 16;
    int d = blockIdx.y * 256 + tid;

#pragma unroll
    for (int r = 0; r < 36; r++) {
        int j = i0 - WW + r;
        hs[r][tid] = (j >= 0 && j < NN) ? h[(size_t)j * DD + d] : 0.f;
    }
    for (int idx = tid; idx < 16 * 21; idx += 256) {
        int il = idx / 21, jo = idx - il * 21;
        int i = i0 + il, j = i - WW + jo;
        a_sh[il][jo] = (j >= 0 && j < NN) ? band[i * BAND + jo] : 0.f;
    }
    if (tid < 36) {
        int j = i0 - WW + tid;
        sp_sh[tid] = (j >= 0 && j < NN) ? spk[j] : -1;
    }
    if (tid < 16) {
        c_sh[tid] = cvec[i0 + tid];
        dg_sh[tid] = diag[i0 + tid];
        spi_sh[tid] = spk[i0 + tid];
    }
    __syncthreads();

    float tot = Pre[(size_t)(NN - 1) * DD + d];
#pragma unroll 2
    for (int ti = 0; ti < 16; ti++) {
        int i = i0 + ti;
        float c = c_sh[ti];
        int spi = spi_sh[ti];
        float yp = 0.f, ys = 0.f, ysm = 0.f;
#pragma unroll
        for (int jo = 0; jo < BAND; jo++) {
            float a = a_sh[ti][jo];
            float hv = hs[ti + jo][tid];
            if (jo >= WW) yp += a * hv; else ys += a * hv;
            if (sp_sh[ti + jo] == spi) ysm += (a - c) * hv;
        }
        int hi = min(i + WW, NN - 1);
        yp += c * (tot - Pre[(size_t)hi * DD + d]);
        if (i - WW - 1 >= 0) ys += c * Pre[(size_t)(i - WW - 1) * DD + d];
        ysm += c * S[spi * DD + d];
        size_t base = (size_t)i * (4 * DD) + d;
        Y[base] = __float2half_rn(yp);
        Y[base + DD] = __float2half_rn(ys);
        Y[base + 2 * DD] = __float2half_rn(ysm);
        Y[base + 3 * DD] = __float2half_rn(dg_sh[ti] * hs[ti + WW][tid]);
    }
}

// ---------------- fp16 mma.sync GEMM, cp.async 3-stage, BK=32 ------------
// C[NN,DD] = sum_s Aseg[s][:,0:1024] @ Bseg[s]^T   (Bseg = fp16 [N,K])
// optional fused epilogues: bias+relu, fp16 mirror, emotion-head reduce
struct GJob {
    const __half* Aseg[4];
    const __half* Bseg[4];
    const float* bias;   // nullptr = none
    float* C;            // nullptr = no fp32 store
    __half* C16;         // nullptr = no fp16 mirror
    const float* We2;    // emotion weights [DD,7] (emo mode)
    float* outEmo;       // emotion output [NN,7] (emo mode, atomicAdd)
    int nseg;
    int lda;             // in halves
    int relu;
    int emo;
};

#define BKH 32
#define A_STRIDE 40
#define S_A_HALFS (128 * A_STRIDE)          // 5120
#define STG_HALFS (2 * S_A_HALFS)           // 10240
#define STAGES 3
#define TILE_LD 132
#define GEMM_SMEM ((128 * TILE_LD + 128 * 7) * 4)  // 71168 (>= pipeline 61440)

__global__ __launch_bounds__(256) void gemm_fp16(GJob job) {
    extern __shared__ __half smh[];
    const uint32_t sbase = smem_u32(smh);

    const int tid = threadIdx.x;
    const int row0 = blockIdx.y * 128;
    const int col0 = blockIdx.x * 128;
    const int KT = job.nseg * 32;
    const int lda = job.lda;

    const int wid = tid >> 5, lane = tid & 31;
    const int g = lane >> 2, t = lane & 3;
    const int wr = (wid & 1) * 64;
    const int wc = (wid >> 1) * 32;

    float acc[4][4][4];
#pragma unroll
    for (int m = 0; m < 4; m++)
#pragma unroll
        for (int n = 0; n < 4; n++)
#pragma unroll
            for (int q = 0; q < 4; q++) acc[m][n][q] = 0.f;

    auto issue = [&](int kt) {
        int seg = kt >> 5;
        int kb = (kt & 31) * BKH;
        const __half* A = job.Aseg[seg];
        const __half* B = job.Bseg[seg];
        uint32_t st = sbase + (uint32_t)((kt % STAGES) * STG_HALFS * 2);
        uint32_t stB = st + S_A_HALFS * 2;
#pragma unroll
        for (int l = 0; l < 2; l++) {
            int q = tid + l * 256;
            int r = q >> 2, c8 = (q & 3) * 8;
            cp16(st + (uint32_t)(r * A_STRIDE + c8) * 2,
                 &A[(size_t)(row0 + r) * lda + kb + c8]);
            cp16(stB + (uint32_t)(r * A_STRIDE + c8) * 2,
                 &B[(size_t)(col0 + r) * DD + kb + c8]);
        }
    };

    issue(0);
    CP_COMMIT();
    issue(1);
    CP_COMMIT();

    for (int kt = 0; kt < KT; kt++) {
        if (kt + 2 < KT) issue(kt + 2);
        CP_COMMIT();
        CP_WAIT2();
        __syncthreads();

        const __half* st = smh + (kt % STAGES) * STG_HALFS;
        const __half* Bt = st + S_A_HALFS;

#pragma unroll
        for (int ks = 0; ks < 2; ks++) {
            const int k0 = ks * 16;
            uint32_t aF[4][4], bF[4][2];
#pragma unroll
            for (int m = 0; m < 4; m++) {
                int r = wr + m * 16 + g;
                const __half* p0 = st + r * A_STRIDE + k0 + t * 2;
                const __half* p1 = st + (r + 8) * A_STRIDE + k0 + t * 2;
                aF[m][0] = *(const uint32_t*)p0;
                aF[m][1] = *(const uint32_t*)p1;
                aF[m][2] = *(const uint32_t*)(p0 + 8);
                aF[m][3] = *(const uint32_t*)(p1 + 8);
            }
#pragma unroll
            for (int n = 0; n < 4; n++) {
                int c = wc + n * 8 + g;
                const __half* pb = Bt + c * A_STRIDE + k0 + t * 2;
                bF[n][0] = *(const uint32_t*)pb;
                bF[n][1] = *(const uint32_t*)(pb + 8);
            }
#pragma unroll
            for (int m = 0; m < 4; m++)
#pragma unroll
                for (int n = 0; n < 4; n++) mma16(acc[m][n], aF[m], bF[n]);
        }
        __syncthreads();
    }

    // ---- epilogue ----
    float* tile = (float*)smh;
    float* we2s = tile + 128 * TILE_LD;
    if (job.emo) {
        CP_WAIT0();
        __syncthreads();
    }

#pragma unroll
    for (int m = 0; m < 4; m++) {
        int rl = wr + m * 16 + g;
        int r = row0 + rl;
#pragma unroll
        for (int n = 0; n < 4; n++) {
            int cl = wc + n * 8 + t * 2;
            int c = col0 + cl;
            float2 v0 = make_float2(acc[m][n][0], acc[m][n][1]);
            float2 v1 = make_float2(acc[m][n][2], acc[m][n][3]);
            if (job.bias) {
                float2 b2 = *(const float2*)&job.bias[c];
                v0.x += b2.x; v0.y += b2.y; v1.x += b2.x; v1.y += b2.y;
            }
            if (job.relu) {
                v0.x = fmaxf(v0.x, 0.f); v0.y = fmaxf(v0.y, 0.f);
                v1.x = fmaxf(v1.x, 0.f); v1.y = fmaxf(v1.y, 0.f);
            }
            if (job.C) {
                *(float2*)&job.C[(size_t)r * DD + c] = v0;
                *(float2*)&job.C[(size_t)(r + 8) * DD + c] = v1;
            }
            if (job.C16) {
                *(__half2*)&job.C16[(size_t)r * DD + c] = __floats2half2_rn(v0.x, v0.y);
                *(__half2*)&job.C16[(size_t)(r + 8) * DD + c] = __floats2half2_rn(v1.x, v1.y);
            }
            if (job.emo) {
                tile[rl * TILE_LD + cl] = v0.x;
                tile[rl * TILE_LD + cl + 1] = v0.y;
                tile[(rl + 8) * TILE_LD + cl] = v1.x;
                tile[(rl + 8) * TILE_LD + cl + 1] = v1.y;
            }
        }
    }

    if (job.emo) {
        for (int idx = tid; idx < 128 * 7; idx += 256)
            we2s[idx] = job.We2[(size_t)(col0 + idx / 7) * 7 + (idx % 7)];
        __syncthreads();
        int row = tid >> 1, half = tid & 1;
        float e[7];
#pragma unroll
        for (int w = 0; w < 7; w++) e[w] = 0.f;
        const float* trow = tile + row * TILE_LD + half * 64;
        const float* wbase = we2s + half * 64 * 7;
#pragma unroll 4
        for (int c = 0; c < 64; c++) {
            float tv = trow[c];
            const float* wp = wbase + c * 7;
#pragma unroll
            for (int w = 0; w < 7; w++) e[w] += tv * wp[w];
        }
#pragma unroll
        for (int w = 0; w < 7; w++) e[w] += __shfl_xor_sync(0xffffffffu, e[w], 1);
        if (half == 0) {
#pragma unroll
            for (int w = 0; w < 7; w++)
                atomicAdd(&job.outEmo[(size_t)(row0 + row) * 7 + w], e[w]);
        }
    }
}

// ---------------- output init + sentiment head ---------------------------
__global__ void init_emo(float* __restrict__ out, const float* __restrict__ be2) {
    int idx = blockIdx.x * 256 + threadIdx.x;
    if (idx < NN * 7) out[idx] = be2[idx % 7];
}

__global__ void sentiment_head(const float* __restrict__ h2, const float* __restrict__ x,
                               const float* __restrict__ Wst, const float* __restrict__ bst,
                               float* __restrict__ out) {
    int i = blockIdx.x;
    int w = threadIdx.x >> 5, lane = threadIdx.x & 31;
    float acc = 0.f;
    for (int k = lane; k < DD; k += 32) acc += h2[(size_t)i * DD + k] * Wst[k * 3 + w];
    for (int k = lane; k < DD; k += 32) acc += x[(size_t)i * DD + k] * Wst[(DD + k) * 3 + w];
#pragma unroll
    for (int o = 16; o > 0; o >>= 1) acc += __shfl_down_sync(0xffffffffu, acc, o);
    if (lane == 0) out[i * 3 + w] = acc + bst[w];
}

// ---------------- launch --------------------------------------------------
extern "C" void kernel_launch(void* const* d_in, const int* in_sizes, int n_in,
                              void* d_out, int out_size) {
    const float* x = (const float*)d_in[0];
    const int* spk = (const int*)d_in[1];
    const float* Wp1 = (const float*)d_in[2];
    const float* Ws1 = (const float*)d_in[3];
    const float* Wsm1 = (const float*)d_in[4];
    const float* Wdf1 = (const float*)d_in[5];
    const float* Wp2 = (const float*)d_in[6];
    const float* Ws2 = (const float*)d_in[7];
    const float* Wsm2 = (const float*)d_in[8];
    const float* Wdf2 = (const float*)d_in[9];
    const float* Wa1 = (const float*)d_in[10];
    const float* Wa2 = (const float*)d_in[11];
    const float* We1 = (const float*)d_in[12];
    const float* be1 = (const float*)d_in[13];
    const float* We2 = (const float*)d_in[14];
    const float* be2 = (const float*)d_in[15];
    const float* Wst = (const float*)d_in[16];
    const float* bst = (const float*)d_in[17];
    float* out = (float*)d_out;

    float *band, *cvec, *diag, *Pre, *chunk, *S, *h1, *h2;
    __half *Yh, *Wh, *Xh, *h2h;
    cudaGetSymbolAddress((void**)&band, g_band);
    cudaGetSymbolAddress((void**)&cvec, g_c);
    cudaGetSymbolAddress((void**)&diag, g_diag);
    cudaGetSymbolAddress((void**)&Pre, g_Pre);
    cudaGetSymbolAddress((void**)&chunk, g_chunk);
    cudaGetSymbolAddress((void**)&S, g_S);
    cudaGetSymbolAddress((void**)&h1, g_h1);
    cudaGetSymbolAddress((void**)&h2, g_h2);
    cudaGetSymbolAddress((void**)&Yh, g_Yh);
    cudaGetSymbolAddress((void**)&Wh, g_Wh);
    cudaGetSymbolAddress((void**)&Xh, g_Xh);
    cudaGetSymbolAddress((void**)&h2h, g_h2h);

    cudaFuncSetAttribute(gemm_fp16, cudaFuncAttributeMaxDynamicSharedMemorySize,
                         GEMM_SMEM);

    // combined fp16 weight panels, transposed to [N,K]:
    // 0..3: L1 {Wp+Wdf, Ws+Wdf, Wsm-Wdf, Wa}; 4..7: L2 same; 8,9: We1 halves
    WCPack wp;
    const float* As[10] = {Wp1, Ws1, Wsm1, Wa1, Wp2, Ws2, Wsm2, Wa2,
                           We1, We1 + (size_t)DD * DD};
    const float* Bs[10] = {Wdf1, Wdf1, Wdf1, Wa1, Wdf2, Wdf2, Wdf2, Wa2,
                           We1, We1};
    float Sg[10] = {1.f, 1.f, -1.f, 0.f, 1.f, 1.f, -1.f, 0.f, 0.f, 0.f};
    for (int i = 0; i < 10; i++) { wp.a[i] = As[i]; wp.b[i] = Bs[i]; wp.s[i] = Sg[i]; }
    conv_wc<<<dim3(32, 32, 10), 256>>>(wp, Wh);
    conv_x<<<NN * DD / 1024, 256>>>(x, Xh);

    att_full<<<NN / 16, 512>>>(x, band, cvec, diag);

    const float* hin = x;
    float* houts[2] = {h1, h2};
    dim3 ggemm(DD / 128, NN / 128);

    for (int L = 0; L < 2; L++) {
        zero1<<<(NSPK * DD + 255) / 256, 256>>>(S, NSPK * DD);
        scan1<<<dim3(128, 4), 256>>>(hin, spk, chunk, S);
        scan2<<<dim3(128, 4), 256>>>(hin, chunk, Pre);
        build_y<<<dim3(NN / 16, 4), 256>>>(hin, Pre, S, band, cvec, diag, spk, Yh);

        GJob jb;
        for (int s = 0; s < 4; s++) {
            jb.Aseg[s] = Yh + (size_t)s * DD;
            jb.Bseg[s] = Wh + (size_t)(L * 4 + s) * DD * DD;
        }
        jb.bias = nullptr;
        jb.C = houts[L];
        jb.C16 = (L == 1) ? h2h : nullptr;
        jb.We2 = nullptr;
        jb.outEmo = nullptr;
        jb.nseg = 4;
        jb.lda = 4 * DD;
        jb.relu = 1;
        jb.emo = 0;
        gemm_fp16<<<ggemm, 256, GEMM_SMEM>>>(jb);
        hin = houts[L];
    }

    // emotion: out[:, :7] = relu([h2|x]@We1 + be1) @ We2 + be2 (fused in GEMM)
    init_emo<<<(NN * 7 + 255) / 256, 256>>>(out, be2);
    {
        GJob jb;
        jb.Aseg[0] = h2h; jb.Aseg[1] = Xh;
        jb.Aseg[2] = nullptr; jb.Aseg[3] = nullptr;
        jb.Bseg[0] = Wh + (size_t)8 * DD * DD;
        jb.Bseg[1] = Wh + (size_t)9 * DD * DD;
        jb.Bseg[2] = nullptr; jb.Bseg[3] = nullptr;
        jb.bias = be1;
        jb.C = nullptr;
        jb.C16 = nullptr;
        jb.We2 = We2;
        jb.outEmo = out;
        jb.nseg = 2;
        jb.lda = DD;
        jb.relu = 1;
        jb.emo = 1;
        gemm_fp16<<<ggemm, 256, GEMM_SMEM>>>(jb);
    }
    sentiment_head<<<NN, 96>>>(h2, x, Wst, bst, out + NN * 7);
}

// round 10
// speedup vs baseline: 5.9446x; 1.0014x over previous
#include <cuda_runtime.h>
#include <cuda_fp16.h>
#include <math.h>
#include <stdint.h>

#define NN 4096
#define DD 1024
#define WW 10
#define BAND 21
#define NSPK 8

// ---------------- device scratch (static, no allocation) ----------------
__device__ float g_band[NN * BAND];
__device__ float g_c[NN];
__device__ float g_diag[NN];
__device__ float g_Pre[NN * DD];
__device__ float g_chunk[128 * DD];
__device__ float g_S[2 * NSPK * DD];
__device__ __half g_Yh[NN * 4 * DD];
__device__ __half g_h1h[NN * DD];
__device__ __half g_h2h[NN * DD];
__device__ __half g_Wh[10 * DD * DD];   // fp16 combined weights, [N,K]
__device__ __half g_Xh[NN * DD];        // fp16 x

// ---------------- helpers -------------------------------------------------
__device__ __forceinline__ uint32_t smem_u32(const void* p) {
    uint32_t a;
    asm("{ .reg .u64 t; cvta.to.shared.u64 t, %1; cvt.u32.u64 %0, t; }"
        : "=r"(a) : "l"(p));
    return a;
}

__device__ __forceinline__ void cp16(uint32_t dst, const void* src) {
    asm volatile("cp.async.cg.shared.global [%0], [%1], 16;"
                 :: "r"(dst), "l"(src) : "memory");
}
#define CP_COMMIT() asm volatile("cp.async.commit_group;" ::: "memory")
#define CP_WAIT2()  asm volatile("cp.async.wait_group 2;" ::: "memory")
#define CP_WAIT0()  asm volatile("cp.async.wait_group 0;" ::: "memory")

__device__ __forceinline__ void mma16(float c[4], const uint32_t a[4],
                                      const uint32_t b[2]) {
    asm volatile(
        "mma.sync.aligned.m16n8k16.row.col.f32.f16.f16.f32 "
        "{%0,%1,%2,%3}, {%4,%5,%6,%7}, {%8,%9}, {%0,%1,%2,%3};"
        : "+f"(c[0]), "+f"(c[1]), "+f"(c[2]), "+f"(c[3])
        : "r"(a[0]), "r"(a[1]), "r"(a[2]), "r"(a[3]), "r"(b[0]), "r"(b[1]));
}

// ---------------- one-time conversion: combined fp16 [N,K] weights ------
struct WCPack {
    const float* a[10];
    const float* b[10];
    float s[10];
};

// dst[z][n*DD + k] = (half)( a[z][k*DD + n] + s[z]*b[z][k*DD + n] )
__global__ __launch_bounds__(256) void conv_wc(WCPack p, __half* __restrict__ dst) {
    __shared__ float t[32][33];
    int z = blockIdx.z;
    const float* A = p.a[z];
    const float* B = p.b[z];
    float sg = p.s[z];
    __half* d = dst + (size_t)z * DD * DD;
    int bx = blockIdx.x * 32, by = blockIdx.y * 32;
    int tx = threadIdx.x & 31, ty = threadIdx.x >> 5;  // 32 x 8
    if (sg != 0.f) {
#pragma unroll
        for (int j = 0; j < 32; j += 8) {
            size_t off = (size_t)(by + ty + j) * DD + bx + tx;
            t[ty + j][tx] = A[off] + sg * B[off];
        }
    } else {
#pragma unroll
        for (int j = 0; j < 32; j += 8) {
            size_t off = (size_t)(by + ty + j) * DD + bx + tx;
            t[ty + j][tx] = A[off];
        }
    }
    __syncthreads();
#pragma unroll
    for (int j = 0; j < 32; j += 8)
        d[(size_t)(bx + ty + j) * DD + by + tx] = __float2half_rn(t[tx][ty + j]);
}

__global__ __launch_bounds__(256) void conv_x(const float* __restrict__ x,
                                              __half* __restrict__ xh) {
    size_t i = ((size_t)blockIdx.x * 256 + threadIdx.x) * 4;
    float4 v = *(const float4*)&x[i];
    *(__half2*)&xh[i] = __floats2half2_rn(v.x, v.y);
    *(__half2*)&xh[i + 2] = __floats2half2_rn(v.z, v.w);
}

// prep: zero both S buffers + init emotion output with bias
__global__ void prep(float* __restrict__ S, float* __restrict__ out,
                     const float* __restrict__ be2) {
    int idx = blockIdx.x * 256 + threadIdx.x;
    if (idx < 2 * NSPK * DD) S[idx] = 0.f;
    int e = idx - 2 * NSPK * DD;
    if (e >= 0 && e < NN * 7) out[e] = be2[e % 7];
}

// ---------------- fused banded logits + softmax (16 i-rows/block) -------
// fp32 x: logits feed exp(), fp16 would break accuracy
__global__ __launch_bounds__(512) void att_full(const float* __restrict__ x,
                                                float* __restrict__ band,
                                                float* __restrict__ cvec,
                                                float* __restrict__ diag) {
    __shared__ float hs[36][256];
    int i0 = blockIdx.x * 16;
    int tid = threadIdx.x, w = tid >> 5, l = tid & 31;

    float acc[BAND];
#pragma unroll
    for (int jo = 0; jo < BAND; jo++) acc[jo] = 0.f;

    for (int ch = 0; ch < 4; ch++) {
        __syncthreads();
        for (int idx = tid; idx < 36 * 256; idx += 512) {
            int r = idx >> 8, c = idx & 255;
            int j = i0 - WW + r;
            hs[r][c] = (j >= 0 && j < NN) ? x[(size_t)j * DD + ch * 256 + c] : 0.f;
        }
        __syncthreads();
#pragma unroll
        for (int e = 0; e < 8; e++) {
            int d = l + e * 32;
            float xv = hs[WW + w][d];
#pragma unroll
            for (int jo = 0; jo < BAND; jo++) acc[jo] += xv * hs[w + jo][d];
        }
    }
#pragma unroll
    for (int jo = 0; jo < BAND; jo++) {
        float v = acc[jo];
#pragma unroll
        for (int o = 16; o > 0; o >>= 1) v += __shfl_down_sync(0xffffffffu, v, o);
        acc[jo] = v;
    }
    if (l == 0) {
        int i = i0 + w;
        int lo = max(i - WW, 0), hi = min(i + WW, NN - 1);
        int cnt = hi - lo + 1;
        float m = 0.0f;  // zeros always in row
#pragma unroll
        for (int jo = 0; jo < BAND; jo++) {
            int j = i - WW + jo;
            if (j >= 0 && j < NN) m = fmaxf(m, acc[jo]);
        }
        float em = expf(-m);
        float Z = (float)(NN - cnt) * em;
        float vals[BAND];
#pragma unroll
        for (int jo = 0; jo < BAND; jo++) {
            int j = i - WW + jo;
            float v = 0.f;
            if (j >= 0 && j < NN) {
                v = expf(acc[jo] - m);
                Z += v;
            }
            vals[jo] = v;
        }
        float inv = 1.0f / Z;
#pragma unroll
        for (int jo = 0; jo < BAND; jo++) band[i * BAND + jo] = vals[jo] * inv;
        cvec[i] = em * inv;
        diag[i] = vals[WW] * inv;
    }
}

// ---------------- scan pass 1: chunk sums + per-speaker sums (fp16 h) ---
__global__ __launch_bounds__(256) void scan1(const __half* __restrict__ h,
                                             const int* __restrict__ spk,
                                             float* __restrict__ chunk,
                                             float* __restrict__ S) {
    __shared__ int sp_sh[32];
    int tid = threadIdx.x;
    int d = blockIdx.y * 256 + tid;
    int base = blockIdx.x * 32;
    if (tid < 32) sp_sh[tid] = spk[base + tid];
    __syncthreads();
    float s = 0.f, sreg[NSPK];
#pragma unroll
    for (int k = 0; k < NSPK; k++) sreg[k] = 0.f;
#pragma unroll 8
    for (int r = 0; r < 32; r++) {
        float v = __half2float(h[(size_t)(base + r) * DD + d]);
        s += v;
        int sp = sp_sh[r];
#pragma unroll
        for (int k = 0; k < NSPK; k++)
            if (sp == k) sreg[k] += v;
    }
    chunk[blockIdx.x * DD + d] = s;
#pragma unroll
    for (int k = 0; k < NSPK; k++) atomicAdd(&S[k * DD + d], sreg[k]);
}

// ---------------- scan pass 2: prefix write (offset from chunk sums) ----
__global__ __launch_bounds__(256) void scan2(const __half* __restrict__ h,
                                             const float* __restrict__ chunk,
                                             float* __restrict__ P) {
    int tid = threadIdx.x;
    int d = blockIdx.y * 256 + tid;
    int bx = blockIdx.x;
    int base = bx * 32;
    float off = 0.f;
#pragma unroll 4
    for (int c = 0; c < bx; c++) off += chunk[c * DD + d];
    float acc = off;
#pragma unroll 8
    for (int r = 0; r < 32; r++) {
        acc += __half2float(h[(size_t)(base + r) * DD + d]);
        P[(size_t)(base + r) * DD + d] = acc;
    }
}

// ---------------- build Y = [ypred | ysuc | ysame | diag*h] (fp16) ------
// (ydiff folded into weights: ydf = yp + ys - ysm)
__global__ __launch_bounds__(256) void build_y(
    const __half* __restrict__ h, const float* __restrict__ Pre,
    const float* __restrict__ S, const float* __restrict__ band,
    const float* __restrict__ cvec, const float* __restrict__ diag,
    const int* __restrict__ spk, __half* __restrict__ Y) {
    __shared__ float hs[36][256];
    __shared__ float a_sh[16][21];
    __shared__ int sp_sh[36];
    __shared__ float c_sh[16], dg_sh[16];
    __shared__ int spi_sh[16];
    int tid = threadIdx.x;
    int i0 = blockIdx.x * 16;
    int d = blockIdx.y * 256 + tid;

#pragma unroll
    for (int r = 0; r < 36; r++) {
        int j = i0 - WW + r;
        hs[r][tid] = (j >= 0 && j < NN) ? __half2float(h[(size_t)j * DD + d]) : 0.f;
    }
    for (int idx = tid; idx < 16 * 21; idx += 256) {
        int il = idx / 21, jo = idx - il * 21;
        int i = i0 + il, j = i - WW + jo;
        a_sh[il][jo] = (j >= 0 && j < NN) ? band[i * BAND + jo] : 0.f;
    }
    if (tid < 36) {
        int j = i0 - WW + tid;
        sp_sh[tid] = (j >= 0 && j < NN) ? spk[j] : -1;
    }
    if (tid < 16) {
        c_sh[tid] = cvec[i0 + tid];
        dg_sh[tid] = diag[i0 + tid];
        spi_sh[tid] = spk[i0 + tid];
    }
    __syncthreads();

    float tot = Pre[(size_t)(NN - 1) * DD + d];
#pragma unroll 2
    for (int ti = 0; ti < 16; ti++) {
        int i = i0 + ti;
        float c = c_sh[ti];
        int spi = spi_sh[ti];
        float yp = 0.f, ys = 0.f, ysm = 0.f;
#pragma unroll
        for (int jo = 0; jo < BAND; jo++) {
            float a = a_sh[ti][jo];
            float hv = hs[ti + jo][tid];
            if (jo >= WW) yp += a * hv; else ys += a * hv;
            if (sp_sh[ti + jo] == spi) ysm += (a - c) * hv;
        }
        int hi = min(i + WW, NN - 1);
        yp += c * (tot - Pre[(size_t)hi * DD + d]);
        if (i - WW - 1 >= 0) ys += c * Pre[(size_t)(i - WW - 1) * DD + d];
        ysm += c * S[spi * DD + d];
        size_t base = (size_t)i * (4 * DD) + d;
        Y[base] = __float2half_rn(yp);
        Y[base + DD] = __float2half_rn(ys);
        Y[base + 2 * DD] = __float2half_rn(ysm);
        Y[base + 3 * DD] = __float2half_rn(dg_sh[ti] * hs[ti + WW][tid]);
    }
}

// ---------------- fp16 mma.sync GEMM, cp.async 3-stage, BK=32 ------------
// C16[NN,DD] = sum_s Aseg[s][:,0:1024] @ Bseg[s]^T   (Bseg = fp16 [N,K])
// optional fused epilogues: bias+relu, emotion-head reduce
struct GJob {
    const __half* Aseg[4];
    const __half* Bseg[4];
    const float* bias;   // nullptr = none
    __half* C16;         // nullptr = no fp16 store
    const float* We2;    // emotion weights [DD,7] (emo mode)
    float* outEmo;       // emotion output [NN,7] (emo mode, atomicAdd)
    int nseg;
    int lda;             // in halves
    int relu;
    int emo;
};

#define BKH 32
#define A_STRIDE 40
#define S_A_HALFS (128 * A_STRIDE)          // 5120
#define STG_HALFS (2 * S_A_HALFS)           // 10240
#define STAGES 3
#define TILE_LD 132
#define GEMM_SMEM ((128 * TILE_LD + 128 * 7) * 4)  // 71168 (>= pipeline 61440)

__global__ __launch_bounds__(256) void gemm_fp16(GJob job) {
    extern __shared__ __half smh[];
    const uint32_t sbase = smem_u32(smh);

    const int tid = threadIdx.x;
    const int row0 = blockIdx.y * 128;
    const int col0 = blockIdx.x * 128;
    const int KT = job.nseg * 32;
    const int lda = job.lda;

    const int wid = tid >> 5, lane = tid & 31;
    const int g = lane >> 2, t = lane & 3;
    const int wr = (wid & 1) * 64;
    const int wc = (wid >> 1) * 32;

    float acc[4][4][4];
#pragma unroll
    for (int m = 0; m < 4; m++)
#pragma unroll
        for (int n = 0; n < 4; n++)
#pragma unroll
            for (int q = 0; q < 4; q++) acc[m][n][q] = 0.f;

    auto issue = [&](int kt) {
        int seg = kt >> 5;
        int kb = (kt & 31) * BKH;
        const __half* A = job.Aseg[seg];
        const __half* B = job.Bseg[seg];
        uint32_t st = sbase + (uint32_t)((kt % STAGES) * STG_HALFS * 2);
        uint32_t stB = st + S_A_HALFS * 2;
#pragma unroll
        for (int l = 0; l < 2; l++) {
            int q = tid + l * 256;
            int r = q >> 2, c8 = (q & 3) * 8;
            cp16(st + (uint32_t)(r * A_STRIDE + c8) * 2,
                 &A[(size_t)(row0 + r) * lda + kb + c8]);
            cp16(stB + (uint32_t)(r * A_STRIDE + c8) * 2,
                 &B[(size_t)(col0 + r) * DD + kb + c8]);
        }
    };

    issue(0);
    CP_COMMIT();
    issue(1);
    CP_COMMIT();

    for (int kt = 0; kt < KT; kt++) {
        if (kt + 2 < KT) issue(kt + 2);
        CP_COMMIT();
        CP_WAIT2();
        __syncthreads();

        const __half* st = smh + (kt % STAGES) * STG_HALFS;
        const __half* Bt = st + S_A_HALFS;

#pragma unroll
        for (int ks = 0; ks < 2; ks++) {
            const int k0 = ks * 16;
            uint32_t aF[4][4], bF[4][2];
#pragma unroll
            for (int m = 0; m < 4; m++) {
                int r = wr + m * 16 + g;
                const __half* p0 = st + r * A_STRIDE + k0 + t * 2;
                const __half* p1 = st + (r + 8) * A_STRIDE + k0 + t * 2;
                aF[m][0] = *(const uint32_t*)p0;
                aF[m][1] = *(const uint32_t*)p1;
                aF[m][2] = *(const uint32_t*)(p0 + 8);
                aF[m][3] = *(const uint32_t*)(p1 + 8);
            }
#pragma unroll
            for (int n = 0; n < 4; n++) {
                int c = wc + n * 8 + g;
                const __half* pb = Bt + c * A_STRIDE + k0 + t * 2;
                bF[n][0] = *(const uint32_t*)pb;
                bF[n][1] = *(const uint32_t*)(pb + 8);
            }
#pragma unroll
            for (int m = 0; m < 4; m++)
#pragma unroll
                for (int n = 0; n < 4; n++) mma16(acc[m][n], aF[m], bF[n]);
        }
        __syncthreads();
    }

    // ---- epilogue ----
    float* tile = (float*)smh;
    float* we2s = tile + 128 * TILE_LD;
    if (job.emo) {
        CP_WAIT0();
        __syncthreads();
    }

#pragma unroll
    for (int m = 0; m < 4; m++) {
        int rl = wr + m * 16 + g;
        int r = row0 + rl;
#pragma unroll
        for (int n = 0; n < 4; n++) {
            int cl = wc + n * 8 + t * 2;
            int c = col0 + cl;
            float2 v0 = make_float2(acc[m][n][0], acc[m][n][1]);
            float2 v1 = make_float2(acc[m][n][2], acc[m][n][3]);
            if (job.bias) {
                float2 b2 = *(const float2*)&job.bias[c];
                v0.x += b2.x; v0.y += b2.y; v1.x += b2.x; v1.y += b2.y;
            }
            if (job.relu) {
                v0.x = fmaxf(v0.x, 0.f); v0.y = fmaxf(v0.y, 0.f);
                v1.x = fmaxf(v1.x, 0.f); v1.y = fmaxf(v1.y, 0.f);
            }
            if (job.C16) {
                *(__half2*)&job.C16[(size_t)r * DD + c] = __floats2half2_rn(v0.x, v0.y);
                *(__half2*)&job.C16[(size_t)(r + 8) * DD + c] = __floats2half2_rn(v1.x, v1.y);
            }
            if (job.emo) {
                tile[rl * TILE_LD + cl] = v0.x;
                tile[rl * TILE_LD + cl + 1] = v0.y;
                tile[(rl + 8) * TILE_LD + cl] = v1.x;
                tile[(rl + 8) * TILE_LD + cl + 1] = v1.y;
            }
        }
    }

    if (job.emo) {
        for (int idx = tid; idx < 128 * 7; idx += 256)
            we2s[idx] = job.We2[(size_t)(col0 + idx / 7) * 7 + (idx % 7)];
        __syncthreads();
        int row = tid >> 1, half = tid & 1;
        float e[7];
#pragma unroll
        for (int w = 0; w < 7; w++) e[w] = 0.f;
        const float* trow = tile + row * TILE_LD + half * 64;
        const float* wbase = we2s + half * 64 * 7;
#pragma unroll 4
        for (int c = 0; c < 64; c++) {
            float tv = trow[c];
            const float* wp = wbase + c * 7;
#pragma unroll
            for (int w = 0; w < 7; w++) e[w] += tv * wp[w];
        }
#pragma unroll
        for (int w = 0; w < 7; w++) e[w] += __shfl_xor_sync(0xffffffffu, e[w], 1);
        if (half == 0) {
#pragma unroll
            for (int w = 0; w < 7; w++)
                atomicAdd(&job.outEmo[(size_t)(row0 + row) * 7 + w], e[w]);
        }
    }
}

// ---------------- sentiment head (fp16 inputs) ----------------------------
__global__ void sentiment_head(const __half* __restrict__ h2,
                               const __half* __restrict__ x,
                               const float* __restrict__ Wst,
                               const float* __restrict__ bst,
                               float* __restrict__ out) {
    int i = blockIdx.x;
    int w = threadIdx.x >> 5, lane = threadIdx.x & 31;
    float acc = 0.f;
    for (int k = lane; k < DD; k += 32)
        acc += __half2float(h2[(size_t)i * DD + k]) * Wst[k * 3 + w];
    for (int k = lane; k < DD; k += 32)
        acc += __half2float(x[(size_t)i * DD + k]) * Wst[(DD + k) * 3 + w];
#pragma unroll
    for (int o = 16; o > 0; o >>= 1) acc += __shfl_down_sync(0xffffffffu, acc, o);
    if (lane == 0) out[i * 3 + w] = acc + bst[w];
}

// ---------------- launch --------------------------------------------------
extern "C" void kernel_launch(void* const* d_in, const int* in_sizes, int n_in,
                              void* d_out, int out_size) {
    const float* x = (const float*)d_in[0];
    const int* spk = (const int*)d_in[1];
    const float* Wp1 = (const float*)d_in[2];
    const float* Ws1 = (const float*)d_in[3];
    const float* Wsm1 = (const float*)d_in[4];
    const float* Wdf1 = (const float*)d_in[5];
    const float* Wp2 = (const float*)d_in[6];
    const float* Ws2 = (const float*)d_in[7];
    const float* Wsm2 = (const float*)d_in[8];
    const float* Wdf2 = (const float*)d_in[9];
    const float* Wa1 = (const float*)d_in[10];
    const float* Wa2 = (const float*)d_in[11];
    const float* We1 = (const float*)d_in[12];
    const float* be1 = (const float*)d_in[13];
    const float* We2 = (const float*)d_in[14];
    const float* be2 = (const float*)d_in[15];
    const float* Wst = (const float*)d_in[16];
    const float* bst = (const float*)d_in[17];
    float* out = (float*)d_out;

    float *band, *cvec, *diag, *Pre, *chunk, *S;
    __half *Yh, *Wh, *Xh, *h1h, *h2h;
    cudaGetSymbolAddress((void**)&band, g_band);
    cudaGetSymbolAddress((void**)&cvec, g_c);
    cudaGetSymbolAddress((void**)&diag, g_diag);
    cudaGetSymbolAddress((void**)&Pre, g_Pre);
    cudaGetSymbolAddress((void**)&chunk, g_chunk);
    cudaGetSymbolAddress((void**)&S, g_S);
    cudaGetSymbolAddress((void**)&Yh, g_Yh);
    cudaGetSymbolAddress((void**)&Wh, g_Wh);
    cudaGetSymbolAddress((void**)&Xh, g_Xh);
    cudaGetSymbolAddress((void**)&h1h, g_h1h);
    cudaGetSymbolAddress((void**)&h2h, g_h2h);

    cudaFuncSetAttribute(gemm_fp16, cudaFuncAttributeMaxDynamicSharedMemorySize,
                         GEMM_SMEM);

    // combined fp16 weight panels, transposed to [N,K]:
    // 0..3: L1 {Wp+Wdf, Ws+Wdf, Wsm-Wdf, Wa}; 4..7: L2 same; 8,9: We1 halves
    WCPack wp;
    const float* As[10] = {Wp1, Ws1, Wsm1, Wa1, Wp2, Ws2, Wsm2, Wa2,
                           We1, We1 + (size_t)DD * DD};
    const float* Bs[10] = {Wdf1, Wdf1, Wdf1, Wa1, Wdf2, Wdf2, Wdf2, Wa2,
                           We1, We1};
    float Sg[10] = {1.f, 1.f, -1.f, 0.f, 1.f, 1.f, -1.f, 0.f, 0.f, 0.f};
    for (int i = 0; i < 10; i++) { wp.a[i] = As[i]; wp.b[i] = Bs[i]; wp.s[i] = Sg[i]; }
    conv_wc<<<dim3(32, 32, 10), 256>>>(wp, Wh);
    conv_x<<<NN * DD / 1024, 256>>>(x, Xh);
    prep<<<(2 * NSPK * DD + NN * 7 + 255) / 256, 256>>>(S, out, be2);

    att_full<<<NN / 16, 512>>>(x, band, cvec, diag);

    const __half* hin = Xh;
    __half* houts[2] = {h1h, h2h};
    dim3 ggemm(DD / 128, NN / 128);

    for (int L = 0; L < 2; L++) {
        float* SL = S + (size_t)L * NSPK * DD;
        scan1<<<dim3(128, 4), 256>>>(hin, spk, chunk, SL);
        scan2<<<dim3(128, 4), 256>>>(hin, chunk, Pre);
        build_y<<<dim3(NN / 16, 4), 256>>>(hin, Pre, SL, band, cvec, diag, spk, Yh);

        GJob jb;
        for (int s = 0; s < 4; s++) {
            jb.Aseg[s] = Yh + (size_t)s * DD;
            jb.Bseg[s] = Wh + (size_t)(L * 4 + s) * DD * DD;
        }
        jb.bias = nullptr;
        jb.C16 = houts[L];
        jb.We2 = nullptr;
        jb.outEmo = nullptr;
        jb.nseg = 4;
        jb.lda = 4 * DD;
        jb.relu = 1;
        jb.emo = 0;
        gemm_fp16<<<ggemm, 256, GEMM_SMEM>>>(jb);
        hin = houts[L];
    }

    // emotion: out[:, :7] = relu([h2|x]@We1 + be1) @ We2 + be2 (fused in GEMM)
    {
        GJob jb;
        jb.Aseg[0] = h2h; jb.Aseg[1] = Xh;
        jb.Aseg[2] = nullptr; jb.Aseg[3] = nullptr;
        jb.Bseg[0] = Wh + (size_t)8 * DD * DD;
        jb.Bseg[1] = Wh + (size_t)9 * DD * DD;
        jb.Bseg[2] = nullptr; jb.Bseg[3] = nullptr;
        jb.bias = be1;
        jb.C16 = nullptr;
        jb.We2 = We2;
        jb.outEmo = out;
        jb.nseg = 2;
        jb.lda = DD;
        jb.relu = 1;
        jb.emo = 1;
        gemm_fp16<<<ggemm, 256, GEMM_SMEM>>>(jb);
    }
    sentiment_head<<<NN, 96>>>(h2h, Xh, Wst, bst, out + NN * 7);
}

// round 11
// speedup vs baseline: 6.4587x; 1.0865x over previous
#include <cuda_runtime.h>
#include <cuda_fp16.h>
#include <math.h>
#include <stdint.h>

#define NN 4096
#define DD 1024
#define WW 10
#define BAND 21
#define NSPK 8
#define H0OFF 10   // halo starts at i0-10 (36 rows)

// ---------------- device scratch (static, no allocation) ----------------
__device__ float g_band[NN * BAND];
__device__ float g_c[NN];
__device__ float g_diag[NN];
__device__ float g_chunk[256 * DD];
__device__ float g_PreC[257 * DD];
__device__ float g_S[2 * NSPK * DD];
__device__ __half g_Yh[NN * 4 * DD];
__device__ __half g_h1h[NN * DD];
__device__ __half g_h2h[NN * DD];
__device__ __half g_Wh[10 * DD * DD];   // fp16 combined weights, [N,K]
__device__ __half g_Xh[NN * DD];        // fp16 x

// ---------------- helpers -------------------------------------------------
__device__ __forceinline__ uint32_t smem_u32(const void* p) {
    uint32_t a;
    asm("{ .reg .u64 t; cvta.to.shared.u64 t, %1; cvt.u32.u64 %0, t; }"
        : "=r"(a) : "l"(p));
    return a;
}

__device__ __forceinline__ void cp16(uint32_t dst, const void* src) {
    asm volatile("cp.async.cg.shared.global [%0], [%1], 16;"
                 :: "r"(dst), "l"(src) : "memory");
}
#define CP_COMMIT() asm volatile("cp.async.commit_group;" ::: "memory")
#define CP_WAIT2()  asm volatile("cp.async.wait_group 2;" ::: "memory")
#define CP_WAIT0()  asm volatile("cp.async.wait_group 0;" ::: "memory")

__device__ __forceinline__ void mma16(float c[4], const uint32_t a[4],
                                      const uint32_t b[2]) {
    asm volatile(
        "mma.sync.aligned.m16n8k16.row.col.f32.f16.f16.f32 "
        "{%0,%1,%2,%3}, {%4,%5,%6,%7}, {%8,%9}, {%0,%1,%2,%3};"
        : "+f"(c[0]), "+f"(c[1]), "+f"(c[2]), "+f"(c[3])
        : "r"(a[0]), "r"(a[1]), "r"(a[2]), "r"(a[3]), "r"(b[0]), "r"(b[1]));
}

__device__ __forceinline__ void ldsm4(uint32_t& r0, uint32_t& r1,
                                      uint32_t& r2, uint32_t& r3, uint32_t addr) {
    asm volatile("ldmatrix.sync.aligned.m8n8.x4.shared.b16 {%0,%1,%2,%3}, [%4];"
                 : "=r"(r0), "=r"(r1), "=r"(r2), "=r"(r3) : "r"(addr));
}

// ---------------- one-time conversion: combined fp16 [N,K] weights ------
struct WCPack {
    const float* a[10];
    const float* b[10];
    float s[10];
};

__global__ __launch_bounds__(256) void conv_wc(WCPack p, __half* __restrict__ dst) {
    __shared__ float t[32][33];
    int z = blockIdx.z;
    const float* A = p.a[z];
    const float* B = p.b[z];
    float sg = p.s[z];
    __half* d = dst + (size_t)z * DD * DD;
    int bx = blockIdx.x * 32, by = blockIdx.y * 32;
    int tx = threadIdx.x & 31, ty = threadIdx.x >> 5;
    if (sg != 0.f) {
#pragma unroll
        for (int j = 0; j < 32; j += 8) {
            size_t off = (size_t)(by + ty + j) * DD + bx + tx;
            t[ty + j][tx] = A[off] + sg * B[off];
        }
    } else {
#pragma unroll
        for (int j = 0; j < 32; j += 8) {
            size_t off = (size_t)(by + ty + j) * DD + bx + tx;
            t[ty + j][tx] = A[off];
        }
    }
    __syncthreads();
#pragma unroll
    for (int j = 0; j < 32; j += 8)
        d[(size_t)(bx + ty + j) * DD + by + tx] = __float2half_rn(t[tx][ty + j]);
}

__global__ __launch_bounds__(256) void conv_x(const float* __restrict__ x,
                                              __half* __restrict__ xh) {
    size_t i = ((size_t)blockIdx.x * 256 + threadIdx.x) * 4;
    float4 v = *(const float4*)&x[i];
    *(__half2*)&xh[i] = __floats2half2_rn(v.x, v.y);
    *(__half2*)&xh[i + 2] = __floats2half2_rn(v.z, v.w);
}

// prep: zero both S buffers + init emotion output with bias
__global__ void prep(float* __restrict__ S, float* __restrict__ out,
                     const float* __restrict__ be2) {
    int idx = blockIdx.x * 256 + threadIdx.x;
    if (idx < 2 * NSPK * DD) S[idx] = 0.f;
    int e = idx - 2 * NSPK * DD;
    if (e >= 0 && e < NN * 7) out[e] = be2[e % 7];
}

// ---------------- fused banded logits + softmax (16 i-rows/block) -------
__global__ __launch_bounds__(512) void att_full(const float* __restrict__ x,
                                                float* __restrict__ band,
                                                float* __restrict__ cvec,
                                                float* __restrict__ diag) {
    __shared__ float hs[36][256];
    int i0 = blockIdx.x * 16;
    int tid = threadIdx.x, w = tid >> 5, l = tid & 31;

    float acc[BAND];
#pragma unroll
    for (int jo = 0; jo < BAND; jo++) acc[jo] = 0.f;

    for (int ch = 0; ch < 4; ch++) {
        __syncthreads();
        for (int idx = tid; idx < 36 * 256; idx += 512) {
            int r = idx >> 8, c = idx & 255;
            int j = i0 - WW + r;
            hs[r][c] = (j >= 0 && j < NN) ? x[(size_t)j * DD + ch * 256 + c] : 0.f;
        }
        __syncthreads();
#pragma unroll
        for (int e = 0; e < 8; e++) {
            int d = l + e * 32;
            float xv = hs[WW + w][d];
#pragma unroll
            for (int jo = 0; jo < BAND; jo++) acc[jo] += xv * hs[w + jo][d];
        }
    }
#pragma unroll
    for (int jo = 0; jo < BAND; jo++) {
        float v = acc[jo];
#pragma unroll
        for (int o = 16; o > 0; o >>= 1) v += __shfl_down_sync(0xffffffffu, v, o);
        acc[jo] = v;
    }
    if (l == 0) {
        int i = i0 + w;
        int lo = max(i - WW, 0), hi = min(i + WW, NN - 1);
        int cnt = hi - lo + 1;
        float m = 0.0f;
#pragma unroll
        for (int jo = 0; jo < BAND; jo++) {
            int j = i - WW + jo;
            if (j >= 0 && j < NN) m = fmaxf(m, acc[jo]);
        }
        float em = expf(-m);
        float Z = (float)(NN - cnt) * em;
        float vals[BAND];
#pragma unroll
        for (int jo = 0; jo < BAND; jo++) {
            int j = i - WW + jo;
            float v = 0.f;
            if (j >= 0 && j < NN) {
                v = expf(acc[jo] - m);
                Z += v;
            }
            vals[jo] = v;
        }
        float inv = 1.0f / Z;
#pragma unroll
        for (int jo = 0; jo < BAND; jo++) band[i * BAND + jo] = vals[jo] * inv;
        cvec[i] = em * inv;
        diag[i] = vals[WW] * inv;
    }
}

// ---------------- scan1: 16-row chunk sums + per-speaker sums -----------
__global__ __launch_bounds__(256) void scan1(const __half* __restrict__ h,
                                             const int* __restrict__ spk,
                                             float* __restrict__ chunk,
                                             float* __restrict__ S) {
    __shared__ int sp_sh[16];
    int tid = threadIdx.x;
    int d = blockIdx.y * 256 + tid;
    int base = blockIdx.x * 16;
    if (tid < 16) sp_sh[tid] = spk[base + tid];
    __syncthreads();
    float s = 0.f, sreg[NSPK];
#pragma unroll
    for (int k = 0; k < NSPK; k++) sreg[k] = 0.f;
#pragma unroll
    for (int r = 0; r < 16; r++) {
        float v = __half2float(h[(size_t)(base + r) * DD + d]);
        s += v;
        int sp = sp_sh[r];
#pragma unroll
        for (int k = 0; k < NSPK; k++)
            if (sp == k) sreg[k] += v;
    }
    chunk[blockIdx.x * DD + d] = s;
#pragma unroll
    for (int k = 0; k < NSPK; k++)
        if (sreg[k] != 0.f) atomicAdd(&S[k * DD + d], sreg[k]);
}

// ---------------- chunkpre: exclusive prefix over 256 chunks -------------
__global__ __launch_bounds__(256) void chunkpre(const float* __restrict__ chunk,
                                                float* __restrict__ PreC) {
    int tid = threadIdx.x;
    int d = blockIdx.y * 256 + tid;
    int c0 = blockIdx.x * 16;
    float s = 0.f;
#pragma unroll 8
    for (int c = 0; c < c0; c++) s += chunk[c * DD + d];
#pragma unroll
    for (int k = 0; k < 16; k++) {
        PreC[(size_t)(c0 + k) * DD + d] = s;
        s += chunk[(c0 + k) * DD + d];
    }
    if (blockIdx.x == 15) PreC[(size_t)256 * DD + d] = s;
}

// ---------------- build Y = [ypred | ysuc | ysame | diag*h] (fp16) ------
// Pre values reconstructed from PreC (chunk prefix) + in-halo prefix hp
#define BY_SMEM (2 * 36 * 256 * 4)

__global__ __launch_bounds__(256) void build_y(
    const __half* __restrict__ h, const float* __restrict__ PreC,
    const float* __restrict__ S, const float* __restrict__ band,
    const float* __restrict__ cvec, const float* __restrict__ diag,
    const int* __restrict__ spk, __half* __restrict__ Y) {
    extern __shared__ float dyn[];
    float(*hs)[256] = (float(*)[256])dyn;
    float(*hp)[256] = (float(*)[256])(dyn + 36 * 256);
    __shared__ float a_sh[16][21];
    __shared__ int sp_sh[36];
    __shared__ float c_sh[16], dg_sh[16];
    __shared__ int spi_sh[16];
    int tid = threadIdx.x;
    int i0 = blockIdx.x * 16;
    int d = blockIdx.y * 256 + tid;
    const int h0 = i0 - H0OFF;

    {
        float run = 0.f;
#pragma unroll
        for (int r = 0; r < 36; r++) {
            int j = h0 + r;
            float v = (j >= 0 && j < NN) ? __half2float(h[(size_t)j * DD + d]) : 0.f;
            hs[r][tid] = v;
            run += v;
            hp[r][tid] = run;
        }
    }
    for (int idx = tid; idx < 16 * 21; idx += 256) {
        int il = idx / 21, jo = idx - il * 21;
        int i = i0 + il, j = i - WW + jo;
        a_sh[il][jo] = (j >= 0 && j < NN) ? band[i * BAND + jo] : 0.f;
    }
    if (tid < 36) {
        int j = h0 + tid;
        sp_sh[tid] = (j >= 0 && j < NN) ? spk[j] : -1;
    }
    if (tid < 16) {
        c_sh[tid] = cvec[i0 + tid];
        dg_sh[tid] = diag[i0 + tid];
        spi_sh[tid] = spk[i0 + tid];
    }
    __syncthreads();

    float tot = PreC[(size_t)256 * DD + d];
#pragma unroll 2
    for (int ti = 0; ti < 16; ti++) {
        int i = i0 + ti;
        float c = c_sh[ti];
        int spi = spi_sh[ti];
        float yp = 0.f, ys = 0.f, ysm = 0.f;
#pragma unroll
        for (int jo = 0; jo < BAND; jo++) {
            float a = a_sh[ti][jo];
            float hv = hs[ti + jo][tid];
            if (jo >= WW) yp += a * hv; else ys += a * hv;
            if (sp_sh[ti + jo] == spi) ysm += (a - c) * hv;
        }
        // suffix: c * (tot - Pre[hi]); Pre[hi] = PreC[cp] + sum rows [16cp..hi]
        int hi = min(i + WW, NN - 1);
        int cp = hi >> 4;
        float PreHi = PreC[(size_t)cp * DD + d] + hp[hi - h0][tid]
                      - hp[16 * cp - 1 - h0][tid];
        yp += c * (tot - PreHi);
        // prefix: c * Pre[p2]; Pre[p2] = PreC[cq] - sum rows [p2+1..16cq-1]
        int p2 = i - WW - 1;
        if (p2 >= 0) {
            int cq = (p2 >> 4) + 1;
            float hpp2 = (p2 >= h0) ? hp[p2 - h0][tid] : 0.f;
            float PreP2 = PreC[(size_t)cq * DD + d]
                          - (hp[16 * cq - 1 - h0][tid] - hpp2);
            ys += c * PreP2;
        }
        ysm += c * S[spi * DD + d];
        size_t base = (size_t)i * (4 * DD) + d;
        Y[base] = __float2half_rn(yp);
        Y[base + DD] = __float2half_rn(ys);
        Y[base + 2 * DD] = __float2half_rn(ysm);
        Y[base + 3 * DD] = __float2half_rn(dg_sh[ti] * hs[ti + H0OFF][tid]);
    }
}

// ---------------- fp16 mma.sync GEMM, cp.async 3-stage, ldmatrix frags ---
struct GJob {
    const __half* Aseg[4];
    const __half* Bseg[4];
    const float* bias;
    __half* C16;
    const float* We2;
    float* outEmo;
    int nseg;
    int lda;
    int relu;
    int emo;
};

#define BKH 32
#define A_STRIDE 40
#define S_A_HALFS (128 * A_STRIDE)
#define STG_HALFS (2 * S_A_HALFS)
#define STAGES 3
#define TILE_LD 132
#define GEMM_SMEM ((128 * TILE_LD + 128 * 7) * 4)

__global__ __launch_bounds__(256) void gemm_fp16(GJob job) {
    extern __shared__ __half smh[];
    const uint32_t sbase = smem_u32(smh);

    const int tid = threadIdx.x;
    const int row0 = blockIdx.y * 128;
    const int col0 = blockIdx.x * 128;
    const int KT = job.nseg * 32;
    const int lda = job.lda;

    const int wid = tid >> 5, lane = tid & 31;
    const int g = lane >> 2, t = lane & 3;
    const int wr = (wid & 1) * 64;
    const int wc = (wid >> 1) * 32;

    // ldmatrix per-lane address components
    const uint32_t laneA =
        (uint32_t)((wr + (lane & 15)) * A_STRIDE + ((lane >> 4) << 3)) * 2;
    const uint32_t laneB =
        (uint32_t)((wc + ((lane >> 4) << 3) + (lane & 7)) * A_STRIDE +
                   (((lane >> 3) & 1) << 3)) * 2;

    float acc[4][4][4];
#pragma unroll
    for (int m = 0; m < 4; m++)
#pragma unroll
        for (int n = 0; n < 4; n++)
#pragma unroll
            for (int q = 0; q < 4; q++) acc[m][n][q] = 0.f;

    auto issue = [&](int kt) {
        int seg = kt >> 5;
        int kb = (kt & 31) * BKH;
        const __half* A = job.Aseg[seg];
        const __half* B = job.Bseg[seg];
        uint32_t st = sbase + (uint32_t)((kt % STAGES) * STG_HALFS * 2);
        uint32_t stB = st + S_A_HALFS * 2;
#pragma unroll
        for (int l = 0; l < 2; l++) {
            int q = tid + l * 256;
            int r = q >> 2, c8 = (q & 3) * 8;
            cp16(st + (uint32_t)(r * A_STRIDE + c8) * 2,
                 &A[(size_t)(row0 + r) * lda + kb + c8]);
            cp16(stB + (uint32_t)(r * A_STRIDE + c8) * 2,
                 &B[(size_t)(col0 + r) * DD + kb + c8]);
        }
    };

    issue(0);
    CP_COMMIT();
    issue(1);
    CP_COMMIT();

    for (int kt = 0; kt < KT; kt++) {
        if (kt + 2 < KT) issue(kt + 2);
        CP_COMMIT();
        CP_WAIT2();
        __syncthreads();

        uint32_t sA = sbase + (uint32_t)((kt % STAGES) * STG_HALFS * 2);
        uint32_t sB = sA + S_A_HALFS * 2;

#pragma unroll
        for (int ks = 0; ks < 2; ks++) {
            const uint32_t koff = ks * 32;  // 16 halves
            uint32_t aF[4][4], bF[4][2];
#pragma unroll
            for (int m = 0; m < 4; m++)
                ldsm4(aF[m][0], aF[m][1], aF[m][2], aF[m][3],
                      sA + laneA + m * 1280 + koff);
#pragma unroll
            for (int j = 0; j < 2; j++) {
                uint32_t r0, r1, r2, r3;
                ldsm4(r0, r1, r2, r3, sB + laneB + j * 1280 + koff);
                bF[2 * j][0] = r0; bF[2 * j][1] = r1;
                bF[2 * j + 1][0] = r2; bF[2 * j + 1][1] = r3;
            }
#pragma unroll
            for (int m = 0; m < 4; m++)
#pragma unroll
                for (int n = 0; n < 4; n++) mma16(acc[m][n], aF[m], bF[n]);
        }
        __syncthreads();
    }

    // ---- epilogue ----
    float* tile = (float*)smh;
    float* we2s = tile + 128 * TILE_LD;
    if (job.emo) {
        CP_WAIT0();
        __syncthreads();
    }

#pragma unroll
    for (int m = 0; m < 4; m++) {
        int rl = wr + m * 16 + g;
        int r = row0 + rl;
#pragma unroll
        for (int n = 0; n < 4; n++) {
            int cl = wc + n * 8 + t * 2;
            int c = col0 + cl;
            float2 v0 = make_float2(acc[m][n][0], acc[m][n][1]);
            float2 v1 = make_float2(acc[m][n][2], acc[m][n][3]);
            if (job.bias) {
                float2 b2 = *(const float2*)&job.bias[c];
                v0.x += b2.x; v0.y += b2.y; v1.x += b2.x; v1.y += b2.y;
            }
            if (job.relu) {
                v0.x = fmaxf(v0.x, 0.f); v0.y = fmaxf(v0.y, 0.f);
                v1.x = fmaxf(v1.x, 0.f); v1.y = fmaxf(v1.y, 0.f);
            }
            if (job.C16) {
                *(__half2*)&job.C16[(size_t)r * DD + c] = __floats2half2_rn(v0.x, v0.y);
                *(__half2*)&job.C16[(size_t)(r + 8) * DD + c] = __floats2half2_rn(v1.x, v1.y);
            }
            if (job.emo) {
                tile[rl * TILE_LD + cl] = v0.x;
                tile[rl * TILE_LD + cl + 1] = v0.y;
                tile[(rl + 8) * TILE_LD + cl] = v1.x;
                tile[(rl + 8) * TILE_LD + cl + 1] = v1.y;
            }
        }
    }

    if (job.emo) {
        for (int idx = tid; idx < 128 * 7; idx += 256)
            we2s[idx] = job.We2[(size_t)(col0 + idx / 7) * 7 + (idx % 7)];
        __syncthreads();
        int row = tid >> 1, half = tid & 1;
        float e[7];
#pragma unroll
        for (int w = 0; w < 7; w++) e[w] = 0.f;
        const float* trow = tile + row * TILE_LD + half * 64;
        const float* wbase = we2s + half * 64 * 7;
#pragma unroll 4
        for (int c = 0; c < 64; c++) {
            float tv = trow[c];
            const float* wp = wbase + c * 7;
#pragma unroll
            for (int w = 0; w < 7; w++) e[w] += tv * wp[w];
        }
#pragma unroll
        for (int w = 0; w < 7; w++) e[w] += __shfl_xor_sync(0xffffffffu, e[w], 1);
        if (half == 0) {
#pragma unroll
            for (int w = 0; w < 7; w++)
                atomicAdd(&job.outEmo[(size_t)(row0 + row) * 7 + w], e[w]);
        }
    }
}

// ---------------- sentiment head (fp16 inputs) ----------------------------
__global__ void sentiment_head(const __half* __restrict__ h2,
                               const __half* __restrict__ x,
                               const float* __restrict__ Wst,
                               const float* __restrict__ bst,
                               float* __restrict__ out) {
    int i = blockIdx.x;
    int w = threadIdx.x >> 5, lane = threadIdx.x & 31;
    float acc = 0.f;
    for (int k = lane; k < DD; k += 32)
        acc += __half2float(h2[(size_t)i * DD + k]) * Wst[k * 3 + w];
    for (int k = lane; k < DD; k += 32)
        acc += __half2float(x[(size_t)i * DD + k]) * Wst[(DD + k) * 3 + w];
#pragma unroll
    for (int o = 16; o > 0; o >>= 1) acc += __shfl_down_sync(0xffffffffu, acc, o);
    if (lane == 0) out[i * 3 + w] = acc + bst[w];
}

// ---------------- launch --------------------------------------------------
extern "C" void kernel_launch(void* const* d_in, const int* in_sizes, int n_in,
                              void* d_out, int out_size) {
    const float* x = (const float*)d_in[0];
    const int* spk = (const int*)d_in[1];
    const float* Wp1 = (const float*)d_in[2];
    const float* Ws1 = (const float*)d_in[3];
    const float* Wsm1 = (const float*)d_in[4];
    const float* Wdf1 = (const float*)d_in[5];
    const float* Wp2 = (const float*)d_in[6];
    const float* Ws2 = (const float*)d_in[7];
    const float* Wsm2 = (const float*)d_in[8];
    const float* Wdf2 = (const float*)d_in[9];
    const float* Wa1 = (const float*)d_in[10];
    const float* Wa2 = (const float*)d_in[11];
    const float* We1 = (const float*)d_in[12];
    const float* be1 = (const float*)d_in[13];
    const float* We2 = (const float*)d_in[14];
    const float* be2 = (const float*)d_in[15];
    const float* Wst = (const float*)d_in[16];
    const float* bst = (const float*)d_in[17];
    float* out = (float*)d_out;

    float *band, *cvec, *diag, *chunk, *PreC, *S;
    __half *Yh, *Wh, *Xh, *h1h, *h2h;
    cudaGetSymbolAddress((void**)&band, g_band);
    cudaGetSymbolAddress((void**)&cvec, g_c);
    cudaGetSymbolAddress((void**)&diag, g_diag);
    cudaGetSymbolAddress((void**)&chunk, g_chunk);
    cudaGetSymbolAddress((void**)&PreC, g_PreC);
    cudaGetSymbolAddress((void**)&S, g_S);
    cudaGetSymbolAddress((void**)&Yh, g_Yh);
    cudaGetSymbolAddress((void**)&Wh, g_Wh);
    cudaGetSymbolAddress((void**)&Xh, g_Xh);
    cudaGetSymbolAddress((void**)&h1h, g_h1h);
    cudaGetSymbolAddress((void**)&h2h, g_h2h);

    cudaFuncSetAttribute(gemm_fp16, cudaFuncAttributeMaxDynamicSharedMemorySize,
                         GEMM_SMEM);
    cudaFuncSetAttribute(build_y, cudaFuncAttributeMaxDynamicSharedMemorySize,
                         BY_SMEM);

    WCPack wp;
    const float* As[10] = {Wp1, Ws1, Wsm1, Wa1, Wp2, Ws2, Wsm2, Wa2,
                           We1, We1 + (size_t)DD * DD};
    const float* Bs[10] = {Wdf1, Wdf1, Wdf1, Wa1, Wdf2, Wdf2, Wdf2, Wa2,
                           We1, We1};
    float Sg[10] = {1.f, 1.f, -1.f, 0.f, 1.f, 1.f, -1.f, 0.f, 0.f, 0.f};
    for (int i = 0; i < 10; i++) { wp.a[i] = As[i]; wp.b[i] = Bs[i]; wp.s[i] = Sg[i]; }
    conv_wc<<<dim3(32, 32, 10), 256>>>(wp, Wh);
    conv_x<<<NN * DD / 1024, 256>>>(x, Xh);
    prep<<<(2 * NSPK * DD + NN * 7 + 255) / 256, 256>>>(S, out, be2);

    att_full<<<NN / 16, 512>>>(x, band, cvec, diag);

    const __half* hin = Xh;
    __half* houts[2] = {h1h, h2h};
    dim3 ggemm(DD / 128, NN / 128);

    for (int L = 0; L < 2; L++) {
        float* SL = S + (size_t)L * NSPK * DD;
        scan1<<<dim3(256, 4), 256>>>(hin, spk, chunk, SL);
        chunkpre<<<dim3(16, 4), 256>>>(chunk, PreC);
        build_y<<<dim3(NN / 16, 4), 256, BY_SMEM>>>(hin, PreC, SL, band, cvec,
                                                    diag, spk, Yh);

        GJob jb;
        for (int s = 0; s < 4; s++) {
            jb.Aseg[s] = Yh + (size_t)s * DD;
            jb.Bseg[s] = Wh + (size_t)(L * 4 + s) * DD * DD;
        }
        jb.bias = nullptr;
        jb.C16 = houts[L];
        jb.We2 = nullptr;
        jb.outEmo = nullptr;
        jb.nseg = 4;
        jb.lda = 4 * DD;
        jb.relu = 1;
        jb.emo = 0;
        gemm_fp16<<<ggemm, 256, GEMM_SMEM>>>(jb);
        hin = houts[L];
    }

    // emotion: out[:, :7] = relu([h2|x]@We1 + be1) @ We2 + be2 (fused)
    {
        GJob jb;
        jb.Aseg[0] = h2h; jb.Aseg[1] = Xh;
        jb.Aseg[2] = nullptr; jb.Aseg[3] = nullptr;
        jb.Bseg[0] = Wh + (size_t)8 * DD * DD;
        jb.Bseg[1] = Wh + (size_t)9 * DD * DD;
        jb.Bseg[2] = nullptr; jb.Bseg[3] = nullptr;
        jb.bias = be1;
        jb.C16 = nullptr;
        jb.We2 = We2;
        jb.outEmo = out;
        jb.nseg = 2;
        jb.lda = DD;
        jb.relu = 1;
        jb.emo = 1;
        gemm_fp16<<<ggemm, 256, GEMM_SMEM>>>(jb);
    }
    sentiment_head<<<NN, 96>>>(h2h, Xh, Wst, bst, out + NN * 7);
}

// round 12
// speedup vs baseline: 6.5976x; 1.0215x over previous
#include <cuda_runtime.h>
#include <cuda_fp16.h>
#include <math.h>
#include <stdint.h>

#define NN 4096
#define DD 1024
#define WW 10
#define BAND 21
#define NSPK 8
#define H0OFF 10   // halo starts at i0-10 (36 rows)

// ---------------- device scratch (static, no allocation) ----------------
__device__ float g_raw[NN * 11];
__device__ float g_band[NN * BAND];
__device__ float g_c[NN];
__device__ float g_diag[NN];
__device__ float g_chunk[256 * DD];
__device__ float g_PreC[257 * DD];
__device__ float g_S[2 * NSPK * DD];
__device__ __half g_Yh[NN * 4 * DD];
__device__ __half g_h1h[NN * DD];
__device__ __half g_h2h[NN * DD];
__device__ __half g_Wh[10 * DD * DD];   // fp16 combined weights, [N,K]
__device__ __half g_Xh[NN * DD];        // fp16 x

// ---------------- helpers -------------------------------------------------
__device__ __forceinline__ uint32_t smem_u32(const void* p) {
    uint32_t a;
    asm("{ .reg .u64 t; cvta.to.shared.u64 t, %1; cvt.u32.u64 %0, t; }"
        : "=r"(a) : "l"(p));
    return a;
}

__device__ __forceinline__ void cp16(uint32_t dst, const void* src) {
    asm volatile("cp.async.cg.shared.global [%0], [%1], 16;"
                 :: "r"(dst), "l"(src) : "memory");
}
#define CP_COMMIT() asm volatile("cp.async.commit_group;" ::: "memory")
#define CP_WAIT2()  asm volatile("cp.async.wait_group 2;" ::: "memory")
#define CP_WAIT0()  asm volatile("cp.async.wait_group 0;" ::: "memory")

__device__ __forceinline__ void mma16(float c[4], const uint32_t a[4],
                                      const uint32_t b[2]) {
    asm volatile(
        "mma.sync.aligned.m16n8k16.row.col.f32.f16.f16.f32 "
        "{%0,%1,%2,%3}, {%4,%5,%6,%7}, {%8,%9}, {%0,%1,%2,%3};"
        : "+f"(c[0]), "+f"(c[1]), "+f"(c[2]), "+f"(c[3])
        : "r"(a[0]), "r"(a[1]), "r"(a[2]), "r"(a[3]), "r"(b[0]), "r"(b[1]));
}

__device__ __forceinline__ void ldsm4(uint32_t& r0, uint32_t& r1,
                                      uint32_t& r2, uint32_t& r3, uint32_t addr) {
    asm volatile("ldmatrix.sync.aligned.m8n8.x4.shared.b16 {%0,%1,%2,%3}, [%4];"
                 : "=r"(r0), "=r"(r1), "=r"(r2), "=r"(r3) : "r"(addr));
}

// ---------------- one-time conversion: combined fp16 [N,K] weights ------
struct WCPack {
    const float* a[10];
    const float* b[10];
    float s[10];
};

__global__ __launch_bounds__(256) void conv_wc(WCPack p, __half* __restrict__ dst) {
    __shared__ float t[32][33];
    int z = blockIdx.z;
    const float* A = p.a[z];
    const float* B = p.b[z];
    float sg = p.s[z];
    __half* d = dst + (size_t)z * DD * DD;
    int bx = blockIdx.x * 32, by = blockIdx.y * 32;
    int tx = threadIdx.x & 31, ty = threadIdx.x >> 5;
    if (sg != 0.f) {
#pragma unroll
        for (int j = 0; j < 32; j += 8) {
            size_t off = (size_t)(by + ty + j) * DD + bx + tx;
            t[ty + j][tx] = A[off] + sg * B[off];
        }
    } else {
#pragma unroll
        for (int j = 0; j < 32; j += 8) {
            size_t off = (size_t)(by + ty + j) * DD + bx + tx;
            t[ty + j][tx] = A[off];
        }
    }
    __syncthreads();
#pragma unroll
    for (int j = 0; j < 32; j += 8)
        d[(size_t)(bx + ty + j) * DD + by + tx] = __float2half_rn(t[tx][ty + j]);
}

__global__ __launch_bounds__(256) void conv_x(const float* __restrict__ x,
                                              __half* __restrict__ xh) {
    size_t i = ((size_t)blockIdx.x * 256 + threadIdx.x) * 4;
    float4 v = *(const float4*)&x[i];
    *(__half2*)&xh[i] = __floats2half2_rn(v.x, v.y);
    *(__half2*)&xh[i + 2] = __floats2half2_rn(v.z, v.w);
}

// prep: zero both S buffers + init emotion output with bias
__global__ void prep(float* __restrict__ S, float* __restrict__ out,
                     const float* __restrict__ be2) {
    int idx = blockIdx.x * 256 + threadIdx.x;
    if (idx < 2 * NSPK * DD) S[idx] = 0.f;
    int e = idx - 2 * NSPK * DD;
    if (e >= 0 && e < NN * 7) out[e] = be2[e % 7];
}

// ---------------- banded logits, symmetric half: raw[i][k]=dot(x_i,x_{i+k})
__global__ __launch_bounds__(512) void att_half(const float* __restrict__ x,
                                                float* __restrict__ raw) {
    __shared__ float hs[26][256];
    int i0 = blockIdx.x * 16;
    int tid = threadIdx.x, w = tid >> 5, l = tid & 31;

    float acc[11];
#pragma unroll
    for (int k = 0; k < 11; k++) acc[k] = 0.f;

    for (int ch = 0; ch < 4; ch++) {
        __syncthreads();
        for (int idx = tid; idx < 26 * 256; idx += 512) {
            int r = idx >> 8, c = idx & 255;
            int j = i0 + r;
            hs[r][c] = (j < NN) ? x[(size_t)j * DD + ch * 256 + c] : 0.f;
        }
        __syncthreads();
#pragma unroll
        for (int e = 0; e < 8; e++) {
            int d = l + e * 32;
            float xv = hs[w][d];
#pragma unroll
            for (int k = 0; k < 11; k++) acc[k] += xv * hs[w + k][d];
        }
    }
#pragma unroll
    for (int k = 0; k < 11; k++) {
        float v = acc[k];
#pragma unroll
        for (int o = 16; o > 0; o >>= 1) v += __shfl_down_sync(0xffffffffu, v, o);
        if (l == 0) raw[(i0 + w) * 11 + k] = v;
    }
}

// ---------------- softmax over full row (assemble from symmetric raw) ----
__global__ void att_soft(const float* __restrict__ raw, float* __restrict__ band,
                         float* __restrict__ cvec, float* __restrict__ diag) {
    int i = blockIdx.x * 128 + threadIdx.x;
    if (i >= NN) return;
    int lo = max(i - WW, 0), hi = min(i + WW, NN - 1);
    int cnt = hi - lo + 1;
    float lg[BAND];
#pragma unroll
    for (int jo = 0; jo < BAND; jo++) {
        int j = i - WW + jo;
        float v = 0.f;
        bool valid = (j >= 0 && j < NN);
        if (valid) {
            if (jo >= WW) v = raw[i * 11 + (jo - WW)];
            else v = raw[j * 11 + (WW - jo)];
        }
        lg[jo] = valid ? v : -1e30f;
    }
    float m = 0.0f;  // zeros always in row
#pragma unroll
    for (int jo = 0; jo < BAND; jo++) m = fmaxf(m, lg[jo]);
    float em = expf(-m);
    float Z = (float)(NN - cnt) * em;
    float vals[BAND];
#pragma unroll
    for (int jo = 0; jo < BAND; jo++) {
        int j = i - WW + jo;
        float v = 0.f;
        if (j >= 0 && j < NN) {
            v = expf(lg[jo] - m);
            Z += v;
        }
        vals[jo] = v;
    }
    float inv = 1.0f / Z;
#pragma unroll
    for (int jo = 0; jo < BAND; jo++) band[i * BAND + jo] = vals[jo] * inv;
    cvec[i] = em * inv;
    diag[i] = vals[WW] * inv;
}

// ---------------- scan1: 16-row chunk sums + per-speaker sums -----------
__global__ __launch_bounds__(256) void scan1(const __half* __restrict__ h,
                                             const int* __restrict__ spk,
                                             float* __restrict__ chunk,
                                             float* __restrict__ S) {
    __shared__ int sp_sh[16];
    int tid = threadIdx.x;
    int d = blockIdx.y * 256 + tid;
    int base = blockIdx.x * 16;
    if (tid < 16) sp_sh[tid] = spk[base + tid];
    __syncthreads();
    float s = 0.f, sreg[NSPK];
#pragma unroll
    for (int k = 0; k < NSPK; k++) sreg[k] = 0.f;
#pragma unroll
    for (int r = 0; r < 16; r++) {
        float v = __half2float(h[(size_t)(base + r) * DD + d]);
        s += v;
        int sp = sp_sh[r];
#pragma unroll
        for (int k = 0; k < NSPK; k++)
            if (sp == k) sreg[k] += v;
    }
    chunk[blockIdx.x * DD + d] = s;
#pragma unroll
    for (int k = 0; k < NSPK; k++)
        if (sreg[k] != 0.f) atomicAdd(&S[k * DD + d], sreg[k]);
}

// ---------------- chunkpre: exclusive prefix over 256 chunks -------------
__global__ __launch_bounds__(256) void chunkpre(const float* __restrict__ chunk,
                                                float* __restrict__ PreC) {
    int tid = threadIdx.x;
    int d = blockIdx.y * 256 + tid;
    int c0 = blockIdx.x * 16;
    float s = 0.f;
#pragma unroll 8
    for (int c = 0; c < c0; c++) s += chunk[c * DD + d];
#pragma unroll
    for (int k = 0; k < 16; k++) {
        PreC[(size_t)(c0 + k) * DD + d] = s;
        s += chunk[(c0 + k) * DD + d];
    }
    if (blockIdx.x == 15) PreC[(size_t)256 * DD + d] = s;
}

// ---------------- build Y = [ypred | ysuc | ysame | diag*h] (fp16) ------
#define BY_SMEM (2 * 36 * 256 * 4)

__global__ __launch_bounds__(256) void build_y(
    const __half* __restrict__ h, const float* __restrict__ PreC,
    const float* __restrict__ S, const float* __restrict__ band,
    const float* __restrict__ cvec, const float* __restrict__ diag,
    const int* __restrict__ spk, __half* __restrict__ Y) {
    extern __shared__ float dyn[];
    float(*hs)[256] = (float(*)[256])dyn;
    float(*hp)[256] = (float(*)[256])(dyn + 36 * 256);
    __shared__ float a_sh[16][21];
    __shared__ int sp_sh[36];
    __shared__ float c_sh[16], dg_sh[16];
    __shared__ int spi_sh[16];
    int tid = threadIdx.x;
    int i0 = blockIdx.x * 16;
    int d = blockIdx.y * 256 + tid;
    const int h0 = i0 - H0OFF;

    {
        float run = 0.f;
#pragma unroll
        for (int r = 0; r < 36; r++) {
            int j = h0 + r;
            float v = (j >= 0 && j < NN) ? __half2float(h[(size_t)j * DD + d]) : 0.f;
            hs[r][tid] = v;
            run += v;
            hp[r][tid] = run;
        }
    }
    for (int idx = tid; idx < 16 * 21; idx += 256) {
        int il = idx / 21, jo = idx - il * 21;
        int i = i0 + il, j = i - WW + jo;
        a_sh[il][jo] = (j >= 0 && j < NN) ? band[i * BAND + jo] : 0.f;
    }
    if (tid < 36) {
        int j = h0 + tid;
        sp_sh[tid] = (j >= 0 && j < NN) ? spk[j] : -1;
    }
    if (tid < 16) {
        c_sh[tid] = cvec[i0 + tid];
        dg_sh[tid] = diag[i0 + tid];
        spi_sh[tid] = spk[i0 + tid];
    }
    __syncthreads();

    float tot = PreC[(size_t)256 * DD + d];
#pragma unroll 2
    for (int ti = 0; ti < 16; ti++) {
        int i = i0 + ti;
        float c = c_sh[ti];
        int spi = spi_sh[ti];
        float yp = 0.f, ys = 0.f, ysm = 0.f;
#pragma unroll
        for (int jo = 0; jo < BAND; jo++) {
            float a = a_sh[ti][jo];
            float hv = hs[ti + jo][tid];
            if (jo >= WW) yp += a * hv; else ys += a * hv;
            if (sp_sh[ti + jo] == spi) ysm += (a - c) * hv;
        }
        int hi = min(i + WW, NN - 1);
        int cp = hi >> 4;
        float PreHi = PreC[(size_t)cp * DD + d] + hp[hi - h0][tid]
                      - hp[16 * cp - 1 - h0][tid];
        yp += c * (tot - PreHi);
        int p2 = i - WW - 1;
        if (p2 >= 0) {
            int cq = (p2 >> 4) + 1;
            float hpp2 = (p2 >= h0) ? hp[p2 - h0][tid] : 0.f;
            float PreP2 = PreC[(size_t)cq * DD + d]
                          - (hp[16 * cq - 1 - h0][tid] - hpp2);
            ys += c * PreP2;
        }
        ysm += c * S[spi * DD + d];
        size_t base = (size_t)i * (4 * DD) + d;
        Y[base] = __float2half_rn(yp);
        Y[base + DD] = __float2half_rn(ys);
        Y[base + 2 * DD] = __float2half_rn(ysm);
        Y[base + 3 * DD] = __float2half_rn(dg_sh[ti] * hs[ti + H0OFF][tid]);
    }
}

// ---------------- fp16 mma.sync GEMM, cp.async 3-stage, ldmatrix frags ---
struct GJob {
    const __half* Aseg[4];
    const __half* Bseg[4];
    const float* bias;
    __half* C16;
    const float* We2;
    float* outEmo;
    int nseg;
    int lda;
    int relu;
    int emo;
};

#define BKH 32
#define A_STRIDE 40
#define S_A_HALFS (128 * A_STRIDE)
#define STG_HALFS (2 * S_A_HALFS)
#define STAGES 3
#define TILE_LD 132
#define GEMM_SMEM ((128 * TILE_LD + 128 * 7) * 4)

__global__ __launch_bounds__(256, 2) void gemm_fp16(GJob job) {
    extern __shared__ __half smh[];
    const uint32_t sbase = smem_u32(smh);

    const int tid = threadIdx.x;
    const int row0 = blockIdx.y * 128;
    const int col0 = blockIdx.x * 128;
    const int KT = job.nseg * 32;
    const int lda = job.lda;

    const int wid = tid >> 5, lane = tid & 31;
    const int g = lane >> 2, t = lane & 3;
    const int wr = (wid & 1) * 64;
    const int wc = (wid >> 1) * 32;

    const uint32_t laneA =
        (uint32_t)((wr + (lane & 15)) * A_STRIDE + ((lane >> 4) << 3)) * 2;
    const uint32_t laneB =
        (uint32_t)((wc + ((lane >> 4) << 3) + (lane & 7)) * A_STRIDE +
                   (((lane >> 3) & 1) << 3)) * 2;

    float acc[4][4][4];
#pragma unroll
    for (int m = 0; m < 4; m++)
#pragma unroll
        for (int n = 0; n < 4; n++)
#pragma unroll
            for (int q = 0; q < 4; q++) acc[m][n][q] = 0.f;

    auto issue = [&](int kt) {
        int seg = kt >> 5;
        int kb = (kt & 31) * BKH;
        const __half* A = job.Aseg[seg];
        const __half* B = job.Bseg[seg];
        uint32_t st = sbase + (uint32_t)((kt % STAGES) * STG_HALFS * 2);
        uint32_t stB = st + S_A_HALFS * 2;
#pragma unroll
        for (int l = 0; l < 2; l++) {
            int q = tid + l * 256;
            int r = q >> 2, c8 = (q & 3) * 8;
            cp16(st + (uint32_t)(r * A_STRIDE + c8) * 2,
                 &A[(size_t)(row0 + r) * lda + kb + c8]);
            cp16(stB + (uint32_t)(r * A_STRIDE + c8) * 2,
                 &B[(size_t)(col0 + r) * DD + kb + c8]);
        }
    };

    issue(0);
    CP_COMMIT();
    issue(1);
    CP_COMMIT();

    for (int kt = 0; kt < KT; kt++) {
        if (kt + 2 < KT) issue(kt + 2);
        CP_COMMIT();
        CP_WAIT2();
        __syncthreads();

        uint32_t sA = sbase + (uint32_t)((kt % STAGES) * STG_HALFS * 2);
        uint32_t sB = sA + S_A_HALFS * 2;

#pragma unroll
        for (int ks = 0; ks < 2; ks++) {
            const uint32_t koff = ks * 32;
            uint32_t aF[4][4], bF[4][2];
#pragma unroll
            for (int m = 0; m < 4; m++)
                ldsm4(aF[m][0], aF[m][1], aF[m][2], aF[m][3],
                      sA + laneA + m * 1280 + koff);
#pragma unroll
            for (int j = 0; j < 2; j++) {
                uint32_t r0, r1, r2, r3;
                ldsm4(r0, r1, r2, r3, sB + laneB + j * 1280 + koff);
                bF[2 * j][0] = r0; bF[2 * j][1] = r1;
                bF[2 * j + 1][0] = r2; bF[2 * j + 1][1] = r3;
            }
#pragma unroll
            for (int m = 0; m < 4; m++)
#pragma unroll
                for (int n = 0; n < 4; n++) mma16(acc[m][n], aF[m], bF[n]);
        }
        __syncthreads();
    }

    // ---- epilogue ----
    float* tile = (float*)smh;
    float* we2s = tile + 128 * TILE_LD;
    if (job.emo) {
        CP_WAIT0();
        __syncthreads();
    }

#pragma unroll
    for (int m = 0; m < 4; m++) {
        int rl = wr + m * 16 + g;
        int r = row0 + rl;
#pragma unroll
        for (int n = 0; n < 4; n++) {
            int cl = wc + n * 8 + t * 2;
            int c = col0 + cl;
            float2 v0 = make_float2(acc[m][n][0], acc[m][n][1]);
            float2 v1 = make_float2(acc[m][n][2], acc[m][n][3]);
            if (job.bias) {
                float2 b2 = *(const float2*)&job.bias[c];
                v0.x += b2.x; v0.y += b2.y; v1.x += b2.x; v1.y += b2.y;
            }
            if (job.relu) {
                v0.x = fmaxf(v0.x, 0.f); v0.y = fmaxf(v0.y, 0.f);
                v1.x = fmaxf(v1.x, 0.f); v1.y = fmaxf(v1.y, 0.f);
            }
            if (job.C16) {
                *(__half2*)&job.C16[(size_t)r * DD + c] = __floats2half2_rn(v0.x, v0.y);
                *(__half2*)&job.C16[(size_t)(r + 8) * DD + c] = __floats2half2_rn(v1.x, v1.y);
            }
            if (job.emo) {
                tile[rl * TILE_LD + cl] = v0.x;
                tile[rl * TILE_LD + cl + 1] = v0.y;
                tile[(rl + 8) * TILE_LD + cl] = v1.x;
                tile[(rl + 8) * TILE_LD + cl + 1] = v1.y;
            }
        }
    }

    if (job.emo) {
        for (int idx = tid; idx < 128 * 7; idx += 256)
            we2s[idx] = job.We2[(size_t)(col0 + idx / 7) * 7 + (idx % 7)];
        __syncthreads();
        int row = tid >> 1, half = tid & 1;
        float e[7];
#pragma unroll
        for (int w = 0; w < 7; w++) e[w] = 0.f;
        const float* trow = tile + row * TILE_LD + half * 64;
        const float* wbase = we2s + half * 64 * 7;
#pragma unroll 4
        for (int c = 0; c < 64; c++) {
            float tv = trow[c];
            const float* wp = wbase + c * 7;
#pragma unroll
            for (int w = 0; w < 7; w++) e[w] += tv * wp[w];
        }
#pragma unroll
        for (int w = 0; w < 7; w++) e[w] += __shfl_xor_sync(0xffffffffu, e[w], 1);
        if (half == 0) {
#pragma unroll
            for (int w = 0; w < 7; w++)
                atomicAdd(&job.outEmo[(size_t)(row0 + row) * 7 + w], e[w]);
        }
    }
}

// ---------------- sentiment head (fp16 inputs) ----------------------------
__global__ void sentiment_head(const __half* __restrict__ h2,
                               const __half* __restrict__ x,
                               const float* __restrict__ Wst,
                               const float* __restrict__ bst,
                               float* __restrict__ out) {
    int i = blockIdx.x;
    int w = threadIdx.x >> 5, lane = threadIdx.x & 31;
    float acc = 0.f;
    for (int k = lane; k < DD; k += 32)
        acc += __half2float(h2[(size_t)i * DD + k]) * Wst[k * 3 + w];
    for (int k = lane; k < DD; k += 32)
        acc += __half2float(x[(size_t)i * DD + k]) * Wst[(DD + k) * 3 + w];
#pragma unroll
    for (int o = 16; o > 0; o >>= 1) acc += __shfl_down_sync(0xffffffffu, acc, o);
    if (lane == 0) out[i * 3 + w] = acc + bst[w];
}

// ---------------- launch --------------------------------------------------
extern "C" void kernel_launch(void* const* d_in, const int* in_sizes, int n_in,
                              void* d_out, int out_size) {
    const float* x = (const float*)d_in[0];
    const int* spk = (const int*)d_in[1];
    const float* Wp1 = (const float*)d_in[2];
    const float* Ws1 = (const float*)d_in[3];
    const float* Wsm1 = (const float*)d_in[4];
    const float* Wdf1 = (const float*)d_in[5];
    const float* Wp2 = (const float*)d_in[6];
    const float* Ws2 = (const float*)d_in[7];
    const float* Wsm2 = (const float*)d_in[8];
    const float* Wdf2 = (const float*)d_in[9];
    const float* Wa1 = (const float*)d_in[10];
    const float* Wa2 = (const float*)d_in[11];
    const float* We1 = (const float*)d_in[12];
    const float* be1 = (const float*)d_in[13];
    const float* We2 = (const float*)d_in[14];
    const float* be2 = (const float*)d_in[15];
    const float* Wst = (const float*)d_in[16];
    const float* bst = (const float*)d_in[17];
    float* out = (float*)d_out;

    float *raw, *band, *cvec, *diag, *chunk, *PreC, *S;
    __half *Yh, *Wh, *Xh, *h1h, *h2h;
    cudaGetSymbolAddress((void**)&raw, g_raw);
    cudaGetSymbolAddress((void**)&band, g_band);
    cudaGetSymbolAddress((void**)&cvec, g_c);
    cudaGetSymbolAddress((void**)&diag, g_diag);
    cudaGetSymbolAddress((void**)&chunk, g_chunk);
    cudaGetSymbolAddress((void**)&PreC, g_PreC);
    cudaGetSymbolAddress((void**)&S, g_S);
    cudaGetSymbolAddress((void**)&Yh, g_Yh);
    cudaGetSymbolAddress((void**)&Wh, g_Wh);
    cudaGetSymbolAddress((void**)&Xh, g_Xh);
    cudaGetSymbolAddress((void**)&h1h, g_h1h);
    cudaGetSymbolAddress((void**)&h2h, g_h2h);

    cudaFuncSetAttribute(gemm_fp16, cudaFuncAttributeMaxDynamicSharedMemorySize,
                         GEMM_SMEM);
    cudaFuncSetAttribute(build_y, cudaFuncAttributeMaxDynamicSharedMemorySize,
                         BY_SMEM);

    WCPack wp;
    const float* As[10] = {Wp1, Ws1, Wsm1, Wa1, Wp2, Ws2, Wsm2, Wa2,
                           We1, We1 + (size_t)DD * DD};
    const float* Bs[10] = {Wdf1, Wdf1, Wdf1, Wa1, Wdf2, Wdf2, Wdf2, Wa2,
                           We1, We1};
    float Sg[10] = {1.f, 1.f, -1.f, 0.f, 1.f, 1.f, -1.f, 0.f, 0.f, 0.f};
    for (int i = 0; i < 10; i++) { wp.a[i] = As[i]; wp.b[i] = Bs[i]; wp.s[i] = Sg[i]; }
    conv_wc<<<dim3(32, 32, 10), 256>>>(wp, Wh);
    conv_x<<<NN * DD / 1024, 256>>>(x, Xh);
    prep<<<(2 * NSPK * DD + NN * 7 + 255) / 256, 256>>>(S, out, be2);

    att_half<<<NN / 16, 512>>>(x, raw);
    att_soft<<<NN / 128, 128>>>(raw, band, cvec, diag);

    const __half* hin = Xh;
    __half* houts[2] = {h1h, h2h};
    dim3 ggemm(DD / 128, NN / 128);

    for (int L = 0; L < 2; L++) {
        float* SL = S + (size_t)L * NSPK * DD;
        scan1<<<dim3(256, 4), 256>>>(hin, spk, chunk, SL);
        chunkpre<<<dim3(16, 4), 256>>>(chunk, PreC);
        build_y<<<dim3(NN / 16, 4), 256, BY_SMEM>>>(hin, PreC, SL, band, cvec,
                                                    diag, spk, Yh);

        GJob jb;
        for (int s = 0; s < 4; s++) {
            jb.Aseg[s] = Yh + (size_t)s * DD;
            jb.Bseg[s] = Wh + (size_t)(L * 4 + s) * DD * DD;
        }
        jb.bias = nullptr;
        jb.C16 = houts[L];
        jb.We2 = nullptr;
        jb.outEmo = nullptr;
        jb.nseg = 4;
        jb.lda = 4 * DD;
        jb.relu = 1;
        jb.emo = 0;
        gemm_fp16<<<ggemm, 256, GEMM_SMEM>>>(jb);
        hin = houts[L];
    }

    // emotion: out[:, :7] = relu([h2|x]@We1 + be1) @ We2 + be2 (fused)
    {
        GJob jb;
        jb.Aseg[0] = h2h; jb.Aseg[1] = Xh;
        jb.Aseg[2] = nullptr; jb.Aseg[3] = nullptr;
        jb.Bseg[0] = Wh + (size_t)8 * DD * DD;
        jb.Bseg[1] = Wh + (size_t)9 * DD * DD;
        jb.Bseg[2] = nullptr; jb.Bseg[3] = nullptr;
        jb.bias = be1;
        jb.C16 = nullptr;
        jb.We2 = We2;
        jb.outEmo = out;
        jb.nseg = 2;
        jb.lda = DD;
        jb.relu = 1;
        jb.emo = 1;
        gemm_fp16<<<ggemm, 256, GEMM_SMEM>>>(jb);
    }
    sentiment_head<<<NN, 96>>>(h2h, Xh, Wst, bst, out + NN * 7);
}

// round 13
// speedup vs baseline: 6.9046x; 1.0465x over previous
#include <cuda_runtime.h>
#include <cuda_fp16.h>
#include <math.h>
#include <stdint.h>

#define NN 4096
#define DD 1024
#define WW 10
#define BAND 21
#define NSPK 8

// ---------------- device scratch (static, no allocation) ----------------
__device__ float g_raw[NN * 11];
__device__ float g_band[NN * BAND];
__device__ float g_c[NN];
__device__ float g_diag[NN];
__device__ float g_chunk[256 * DD];
__device__ float g_PreC[257 * DD];
__device__ float g_S[2 * NSPK * DD];
__device__ __half g_Yh[NN * 4 * DD];
__device__ __half g_h1h[NN * DD];
__device__ __half g_h2h[NN * DD];
__device__ __half g_Wh[10 * DD * DD];   // fp16 combined weights, [N,K]
__device__ __half g_Xh[NN * DD];        // fp16 x

// ---------------- helpers -------------------------------------------------
__device__ __forceinline__ uint32_t smem_u32(const void* p) {
    uint32_t a;
    asm("{ .reg .u64 t; cvta.to.shared.u64 t, %1; cvt.u32.u64 %0, t; }"
        : "=r"(a) : "l"(p));
    return a;
}

__device__ __forceinline__ void cp16(uint32_t dst, const void* src) {
    asm volatile("cp.async.cg.shared.global [%0], [%1], 16;"
                 :: "r"(dst), "l"(src) : "memory");
}
#define CP_COMMIT() asm volatile("cp.async.commit_group;" ::: "memory")
#define CP_WAIT2()  asm volatile("cp.async.wait_group 2;" ::: "memory")
#define CP_WAIT1()  asm volatile("cp.async.wait_group 1;" ::: "memory")
#define CP_WAIT0()  asm volatile("cp.async.wait_group 0;" ::: "memory")

__device__ __forceinline__ void mma16(float c[4], const uint32_t a[4],
                                      const uint32_t b[2]) {
    asm volatile(
        "mma.sync.aligned.m16n8k16.row.col.f32.f16.f16.f32 "
        "{%0,%1,%2,%3}, {%4,%5,%6,%7}, {%8,%9}, {%0,%1,%2,%3};"
        : "+f"(c[0]), "+f"(c[1]), "+f"(c[2]), "+f"(c[3])
        : "r"(a[0]), "r"(a[1]), "r"(a[2]), "r"(a[3]), "r"(b[0]), "r"(b[1]));
}

__device__ __forceinline__ void ldsm4(uint32_t& r0, uint32_t& r1,
                                      uint32_t& r2, uint32_t& r3, uint32_t addr) {
    asm volatile("ldmatrix.sync.aligned.m8n8.x4.shared.b16 {%0,%1,%2,%3}, [%4];"
                 : "=r"(r0), "=r"(r1), "=r"(r2), "=r"(r3) : "r"(addr));
}

// ---------------- one-time conversion: combined fp16 [N,K] weights ------
struct WCPack {
    const float* a[10];
    const float* b[10];
    float s[10];
};

__global__ __launch_bounds__(256) void conv_wc(WCPack p, __half* __restrict__ dst) {
    __shared__ float t[32][33];
    int z = blockIdx.z;
    const float* A = p.a[z];
    const float* B = p.b[z];
    float sg = p.s[z];
    __half* d = dst + (size_t)z * DD * DD;
    int bx = blockIdx.x * 32, by = blockIdx.y * 32;
    int tx = threadIdx.x & 31, ty = threadIdx.x >> 5;
    if (sg != 0.f) {
#pragma unroll
        for (int j = 0; j < 32; j += 8) {
            size_t off = (size_t)(by + ty + j) * DD + bx + tx;
            t[ty + j][tx] = A[off] + sg * B[off];
        }
    } else {
#pragma unroll
        for (int j = 0; j < 32; j += 8) {
            size_t off = (size_t)(by + ty + j) * DD + bx + tx;
            t[ty + j][tx] = A[off];
        }
    }
    __syncthreads();
#pragma unroll
    for (int j = 0; j < 32; j += 8)
        d[(size_t)(bx + ty + j) * DD + by + tx] = __float2half_rn(t[tx][ty + j]);
}

__global__ __launch_bounds__(256) void conv_x(const float* __restrict__ x,
                                              __half* __restrict__ xh) {
    size_t i = ((size_t)blockIdx.x * 256 + threadIdx.x) * 4;
    float4 v = *(const float4*)&x[i];
    *(__half2*)&xh[i] = __floats2half2_rn(v.x, v.y);
    *(__half2*)&xh[i + 2] = __floats2half2_rn(v.z, v.w);
}

// prep: zero both S buffers + init emotion output with bias
__global__ void prep(float* __restrict__ S, float* __restrict__ out,
                     const float* __restrict__ be2) {
    int idx = blockIdx.x * 256 + threadIdx.x;
    if (idx < 2 * NSPK * DD) S[idx] = 0.f;
    int e = idx - 2 * NSPK * DD;
    if (e >= 0 && e < NN * 7) out[e] = be2[e % 7];
}

// ---------------- banded logits, symmetric half, cp.async double-buffered
// raw[i][k] = dot(x_i, x_{i+k}), k = 0..10
#define AH_SMEM (2 * 26 * 256 * 4)

__global__ __launch_bounds__(512) void att_half(const float* __restrict__ x,
                                                float* __restrict__ raw) {
    extern __shared__ float hsd[];
    int i0 = blockIdx.x * 16;
    int tid = threadIdx.x, w = tid >> 5, l = tid & 31;

    auto issue = [&](int ch) {
        float* dstb = hsd + (ch & 1) * (26 * 256);
        for (int idx = tid; idx < 26 * 64; idx += 512) {
            int r = idx >> 6, c4 = (idx & 63) * 4;
            int j = i0 + r;
            uint32_t daddr = smem_u32(dstb + r * 256 + c4);
            if (j < NN) {
                cp16(daddr, &x[(size_t)j * DD + ch * 256 + c4]);
            } else {
                asm volatile("st.shared.v4.f32 [%0], {%1,%1,%1,%1};"
                             :: "r"(daddr), "f"(0.f) : "memory");
            }
        }
    };

    float acc[11];
#pragma unroll
    for (int k = 0; k < 11; k++) acc[k] = 0.f;

    issue(0);
    CP_COMMIT();
#pragma unroll
    for (int ch = 0; ch < 4; ch++) {
        if (ch < 3) {
            issue(ch + 1);
            CP_COMMIT();
            CP_WAIT1();
        } else {
            CP_WAIT0();
        }
        __syncthreads();
        const float* hb = hsd + (ch & 1) * (26 * 256);
#pragma unroll
        for (int e = 0; e < 8; e++) {
            int d = l + e * 32;
            float xv = hb[w * 256 + d];
#pragma unroll
            for (int k = 0; k < 11; k++) acc[k] += xv * hb[(w + k) * 256 + d];
        }
        __syncthreads();
    }
#pragma unroll
    for (int k = 0; k < 11; k++) {
        float v = acc[k];
#pragma unroll
        for (int o = 16; o > 0; o >>= 1) v += __shfl_down_sync(0xffffffffu, v, o);
        if (l == 0) raw[(i0 + w) * 11 + k] = v;
    }
}

// ---------------- softmax over full row (assemble from symmetric raw) ----
__global__ void att_soft(const float* __restrict__ raw, float* __restrict__ band,
                         float* __restrict__ cvec, float* __restrict__ diag) {
    int i = blockIdx.x * 128 + threadIdx.x;
    if (i >= NN) return;
    int lo = max(i - WW, 0), hi = min(i + WW, NN - 1);
    int cnt = hi - lo + 1;
    float lg[BAND];
#pragma unroll
    for (int jo = 0; jo < BAND; jo++) {
        int j = i - WW + jo;
        float v = 0.f;
        bool valid = (j >= 0 && j < NN);
        if (valid) {
            if (jo >= WW) v = raw[i * 11 + (jo - WW)];
            else v = raw[j * 11 + (WW - jo)];
        }
        lg[jo] = valid ? v : -1e30f;
    }
    float m = 0.0f;
#pragma unroll
    for (int jo = 0; jo < BAND; jo++) m = fmaxf(m, lg[jo]);
    float em = expf(-m);
    float Z = (float)(NN - cnt) * em;
    float vals[BAND];
#pragma unroll
    for (int jo = 0; jo < BAND; jo++) {
        int j = i - WW + jo;
        float v = 0.f;
        if (j >= 0 && j < NN) {
            v = expf(lg[jo] - m);
            Z += v;
        }
        vals[jo] = v;
    }
    float inv = 1.0f / Z;
#pragma unroll
    for (int jo = 0; jo < BAND; jo++) band[i * BAND + jo] = vals[jo] * inv;
    cvec[i] = em * inv;
    diag[i] = vals[WW] * inv;
}

// ---------------- scan1: 16-row chunk sums + per-speaker sums (half2) ---
__global__ __launch_bounds__(256) void scan1(const __half2* __restrict__ h2v,
                                             const int* __restrict__ spk,
                                             float2* __restrict__ chunk2,
                                             float* __restrict__ S) {
    __shared__ int sp_sh[16];
    int tid = threadIdx.x;
    int d2 = blockIdx.y * 256 + tid;  // half2 column, 0..511
    int base = blockIdx.x * 16;
    if (tid < 16) sp_sh[tid] = spk[base + tid];
    __syncthreads();
    float2 s = make_float2(0.f, 0.f);
    float2 sreg[NSPK];
#pragma unroll
    for (int k = 0; k < NSPK; k++) sreg[k] = make_float2(0.f, 0.f);
#pragma unroll
    for (int r = 0; r < 16; r++) {
        float2 v = __half22float2(h2v[(size_t)(base + r) * 512 + d2]);
        s.x += v.x; s.y += v.y;
        int sp = sp_sh[r];
#pragma unroll
        for (int k = 0; k < NSPK; k++)
            if (sp == k) { sreg[k].x += v.x; sreg[k].y += v.y; }
    }
    chunk2[(size_t)blockIdx.x * 512 + d2] = s;
#pragma unroll
    for (int k = 0; k < NSPK; k++) {
        if (sreg[k].x != 0.f) atomicAdd(&S[k * DD + 2 * d2], sreg[k].x);
        if (sreg[k].y != 0.f) atomicAdd(&S[k * DD + 2 * d2 + 1], sreg[k].y);
    }
}

// ---------------- chunkpre: exclusive prefix over 256 chunks -------------
__global__ __launch_bounds__(256) void chunkpre(const float* __restrict__ chunk,
                                                float* __restrict__ PreC) {
    int tid = threadIdx.x;
    int d = blockIdx.y * 256 + tid;
    int c0 = blockIdx.x * 16;
    float s = 0.f;
#pragma unroll 8
    for (int c = 0; c < c0; c++) s += chunk[c * DD + d];
#pragma unroll
    for (int k = 0; k < 16; k++) {
        PreC[(size_t)(c0 + k) * DD + d] = s;
        s += chunk[(c0 + k) * DD + d];
    }
    if (blockIdx.x == 15) PreC[(size_t)256 * DD + d] = s;
}

// ---------------- build Y = [ypred | ysuc | ysame | diag*h] (fp16) ------
// register halo + register prefix; all indices compile-time constant
__global__ __launch_bounds__(256) void build_y(
    const __half* __restrict__ h, const float* __restrict__ PreC,
    const float* __restrict__ S, const float* __restrict__ band,
    const float* __restrict__ cvec, const float* __restrict__ diag,
    const int* __restrict__ spk, __half* __restrict__ Y) {
    __shared__ float a_sh[16][21];
    __shared__ float amc_sh[16][21];  // (a - c_i) if same speaker else 0
    __shared__ float c_sh[16], dg_sh[16];
    __shared__ int spi_sh[16];
    int tid = threadIdx.x;
    int i0 = blockIdx.x * 16;
    int d = blockIdx.y * 256 + tid;
    const int h0 = i0 - WW;

    for (int idx = tid; idx < 16 * 21; idx += 256) {
        int il = idx / 21, jo = idx - il * 21;
        int i = i0 + il, j = i - WW + jo;
        bool valid = (j >= 0 && j < NN);
        float a = valid ? band[i * BAND + jo] : 0.f;
        a_sh[il][jo] = a;
        int spj = valid ? spk[j] : -1;
        amc_sh[il][jo] = (spj == spk[i]) ? (a - cvec[i]) : 0.f;
    }
    if (tid < 16) {
        c_sh[tid] = cvec[i0 + tid];
        dg_sh[tid] = diag[i0 + tid];
        spi_sh[tid] = spk[i0 + tid];
    }
    __syncthreads();

    float hreg[36], hp[36];
    {
        float run = 0.f;
#pragma unroll
        for (int r = 0; r < 36; r++) {
            int j = h0 + r;
            float v = (j >= 0 && j < NN) ? __half2float(h[(size_t)j * DD + d]) : 0.f;
            hreg[r] = v;
            run += v;
            hp[r] = run;
        }
    }
    int c16 = i0 >> 4;
    float PreC0 = PreC[(size_t)c16 * DD + d];
    float PreC1 = PreC[(size_t)(c16 + 1) * DD + d];
    float tot = PreC[(size_t)256 * DD + d];

#pragma unroll
    for (int ti = 0; ti < 16; ti++) {
        float c = c_sh[ti];
        float yp = 0.f, ys = 0.f, ysm = 0.f;
#pragma unroll
        for (int jo = 0; jo < BAND; jo++) {
            float hv = hreg[ti + jo];
            float a = a_sh[ti][jo];
            if (jo >= WW) yp += a * hv; else ys += a * hv;
            ysm += amc_sh[ti][jo] * hv;
        }
        // suffix: c * (tot - Pre[min(i+W, N-1)])
        float PreHi = (ti <= 5 ? PreC0 : PreC1) + hp[ti + 20]
                      - (ti <= 5 ? hp[9] : hp[25]);
        yp += c * (tot - PreHi);
        // prefix: c * Pre[i-W-1] (when >= 0)
        if (i0 + ti >= WW + 1) {
            float hpp2 = (ti >= 1) ? hp[ti - 1] : 0.f;
            float PreP2 = (ti <= 10 ? PreC0 : PreC1)
                          - ((ti <= 10 ? hp[9] : hp[25]) - hpp2);
            ys += c * PreP2;
        }
        ysm += c * S[spi_sh[ti] * DD + d];
        size_t base = (size_t)(i0 + ti) * (4 * DD) + d;
        Y[base] = __float2half_rn(yp);
        Y[base + DD] = __float2half_rn(ys);
        Y[base + 2 * DD] = __float2half_rn(ysm);
        Y[base + 3 * DD] = __float2half_rn(dg_sh[ti] * hreg[ti + WW]);
    }
}

// ---------------- fp16 mma.sync GEMM, cp.async 3-stage, ldmatrix frags ---
struct GJob {
    const __half* Aseg[4];
    const __half* Bseg[4];
    const float* bias;
    __half* C16;
    const float* We2;
    float* outEmo;
    int nseg;
    int lda;
    int relu;
    int emo;
};

#define BKH 32
#define A_STRIDE 40
#define S_A_HALFS (128 * A_STRIDE)
#define STG_HALFS (2 * S_A_HALFS)
#define STAGES 3
#define TILE_LD 132
#define GEMM_SMEM ((128 * TILE_LD + 128 * 7) * 4)

__global__ __launch_bounds__(256, 2) void gemm_fp16(GJob job) {
    extern __shared__ __half smh[];
    const uint32_t sbase = smem_u32(smh);

    const int tid = threadIdx.x;
    const int row0 = blockIdx.y * 128;
    const int col0 = blockIdx.x * 128;
    const int KT = job.nseg * 32;
    const int lda = job.lda;

    const int wid = tid >> 5, lane = tid & 31;
    const int g = lane >> 2, t = lane & 3;
    const int wr = (wid & 1) * 64;
    const int wc = (wid >> 1) * 32;

    const uint32_t laneA =
        (uint32_t)((wr + (lane & 15)) * A_STRIDE + ((lane >> 4) << 3)) * 2;
    const uint32_t laneB =
        (uint32_t)((wc + ((lane >> 4) << 3) + (lane & 7)) * A_STRIDE +
                   (((lane >> 3) & 1) << 3)) * 2;

    float acc[4][4][4];
#pragma unroll
    for (int m = 0; m < 4; m++)
#pragma unroll
        for (int n = 0; n < 4; n++)
#pragma unroll
            for (int q = 0; q < 4; q++) acc[m][n][q] = 0.f;

    auto issue = [&](int kt) {
        int seg = kt >> 5;
        int kb = (kt & 31) * BKH;
        const __half* A = job.Aseg[seg];
        const __half* B = job.Bseg[seg];
        uint32_t st = sbase + (uint32_t)((kt % STAGES) * STG_HALFS * 2);
        uint32_t stB = st + S_A_HALFS * 2;
#pragma unroll
        for (int l = 0; l < 2; l++) {
            int q = tid + l * 256;
            int r = q >> 2, c8 = (q & 3) * 8;
            cp16(st + (uint32_t)(r * A_STRIDE + c8) * 2,
                 &A[(size_t)(row0 + r) * lda + kb + c8]);
            cp16(stB + (uint32_t)(r * A_STRIDE + c8) * 2,
                 &B[(size_t)(col0 + r) * DD + kb + c8]);
        }
    };

    issue(0);
    CP_COMMIT();
    issue(1);
    CP_COMMIT();

    for (int kt = 0; kt < KT; kt++) {
        if (kt + 2 < KT) issue(kt + 2);
        CP_COMMIT();
        CP_WAIT2();
        __syncthreads();

        uint32_t sA = sbase + (uint32_t)((kt % STAGES) * STG_HALFS * 2);
        uint32_t sB = sA + S_A_HALFS * 2;

#pragma unroll
        for (int ks = 0; ks < 2; ks++) {
            const uint32_t koff = ks * 32;
            uint32_t aF[4][4], bF[4][2];
#pragma unroll
            for (int m = 0; m < 4; m++)
                ldsm4(aF[m][0], aF[m][1], aF[m][2], aF[m][3],
                      sA + laneA + m * 1280 + koff);
#pragma unroll
            for (int j = 0; j < 2; j++) {
                uint32_t r0, r1, r2, r3;
                ldsm4(r0, r1, r2, r3, sB + laneB + j * 1280 + koff);
                bF[2 * j][0] = r0; bF[2 * j][1] = r1;
                bF[2 * j + 1][0] = r2; bF[2 * j + 1][1] = r3;
            }
#pragma unroll
            for (int m = 0; m < 4; m++)
#pragma unroll
                for (int n = 0; n < 4; n++) mma16(acc[m][n], aF[m], bF[n]);
        }
        __syncthreads();
    }

    // ---- epilogue ----
    float* tile = (float*)smh;
    float* we2s = tile + 128 * TILE_LD;
    if (job.emo) {
        CP_WAIT0();
        __syncthreads();
    }

#pragma unroll
    for (int m = 0; m < 4; m++) {
        int rl = wr + m * 16 + g;
        int r = row0 + rl;
#pragma unroll
        for (int n = 0; n < 4; n++) {
            int cl = wc + n * 8 + t * 2;
            int c = col0 + cl;
            float2 v0 = make_float2(acc[m][n][0], acc[m][n][1]);
            float2 v1 = make_float2(acc[m][n][2], acc[m][n][3]);
            if (job.bias) {
                float2 b2 = *(const float2*)&job.bias[c];
                v0.x += b2.x; v0.y += b2.y; v1.x += b2.x; v1.y += b2.y;
            }
            if (job.relu) {
                v0.x = fmaxf(v0.x, 0.f); v0.y = fmaxf(v0.y, 0.f);
                v1.x = fmaxf(v1.x, 0.f); v1.y = fmaxf(v1.y, 0.f);
            }
            if (job.C16) {
                *(__half2*)&job.C16[(size_t)r * DD + c] = __floats2half2_rn(v0.x, v0.y);
                *(__half2*)&job.C16[(size_t)(r + 8) * DD + c] = __floats2half2_rn(v1.x, v1.y);
            }
            if (job.emo) {
                tile[rl * TILE_LD + cl] = v0.x;
                tile[rl * TILE_LD + cl + 1] = v0.y;
                tile[(rl + 8) * TILE_LD + cl] = v1.x;
                tile[(rl + 8) * TILE_LD + cl + 1] = v1.y;
            }
        }
    }

    if (job.emo) {
        for (int idx = tid; idx < 128 * 7; idx += 256)
            we2s[idx] = job.We2[(size_t)(col0 + idx / 7) * 7 + (idx % 7)];
        __syncthreads();
        int row = tid >> 1, half = tid & 1;
        float e[7];
#pragma unroll
        for (int w = 0; w < 7; w++) e[w] = 0.f;
        const float* trow = tile + row * TILE_LD + half * 64;
        const float* wbase = we2s + half * 64 * 7;
#pragma unroll 4
        for (int c = 0; c < 64; c++) {
            float tv = trow[c];
            const float* wp = wbase + c * 7;
#pragma unroll
            for (int w = 0; w < 7; w++) e[w] += tv * wp[w];
        }
#pragma unroll
        for (int w = 0; w < 7; w++) e[w] += __shfl_xor_sync(0xffffffffu, e[w], 1);
        if (half == 0) {
#pragma unroll
            for (int w = 0; w < 7; w++)
                atomicAdd(&job.outEmo[(size_t)(row0 + row) * 7 + w], e[w]);
        }
    }
}

// ---------------- sentiment head (fp16 inputs) ----------------------------
__global__ void sentiment_head(const __half* __restrict__ h2,
                               const __half* __restrict__ x,
                               const float* __restrict__ Wst,
                               const float* __restrict__ bst,
                               float* __restrict__ out) {
    int i = blockIdx.x;
    int w = threadIdx.x >> 5, lane = threadIdx.x & 31;
    float acc = 0.f;
    for (int k = lane; k < DD; k += 32)
        acc += __half2float(h2[(size_t)i * DD + k]) * Wst[k * 3 + w];
    for (int k = lane; k < DD; k += 32)
        acc += __half2float(x[(size_t)i * DD + k]) * Wst[(DD + k) * 3 + w];
#pragma unroll
    for (int o = 16; o > 0; o >>= 1) acc += __shfl_down_sync(0xffffffffu, acc, o);
    if (lane == 0) out[i * 3 + w] = acc + bst[w];
}

// ---------------- launch --------------------------------------------------
extern "C" void kernel_launch(void* const* d_in, const int* in_sizes, int n_in,
                              void* d_out, int out_size) {
    const float* x = (const float*)d_in[0];
    const int* spk = (const int*)d_in[1];
    const float* Wp1 = (const float*)d_in[2];
    const float* Ws1 = (const float*)d_in[3];
    const float* Wsm1 = (const float*)d_in[4];
    const float* Wdf1 = (const float*)d_in[5];
    const float* Wp2 = (const float*)d_in[6];
    const float* Ws2 = (const float*)d_in[7];
    const float* Wsm2 = (const float*)d_in[8];
    const float* Wdf2 = (const float*)d_in[9];
    const float* Wa1 = (const float*)d_in[10];
    const float* Wa2 = (const float*)d_in[11];
    const float* We1 = (const float*)d_in[12];
    const float* be1 = (const float*)d_in[13];
    const float* We2 = (const float*)d_in[14];
    const float* be2 = (const float*)d_in[15];
    const float* Wst = (const float*)d_in[16];
    const float* bst = (const float*)d_in[17];
    float* out = (float*)d_out;

    float *raw, *band, *cvec, *diag, *chunk, *PreC, *S;
    __half *Yh, *Wh, *Xh, *h1h, *h2h;
    cudaGetSymbolAddress((void**)&raw, g_raw);
    cudaGetSymbolAddress((void**)&band, g_band);
    cudaGetSymbolAddress((void**)&cvec, g_c);
    cudaGetSymbolAddress((void**)&diag, g_diag);
    cudaGetSymbolAddress((void**)&chunk, g_chunk);
    cudaGetSymbolAddress((void**)&PreC, g_PreC);
    cudaGetSymbolAddress((void**)&S, g_S);
    cudaGetSymbolAddress((void**)&Yh, g_Yh);
    cudaGetSymbolAddress((void**)&Wh, g_Wh);
    cudaGetSymbolAddress((void**)&Xh, g_Xh);
    cudaGetSymbolAddress((void**)&h1h, g_h1h);
    cudaGetSymbolAddress((void**)&h2h, g_h2h);

    cudaFuncSetAttribute(gemm_fp16, cudaFuncAttributeMaxDynamicSharedMemorySize,
                         GEMM_SMEM);
    cudaFuncSetAttribute(att_half, cudaFuncAttributeMaxDynamicSharedMemorySize,
                         AH_SMEM);

    WCPack wp;
    const float* As[10] = {Wp1, Ws1, Wsm1, Wa1, Wp2, Ws2, Wsm2, Wa2,
                           We1, We1 + (size_t)DD * DD};
    const float* Bs[10] = {Wdf1, Wdf1, Wdf1, Wa1, Wdf2, Wdf2, Wdf2, Wa2,
                           We1, We1};
    float Sg[10] = {1.f, 1.f, -1.f, 0.f, 1.f, 1.f, -1.f, 0.f, 0.f, 0.f};
    for (int i = 0; i < 10; i++) { wp.a[i] = As[i]; wp.b[i] = Bs[i]; wp.s[i] = Sg[i]; }
    conv_wc<<<dim3(32, 32, 10), 256>>>(wp, Wh);
    conv_x<<<NN * DD / 1024, 256>>>(x, Xh);
    prep<<<(2 * NSPK * DD + NN * 7 + 255) / 256, 256>>>(S, out, be2);

    att_half<<<NN / 16, 512, AH_SMEM>>>(x, raw);
    att_soft<<<NN / 128, 128>>>(raw, band, cvec, diag);

    const __half* hin = Xh;
    __half* houts[2] = {h1h, h2h};
    dim3 ggemm(DD / 128, NN / 128);

    for (int L = 0; L < 2; L++) {
        float* SL = S + (size_t)L * NSPK * DD;
        scan1<<<dim3(256, 2), 256>>>((const __half2*)hin, spk, (float2*)chunk, SL);
        chunkpre<<<dim3(16, 4), 256>>>(chunk, PreC);
        build_y<<<dim3(NN / 16, 4), 256>>>(hin, PreC, SL, band, cvec, diag, spk,
                                           Yh);

        GJob jb;
        for (int s = 0; s < 4; s++) {
            jb.Aseg[s] = Yh + (size_t)s * DD;
            jb.Bseg[s] = Wh + (size_t)(L * 4 + s) * DD * DD;
        }
        jb.bias = nullptr;
        jb.C16 = houts[L];
        jb.We2 = nullptr;
        jb.outEmo = nullptr;
        jb.nseg = 4;
        jb.lda = 4 * DD;
        jb.relu = 1;
        jb.emo = 0;
        gemm_fp16<<<ggemm, 256, GEMM_SMEM>>>(jb);
        hin = houts[L];
    }

    // emotion: out[:, :7] = relu([h2|x]@We1 + be1) @ We2 + be2 (fused)
    {
        GJob jb;
        jb.Aseg[0] = h2h; jb.Aseg[1] = Xh;
        jb.Aseg[2] = nullptr; jb.Aseg[3] = nullptr;
        jb.Bseg[0] = Wh + (size_t)8 * DD * DD;
        jb.Bseg[1] = Wh + (size_t)9 * DD * DD;
        jb.Bseg[2] = nullptr; jb.Bseg[3] = nullptr;
        jb.bias = be1;
        jb.C16 = nullptr;
        jb.We2 = We2;
        jb.outEmo = out;
        jb.nseg = 2;
        jb.lda = DD;
        jb.relu = 1;
        jb.emo = 1;
        gemm_fp16<<<ggemm, 256, GEMM_SMEM>>>(jb);
    }
    sentiment_head<<<NN, 96>>>(h2h, Xh, Wst, bst, out + NN * 7);
}